// round 1
// baseline (speedup 1.0000x reference)
#include <cuda_runtime.h>
#include <cstdint>

// Problem constants
// B=8, H=W=32, N=1024, C_IN=256, HEADS=8, DH=64, ATTN_DIM=512, C_OUT=256
#define NB    8
#define NPOS  1024
#define CIN   256
#define HEADS 8
#define DH    64
#define AD    512
#define COUT  256
#define QK_SCALE 0.125f   // 64^-0.5
#define GN_EPS 1e-5f

// Scratch (static device globals; no runtime allocation)
__device__ float g_Q[NB * HEADS * NPOS * DH];   // [bh][n][c], pre-scaled
__device__ float g_K[NB * HEADS * NPOS * DH];   // [bh][n][c]
__device__ float g_V[NB * HEADS * NPOS * DH];   // [bh][n][c]
__device__ float g_A2[NB * AD * NPOS];          // [b][ch][pos]  (K-major A for out-GEMM)
__device__ float g_Y[NB * NPOS * COUT];         // [b][pos][d]  pre-GN
__device__ float g_stats[2 * NB];               // mean, rstd per b

// ---------------------------------------------------------------------------
// Kernel 1: QKV GEMM.  C[8192,1536] = X[8192,256] @ Wqkv[256,1536]
// Epilogue scatters into g_Q (scaled), g_K, g_V in [bh][n][c] layout.
// 128x128x16 tile, 256 threads, 8x8 per thread (split 4+4 register tiling).
// ---------------------------------------------------------------------------
__global__ __launch_bounds__(256) void qkv_gemm_kernel(
    const float* __restrict__ X, const float* __restrict__ W)
{
    __shared__ float As[16][128];
    __shared__ float Bs[16][128];

    const int t  = threadIdx.x;
    const int m0 = blockIdx.x * 128;   // row block (b*1024+n)
    const int n0 = blockIdx.y * 128;   // col block (qkv col)

    const int tm0 = (t >> 4) << 2;     // 0..60
    const int tn0 = (t & 15) << 2;     // 0..60

    float acc[8][8];
    #pragma unroll
    for (int i = 0; i < 8; i++)
        #pragma unroll
        for (int j = 0; j < 8; j++) acc[i][j] = 0.0f;

    const float4* X4 = reinterpret_cast<const float4*>(X);
    const float4* W4 = reinterpret_cast<const float4*>(W);

    for (int k0 = 0; k0 < CIN; k0 += 16) {
        // Load A tile 128x16 (transpose into As[k][m]) : 512 float4, 2/thread
        #pragma unroll
        for (int it = 0; it < 2; it++) {
            int idx = t + it * 256;
            int row = idx >> 2;          // 0..127
            int kc  = (idx & 3) << 2;    // 0,4,8,12
            float4 a = X4[(size_t)(m0 + row) * (CIN / 4) + ((k0 + kc) >> 2)];
            As[kc + 0][row] = a.x;
            As[kc + 1][row] = a.y;
            As[kc + 2][row] = a.z;
            As[kc + 3][row] = a.w;
        }
        // Load B tile 16x128 : 512 float4, 2/thread
        #pragma unroll
        for (int it = 0; it < 2; it++) {
            int idx = t + it * 256;
            int row = idx >> 5;          // 0..15
            int c4  = idx & 31;          // 0..31
            float4 b = W4[(size_t)(k0 + row) * (3 * AD / 4) + (n0 >> 2) + c4];
            *reinterpret_cast<float4*>(&Bs[row][c4 << 2]) = b;
        }
        __syncthreads();

        #pragma unroll
        for (int kk = 0; kk < 16; kk++) {
            float a[8], b[8];
            float4 a0 = *reinterpret_cast<const float4*>(&As[kk][tm0]);
            float4 a1 = *reinterpret_cast<const float4*>(&As[kk][tm0 + 64]);
            float4 b0 = *reinterpret_cast<const float4*>(&Bs[kk][tn0]);
            float4 b1 = *reinterpret_cast<const float4*>(&Bs[kk][tn0 + 64]);
            a[0]=a0.x; a[1]=a0.y; a[2]=a0.z; a[3]=a0.w;
            a[4]=a1.x; a[5]=a1.y; a[6]=a1.z; a[7]=a1.w;
            b[0]=b0.x; b[1]=b0.y; b[2]=b0.z; b[3]=b0.w;
            b[4]=b1.x; b[5]=b1.y; b[6]=b1.z; b[7]=b1.w;
            #pragma unroll
            for (int i = 0; i < 8; i++)
                #pragma unroll
                for (int j = 0; j < 8; j++)
                    acc[i][j] = fmaf(a[i], b[j], acc[i][j]);
        }
        __syncthreads();
    }

    // Epilogue: scatter to Q/K/V
    #pragma unroll
    for (int ig = 0; ig < 2; ig++) {
        #pragma unroll
        for (int ii = 0; ii < 4; ii++) {
            int r = m0 + ig * 64 + tm0 + ii;     // global row
            int b = r >> 10;
            int n = r & 1023;
            #pragma unroll
            for (int jg = 0; jg < 2; jg++) {
                int cg = n0 + jg * 64 + tn0;     // global col, 4-aligned
                int which = cg >> 9;             // 0=q,1=k,2=v
                int h = (cg >> 6) & 7;
                int c = cg & 63;
                float4 v;
                v.x = acc[ig * 4 + ii][jg * 4 + 0];
                v.y = acc[ig * 4 + ii][jg * 4 + 1];
                v.z = acc[ig * 4 + ii][jg * 4 + 2];
                v.w = acc[ig * 4 + ii][jg * 4 + 3];
                float* dst;
                if (which == 0) {
                    v.x *= QK_SCALE; v.y *= QK_SCALE; v.z *= QK_SCALE; v.w *= QK_SCALE;
                    dst = g_Q;
                } else if (which == 1) {
                    dst = g_K;
                } else {
                    dst = g_V;
                }
                size_t off = ((size_t)(b * HEADS + h) * NPOS + n) * DH + c;
                *reinterpret_cast<float4*>(&dst[off]) = v;
            }
        }
    }
}

// ---------------------------------------------------------------------------
// Kernel 2: fused attention (flash-style online softmax).
// Grid (8 row-tiles, 64 bh), block = 128 threads; 1 thread = 1 query row.
// Output written directly in permuted layout A2[b][ch][pos]:
//   ch = h*64 + n/16,  pos = (n%16)*64 + c
// ---------------------------------------------------------------------------
__global__ __launch_bounds__(128) void attn_kernel()
{
    __shared__ float Ks[64][64];
    __shared__ float Vs[64][64];

    const int t  = threadIdx.x;
    const int bh = blockIdx.y;           // 0..63
    const int n  = blockIdx.x * 128 + t; // query row

    // Load this row's q into registers
    float q[64];
    {
        const float4* q4 = reinterpret_cast<const float4*>(
            g_Q + ((size_t)bh * NPOS + n) * DH);
        #pragma unroll
        for (int c4 = 0; c4 < 16; c4++) {
            float4 v = q4[c4];
            q[c4 * 4 + 0] = v.x; q[c4 * 4 + 1] = v.y;
            q[c4 * 4 + 2] = v.z; q[c4 * 4 + 3] = v.w;
        }
    }

    float o[64];
    #pragma unroll
    for (int c = 0; c < 64; c++) o[c] = 0.0f;
    float mx = -1e30f;
    float l  = 0.0f;

    const float4* Kg_base = reinterpret_cast<const float4*>(g_K + (size_t)bh * NPOS * DH);
    const float4* Vg_base = reinterpret_cast<const float4*>(g_V + (size_t)bh * NPOS * DH);

    for (int mt = 0; mt < 16; mt++) {
        __syncthreads();
        // Cooperative load of 64x64 K and V tiles (1024 float4 each, 8/thread)
        const float4* Kg = Kg_base + (size_t)mt * 64 * 16;
        const float4* Vg = Vg_base + (size_t)mt * 64 * 16;
        #pragma unroll
        for (int i = 0; i < 8; i++) {
            int idx = i * 128 + t;
            int j  = idx >> 4;
            int c4 = idx & 15;
            *reinterpret_cast<float4*>(&Ks[j][c4 << 2]) = Kg[idx];
            *reinterpret_cast<float4*>(&Vs[j][c4 << 2]) = Vg[idx];
        }
        __syncthreads();

        #pragma unroll
        for (int jc = 0; jc < 8; jc++) {
            float s[8];
            #pragma unroll
            for (int jj = 0; jj < 8; jj++) {
                int j = jc * 8 + jj;
                float accq = 0.0f;
                #pragma unroll
                for (int c4 = 0; c4 < 16; c4++) {
                    float4 kv = *reinterpret_cast<const float4*>(&Ks[j][c4 << 2]);
                    accq = fmaf(q[c4 * 4 + 0], kv.x, accq);
                    accq = fmaf(q[c4 * 4 + 1], kv.y, accq);
                    accq = fmaf(q[c4 * 4 + 2], kv.z, accq);
                    accq = fmaf(q[c4 * 4 + 3], kv.w, accq);
                }
                s[jj] = accq;
            }
            // chunk max
            float cm = s[0];
            #pragma unroll
            for (int jj = 1; jj < 8; jj++) cm = fmaxf(cm, s[jj]);
            if (cm > mx) {
                float f = __expf(mx - cm);
                l *= f;
                #pragma unroll
                for (int c = 0; c < 64; c++) o[c] *= f;
                mx = cm;
            }
            #pragma unroll
            for (int jj = 0; jj < 8; jj++) {
                int j = jc * 8 + jj;
                float p = __expf(s[jj] - mx);
                l += p;
                #pragma unroll
                for (int c4 = 0; c4 < 16; c4++) {
                    float4 vv = *reinterpret_cast<const float4*>(&Vs[j][c4 << 2]);
                    o[c4 * 4 + 0] = fmaf(p, vv.x, o[c4 * 4 + 0]);
                    o[c4 * 4 + 1] = fmaf(p, vv.y, o[c4 * 4 + 1]);
                    o[c4 * 4 + 2] = fmaf(p, vv.z, o[c4 * 4 + 2]);
                    o[c4 * 4 + 3] = fmaf(p, vv.w, o[c4 * 4 + 3]);
                }
            }
        }
    }

    // Normalize and write in permuted layout
    float inv = 1.0f / l;
    int b = bh >> 3;
    int h = bh & 7;
    int ch   = h * 64 + (n >> 4);
    int pos0 = (n & 15) << 6;
    float* dst = g_A2 + ((size_t)b * AD + ch) * NPOS + pos0;
    #pragma unroll
    for (int c4 = 0; c4 < 16; c4++) {
        float4 w;
        w.x = o[c4 * 4 + 0] * inv;
        w.y = o[c4 * 4 + 1] * inv;
        w.z = o[c4 * 4 + 2] * inv;
        w.w = o[c4 * 4 + 3] * inv;
        *reinterpret_cast<float4*>(&dst[c4 << 2]) = w;
    }
}

// ---------------------------------------------------------------------------
// Kernel 3: out GEMM.  Per b: Y[pos,d] = sum_ch A2[b][ch][pos] * Wout[ch][d] + bout[d]
// A is K-major (already transposed), so As loads need no transpose.
// ---------------------------------------------------------------------------
__global__ __launch_bounds__(256) void out_gemm_kernel(
    const float* __restrict__ Wout, const float* __restrict__ bout)
{
    __shared__ float As[16][128];
    __shared__ float Bs[16][128];

    const int t  = threadIdx.x;
    const int m0 = blockIdx.x * 128;   // pos block
    const int n0 = blockIdx.y * 128;   // d block
    const int bb = blockIdx.z;

    const int tm0 = (t >> 4) << 2;
    const int tn0 = (t & 15) << 2;

    float acc[8][8];
    #pragma unroll
    for (int i = 0; i < 8; i++)
        #pragma unroll
        for (int j = 0; j < 8; j++) acc[i][j] = 0.0f;

    const float4* A4 = reinterpret_cast<const float4*>(g_A2 + (size_t)bb * AD * NPOS);
    const float4* W4 = reinterpret_cast<const float4*>(Wout);

    for (int k0 = 0; k0 < AD; k0 += 16) {
        #pragma unroll
        for (int it = 0; it < 2; it++) {
            int idx = t + it * 256;
            int row = idx >> 5;          // 0..15 (ch offset)
            int c4  = idx & 31;          // pos/4 offset
            float4 a = A4[(size_t)(k0 + row) * (NPOS / 4) + (m0 >> 2) + c4];
            *reinterpret_cast<float4*>(&As[row][c4 << 2]) = a;
        }
        #pragma unroll
        for (int it = 0; it < 2; it++) {
            int idx = t + it * 256;
            int row = idx >> 5;
            int c4  = idx & 31;
            float4 b = W4[(size_t)(k0 + row) * (COUT / 4) + (n0 >> 2) + c4];
            *reinterpret_cast<float4*>(&Bs[row][c4 << 2]) = b;
        }
        __syncthreads();

        #pragma unroll
        for (int kk = 0; kk < 16; kk++) {
            float a[8], b[8];
            float4 a0 = *reinterpret_cast<const float4*>(&As[kk][tm0]);
            float4 a1 = *reinterpret_cast<const float4*>(&As[kk][tm0 + 64]);
            float4 b0 = *reinterpret_cast<const float4*>(&Bs[kk][tn0]);
            float4 b1 = *reinterpret_cast<const float4*>(&Bs[kk][tn0 + 64]);
            a[0]=a0.x; a[1]=a0.y; a[2]=a0.z; a[3]=a0.w;
            a[4]=a1.x; a[5]=a1.y; a[6]=a1.z; a[7]=a1.w;
            b[0]=b0.x; b[1]=b0.y; b[2]=b0.z; b[3]=b0.w;
            b[4]=b1.x; b[5]=b1.y; b[6]=b1.z; b[7]=b1.w;
            #pragma unroll
            for (int i = 0; i < 8; i++)
                #pragma unroll
                for (int j = 0; j < 8; j++)
                    acc[i][j] = fmaf(a[i], b[j], acc[i][j]);
        }
        __syncthreads();
    }

    #pragma unroll
    for (int ig = 0; ig < 2; ig++) {
        #pragma unroll
        for (int ii = 0; ii < 4; ii++) {
            int pos = m0 + ig * 64 + tm0 + ii;
            #pragma unroll
            for (int jg = 0; jg < 2; jg++) {
                int d = n0 + jg * 64 + tn0;   // 4-aligned
                float4 bv = *reinterpret_cast<const float4*>(&bout[d]);
                float4 v;
                v.x = acc[ig * 4 + ii][jg * 4 + 0] + bv.x;
                v.y = acc[ig * 4 + ii][jg * 4 + 1] + bv.y;
                v.z = acc[ig * 4 + ii][jg * 4 + 2] + bv.z;
                v.w = acc[ig * 4 + ii][jg * 4 + 3] + bv.w;
                size_t off = ((size_t)bb * NPOS + pos) * COUT + d;
                *reinterpret_cast<float4*>(&g_Y[off]) = v;
            }
        }
    }
}

// ---------------------------------------------------------------------------
// Kernel 4: GroupNorm reduce (deterministic per-b mean/var). 1 block per b.
// ---------------------------------------------------------------------------
__global__ __launch_bounds__(512) void gn_reduce_kernel()
{
    const int b = blockIdx.x;
    const int t = threadIdx.x;
    const float4* Y4 = reinterpret_cast<const float4*>(g_Y + (size_t)b * NPOS * COUT);
    const int nf4 = NPOS * COUT / 4;   // 65536

    float s = 0.0f, ss = 0.0f;
    for (int i = t; i < nf4; i += 512) {
        float4 v = Y4[i];
        s  += v.x + v.y + v.z + v.w;
        ss += v.x * v.x + v.y * v.y + v.z * v.z + v.w * v.w;
    }

    __shared__ float rs[512];
    __shared__ float rss[512];
    rs[t] = s; rss[t] = ss;
    __syncthreads();
    for (int stride = 256; stride > 0; stride >>= 1) {
        if (t < stride) {
            rs[t]  += rs[t + stride];
            rss[t] += rss[t + stride];
        }
        __syncthreads();
    }
    if (t == 0) {
        const float inv_n = 1.0f / (float)(NPOS * COUT);
        float mean = rs[0] * inv_n;
        float var  = rss[0] * inv_n - mean * mean;
        g_stats[2 * b + 0] = mean;
        g_stats[2 * b + 1] = rsqrtf(var + GN_EPS);
    }
}

// ---------------------------------------------------------------------------
// Kernel 5: normalize + gamma/beta -> output
// ---------------------------------------------------------------------------
__global__ __launch_bounds__(256) void gn_norm_kernel(
    const float* __restrict__ gamma, const float* __restrict__ beta,
    float* __restrict__ out)
{
    int idx4 = blockIdx.x * 256 + threadIdx.x;   // 0..524287
    int b  = idx4 >> 16;                         // 65536 f4 per batch
    int d4 = idx4 & 63;                          // 64 f4 per channel row

    float mean = g_stats[2 * b + 0];
    float rstd = g_stats[2 * b + 1];

    float4 y = reinterpret_cast<const float4*>(g_Y)[idx4];
    float4 g = reinterpret_cast<const float4*>(gamma)[d4];
    float4 be = reinterpret_cast<const float4*>(beta)[d4];

    float4 r;
    r.x = (y.x - mean) * rstd * g.x + be.x;
    r.y = (y.y - mean) * rstd * g.y + be.y;
    r.z = (y.z - mean) * rstd * g.z + be.z;
    r.w = (y.w - mean) * rstd * g.w + be.w;
    reinterpret_cast<float4*>(out)[idx4] = r;
}

// ---------------------------------------------------------------------------
extern "C" void kernel_launch(void* const* d_in, const int* in_sizes, int n_in,
                              void* d_out, int out_size)
{
    const float* x      = (const float*)d_in[0];
    const float* w_qkv  = (const float*)d_in[1];
    const float* w_out  = (const float*)d_in[2];
    const float* b_out  = (const float*)d_in[3];
    const float* gamma  = (const float*)d_in[4];
    const float* beta   = (const float*)d_in[5];
    float* out = (float*)d_out;

    qkv_gemm_kernel<<<dim3(64, 12), 256>>>(x, w_qkv);
    attn_kernel<<<dim3(8, 64), 128>>>();
    out_gemm_kernel<<<dim3(8, 2, 8), 256>>>(w_out, b_out);
    gn_reduce_kernel<<<NB, 512>>>();
    gn_norm_kernel<<<2048, 256>>>(gamma, beta, out);
}

// round 3
// speedup vs baseline: 3.4003x; 3.4003x over previous
#include <cuda_runtime.h>
#include <cuda_bf16.h>
#include <cstdint>

#define NB    8
#define NPOS  1024
#define CIN   256
#define HEADS 8
#define DH    64
#define AD    512
#define COUT  256
#define QK_SCALE 0.125f
#define GN_EPS 1e-5f

// ---------------------------------------------------------------------------
// helpers
// ---------------------------------------------------------------------------
__device__ __forceinline__ uint32_t smem_u32(const void* p) {
    uint32_t a;
    asm("{ .reg .u64 t; cvta.to.shared.u64 t, %1; cvt.u32.u64 %0, t; }" : "=r"(a) : "l"(p));
    return a;
}

// split fp32 pair into packed bf16x2 hi + lo (residual)
__device__ __forceinline__ void split_pair(float a, float b, uint32_t& hi, uint32_t& lo)
{
    __nv_bfloat16 ah = __float2bfloat16(a);
    __nv_bfloat16 bh = __float2bfloat16(b);
    float al = a - __bfloat162float(ah);
    float bl = b - __bfloat162float(bh);
    __nv_bfloat16 alh = __float2bfloat16(al);
    __nv_bfloat16 blh = __float2bfloat16(bl);
    hi = ((uint32_t)__bfloat16_as_ushort(bh)  << 16) | (uint32_t)__bfloat16_as_ushort(ah);
    lo = ((uint32_t)__bfloat16_as_ushort(blh) << 16) | (uint32_t)__bfloat16_as_ushort(alh);
}

// mma.sync m16n8k16 bf16 -> f32 accum
__device__ __forceinline__ void mma16816(float* c, const uint32_t* a, const uint32_t* b)
{
    asm volatile("mma.sync.aligned.m16n8k16.row.col.f32.bf16.bf16.f32 "
        "{%0,%1,%2,%3},{%4,%5,%6,%7},{%8,%9},{%0,%1,%2,%3};"
        : "+f"(c[0]), "+f"(c[1]), "+f"(c[2]), "+f"(c[3])
        : "r"(a[0]), "r"(a[1]), "r"(a[2]), "r"(a[3]), "r"(b[0]), "r"(b[1]));
}

__device__ __forceinline__ void ldsm4(uint32_t* r, uint32_t addr)
{
    asm volatile("ldmatrix.sync.aligned.m8n8.x4.shared.b16 {%0,%1,%2,%3}, [%4];"
        : "=r"(r[0]), "=r"(r[1]), "=r"(r[2]), "=r"(r[3]) : "r"(addr));
}

// B-fragment ldmatrix address in a 64x64 bf16 tile (128B rows, xor-swizzled):
// lanes 0-7: rows n0..n0+7 chunk 2kc; 8-15: same rows chunk 2kc+1;
// 16-23: rows n0+8..15 chunk 2kc; 24-31: chunk 2kc+1.
__device__ __forceinline__ uint32_t bfrag_addr(uint32_t base, int n0, int kc, int lane)
{
    int row = n0 + (lane & 7) + ((lane >> 4) & 1) * 8;
    int ch  = 2 * kc + ((lane >> 3) & 1);
    return base + row * 128 + ((ch ^ (row & 7)) << 4);
}

// ---------------------------------------------------------------------------
// Scratch globals
// ---------------------------------------------------------------------------
__device__ __nv_bfloat16 g_Qh[NB * HEADS * NPOS * DH];   // [bh][n][c] hi (pre-scaled)
__device__ __nv_bfloat16 g_Ql[NB * HEADS * NPOS * DH];   // lo
__device__ __nv_bfloat16 g_Kh[NB * HEADS * NPOS * DH];   // [bh][n][c]
__device__ __nv_bfloat16 g_Kl[NB * HEADS * NPOS * DH];
__device__ __nv_bfloat16 g_Vth[NB * HEADS * DH * NPOS];  // [bh][c][n] transposed
__device__ __nv_bfloat16 g_Vtl[NB * HEADS * DH * NPOS];
__device__ float g_A2[NB * AD * NPOS];                   // [b][ch][pos]
__device__ float g_Y[NB * NPOS * COUT];
__device__ float g_part[128];
__device__ float g_stats[2 * NB];

// ---------------------------------------------------------------------------
// Kernel 1: QKV GEMM (fp32). Epilogue: split-bf16 Q (scaled), K; V split +
// transposed to [bh][c][n].
// ---------------------------------------------------------------------------
__global__ __launch_bounds__(256) void qkv_gemm_kernel(
    const float* __restrict__ X, const float* __restrict__ W)
{
    __shared__ float As[16][128];
    __shared__ float Bs[16][128];

    const int t  = threadIdx.x;
    const int m0 = blockIdx.x * 128;
    const int n0 = blockIdx.y * 128;
    const int tm0 = (t >> 4) << 2;
    const int tn0 = (t & 15) << 2;

    float acc[8][8];
    #pragma unroll
    for (int i = 0; i < 8; i++)
        #pragma unroll
        for (int j = 0; j < 8; j++) acc[i][j] = 0.0f;

    const float4* X4 = reinterpret_cast<const float4*>(X);
    const float4* W4 = reinterpret_cast<const float4*>(W);

    for (int k0 = 0; k0 < CIN; k0 += 16) {
        #pragma unroll
        for (int it = 0; it < 2; it++) {
            int idx = t + it * 256;
            int row = idx >> 2;
            int kc  = (idx & 3) << 2;
            float4 a = X4[(size_t)(m0 + row) * (CIN / 4) + ((k0 + kc) >> 2)];
            As[kc + 0][row] = a.x; As[kc + 1][row] = a.y;
            As[kc + 2][row] = a.z; As[kc + 3][row] = a.w;
        }
        #pragma unroll
        for (int it = 0; it < 2; it++) {
            int idx = t + it * 256;
            int row = idx >> 5;
            int c4  = idx & 31;
            float4 b = W4[(size_t)(k0 + row) * (3 * AD / 4) + (n0 >> 2) + c4];
            *reinterpret_cast<float4*>(&Bs[row][c4 << 2]) = b;
        }
        __syncthreads();
        #pragma unroll
        for (int kk = 0; kk < 16; kk++) {
            float a[8], b[8];
            float4 a0 = *reinterpret_cast<const float4*>(&As[kk][tm0]);
            float4 a1 = *reinterpret_cast<const float4*>(&As[kk][tm0 + 64]);
            float4 b0 = *reinterpret_cast<const float4*>(&Bs[kk][tn0]);
            float4 b1 = *reinterpret_cast<const float4*>(&Bs[kk][tn0 + 64]);
            a[0]=a0.x; a[1]=a0.y; a[2]=a0.z; a[3]=a0.w;
            a[4]=a1.x; a[5]=a1.y; a[6]=a1.z; a[7]=a1.w;
            b[0]=b0.x; b[1]=b0.y; b[2]=b0.z; b[3]=b0.w;
            b[4]=b1.x; b[5]=b1.y; b[6]=b1.z; b[7]=b1.w;
            #pragma unroll
            for (int i = 0; i < 8; i++)
                #pragma unroll
                for (int j = 0; j < 8; j++)
                    acc[i][j] = fmaf(a[i], b[j], acc[i][j]);
        }
        __syncthreads();
    }

    #pragma unroll
    for (int ig = 0; ig < 2; ig++) {
        int rbase = m0 + ig * 64 + tm0;
        int b  = rbase >> 10;
        int nb = rbase & 1023;
        #pragma unroll
        for (int jg = 0; jg < 2; jg++) {
            int cg = n0 + jg * 64 + tn0;
            int which = cg >> 9;
            int h = (cg >> 6) & 7;
            int c = cg & 63;
            int bhh = b * HEADS + h;
            if (which == 0) {
                #pragma unroll
                for (int ii = 0; ii < 4; ii++) {
                    size_t base = ((size_t)bhh*NPOS + nb+ii)*DH + c;
                    uint32_t h0,l0,h1,l1;
                    split_pair(acc[ig*4+ii][jg*4+0]*QK_SCALE, acc[ig*4+ii][jg*4+1]*QK_SCALE, h0, l0);
                    split_pair(acc[ig*4+ii][jg*4+2]*QK_SCALE, acc[ig*4+ii][jg*4+3]*QK_SCALE, h1, l1);
                    *reinterpret_cast<uint32_t*>(&g_Qh[base])     = h0;
                    *reinterpret_cast<uint32_t*>(&g_Qh[base + 2]) = h1;
                    *reinterpret_cast<uint32_t*>(&g_Ql[base])     = l0;
                    *reinterpret_cast<uint32_t*>(&g_Ql[base + 2]) = l1;
                }
            } else if (which == 1) {
                #pragma unroll
                for (int ii = 0; ii < 4; ii++) {
                    size_t base = ((size_t)bhh*NPOS + nb+ii)*DH + c;
                    uint32_t h0,l0,h1,l1;
                    split_pair(acc[ig*4+ii][jg*4+0], acc[ig*4+ii][jg*4+1], h0, l0);
                    split_pair(acc[ig*4+ii][jg*4+2], acc[ig*4+ii][jg*4+3], h1, l1);
                    *reinterpret_cast<uint32_t*>(&g_Kh[base])     = h0;
                    *reinterpret_cast<uint32_t*>(&g_Kh[base + 2]) = h1;
                    *reinterpret_cast<uint32_t*>(&g_Kl[base])     = l0;
                    *reinterpret_cast<uint32_t*>(&g_Kl[base + 2]) = l1;
                }
            } else {
                #pragma unroll
                for (int j = 0; j < 4; j++) {
                    size_t base = ((size_t)bhh*DH + (c + j))*NPOS + nb;
                    uint32_t h0,l0,h1,l1;
                    split_pair(acc[ig*4+0][jg*4+j], acc[ig*4+1][jg*4+j], h0, l0);
                    split_pair(acc[ig*4+2][jg*4+j], acc[ig*4+3][jg*4+j], h1, l1);
                    *reinterpret_cast<uint32_t*>(&g_Vth[base])     = h0;
                    *reinterpret_cast<uint32_t*>(&g_Vth[base + 2]) = h1;
                    *reinterpret_cast<uint32_t*>(&g_Vtl[base])     = l0;
                    *reinterpret_cast<uint32_t*>(&g_Vtl[base + 2]) = l1;
                }
            }
        }
    }
}

// ---------------------------------------------------------------------------
// Kernel 2: FA2-style mma.sync attention, split bf16, no max subtraction.
// Grid (16 q-tiles, 64 bh), 128 threads (4 warps x 16 q rows).
// ---------------------------------------------------------------------------
__global__ __launch_bounds__(128) void attn_mma_kernel()
{
    __shared__ uint8_t Kh_s[8192];
    __shared__ uint8_t Kl_s[8192];
    __shared__ uint8_t Vh_s[8192];
    __shared__ uint8_t Vl_s[8192];

    const int tid  = threadIdx.x;
    const int lane = tid & 31;
    const int wid  = tid >> 5;
    const int bh   = blockIdx.y;
    const int qb   = blockIdx.x * 64 + wid * 16;
    const int g    = lane >> 2;
    const int tig  = lane & 3;

    // ---- Q fragments, direct from gmem (reused across all 16 key tiles) ----
    uint32_t qh[4][4], ql[4][4];
    {
        const __nv_bfloat16* Qh = g_Qh + (size_t)bh * NPOS * DH;
        const __nv_bfloat16* Ql = g_Ql + (size_t)bh * NPOS * DH;
        int r = qb + g;
        #pragma unroll
        for (int kc = 0; kc < 4; kc++) {
            int c0 = kc * 16 + tig * 2;
            qh[kc][0] = *reinterpret_cast<const uint32_t*>(Qh + (size_t)r*DH + c0);
            qh[kc][1] = *reinterpret_cast<const uint32_t*>(Qh + (size_t)(r+8)*DH + c0);
            qh[kc][2] = *reinterpret_cast<const uint32_t*>(Qh + (size_t)r*DH + c0 + 8);
            qh[kc][3] = *reinterpret_cast<const uint32_t*>(Qh + (size_t)(r+8)*DH + c0 + 8);
            ql[kc][0] = *reinterpret_cast<const uint32_t*>(Ql + (size_t)r*DH + c0);
            ql[kc][1] = *reinterpret_cast<const uint32_t*>(Ql + (size_t)(r+8)*DH + c0);
            ql[kc][2] = *reinterpret_cast<const uint32_t*>(Ql + (size_t)r*DH + c0 + 8);
            ql[kc][3] = *reinterpret_cast<const uint32_t*>(Ql + (size_t)(r+8)*DH + c0 + 8);
        }
    }

    float oc[8][4];
    #pragma unroll
    for (int i = 0; i < 8; i++)
        #pragma unroll
        for (int j = 0; j < 4; j++) oc[i][j] = 0.0f;
    float lsum0 = 0.0f, lsum1 = 0.0f;

    const __nv_bfloat16* gKh = g_Kh  + (size_t)bh * NPOS * DH;
    const __nv_bfloat16* gKl = g_Kl  + (size_t)bh * NPOS * DH;
    const __nv_bfloat16* gVh = g_Vth + (size_t)bh * DH * NPOS;
    const __nv_bfloat16* gVl = g_Vtl + (size_t)bh * DH * NPOS;

    const uint32_t sKh = smem_u32(Kh_s);
    const uint32_t sKl = smem_u32(Kl_s);
    const uint32_t sVh = smem_u32(Vh_s);
    const uint32_t sVl = smem_u32(Vl_s);

    for (int kt = 0; kt < 16; kt++) {
        // ---- cooperative tile load (swizzled), 4 x 8KB ----
        #pragma unroll
        for (int i = 0; i < 4; i++) {
            int idx = i * 128 + tid;
            int row = idx >> 3;
            int ch  = idx & 7;
            uint32_t dsto = (uint32_t)(row * 128 + ((ch ^ (row & 7)) << 4));
            *reinterpret_cast<uint4*>(Kh_s + dsto) =
                *reinterpret_cast<const uint4*>(gKh + (size_t)(kt*64 + row)*DH + ch*8);
            *reinterpret_cast<uint4*>(Kl_s + dsto) =
                *reinterpret_cast<const uint4*>(gKl + (size_t)(kt*64 + row)*DH + ch*8);
            *reinterpret_cast<uint4*>(Vh_s + dsto) =
                *reinterpret_cast<const uint4*>(gVh + (size_t)row*NPOS + kt*64 + ch*8);
            *reinterpret_cast<uint4*>(Vl_s + dsto) =
                *reinterpret_cast<const uint4*>(gVl + (size_t)row*NPOS + kt*64 + ch*8);
        }
        __syncthreads();

        // ---- S = Qh*Kh + Qh*Kl + Ql*Kh ----
        float s[8][4];
        #pragma unroll
        for (int i = 0; i < 8; i++)
            #pragma unroll
            for (int j = 0; j < 4; j++) s[i][j] = 0.0f;

        #pragma unroll
        for (int np = 0; np < 4; np++) {
            #pragma unroll
            for (int kc = 0; kc < 4; kc++) {
                uint32_t bh4[4], bl4[4];
                ldsm4(bh4, bfrag_addr(sKh, np*16, kc, lane));
                ldsm4(bl4, bfrag_addr(sKl, np*16, kc, lane));
                mma16816(s[2*np],   qh[kc], bh4 + 0);
                mma16816(s[2*np],   qh[kc], bl4 + 0);
                mma16816(s[2*np],   ql[kc], bh4 + 0);
                mma16816(s[2*np+1], qh[kc], bh4 + 2);
                mma16816(s[2*np+1], qh[kc], bl4 + 2);
                mma16816(s[2*np+1], ql[kc], bh4 + 2);
            }
        }

        // ---- exp + pack P frags (C-frag -> A-frag layout identity) ----
        uint32_t ph[4][4], pl[4][4];
        #pragma unroll
        for (int np = 0; np < 4; np++) {
            float p0[4], p1[4];
            #pragma unroll
            for (int j = 0; j < 4; j++) {
                p0[j] = __expf(s[2*np][j]);
                p1[j] = __expf(s[2*np+1][j]);
            }
            lsum0 += p0[0] + p0[1] + p1[0] + p1[1];
            lsum1 += p0[2] + p0[3] + p1[2] + p1[3];
            split_pair(p0[0], p0[1], ph[np][0], pl[np][0]);
            split_pair(p0[2], p0[3], ph[np][1], pl[np][1]);
            split_pair(p1[0], p1[1], ph[np][2], pl[np][2]);
            split_pair(p1[2], p1[3], ph[np][3], pl[np][3]);
        }

        // ---- O += Ph*Vh + Ph*Vl + Pl*Vh ----
        #pragma unroll
        for (int vp = 0; vp < 4; vp++) {
            #pragma unroll
            for (int jc = 0; jc < 4; jc++) {
                uint32_t vh4[4], vl4[4];
                ldsm4(vh4, bfrag_addr(sVh, vp*16, jc, lane));
                ldsm4(vl4, bfrag_addr(sVl, vp*16, jc, lane));
                mma16816(oc[2*vp],   ph[jc], vh4 + 0);
                mma16816(oc[2*vp],   ph[jc], vl4 + 0);
                mma16816(oc[2*vp],   pl[jc], vh4 + 0);
                mma16816(oc[2*vp+1], ph[jc], vh4 + 2);
                mma16816(oc[2*vp+1], ph[jc], vl4 + 2);
                mma16816(oc[2*vp+1], pl[jc], vh4 + 2);
            }
        }
        __syncthreads();
    }

    // ---- normalize + write to g_A2 (permuted layout) ----
    lsum0 += __shfl_xor_sync(0xffffffffu, lsum0, 1);
    lsum0 += __shfl_xor_sync(0xffffffffu, lsum0, 2);
    lsum1 += __shfl_xor_sync(0xffffffffu, lsum1, 1);
    lsum1 += __shfl_xor_sync(0xffffffffu, lsum1, 2);
    float inv0 = 1.0f / lsum0;
    float inv1 = 1.0f / lsum1;

    int b = bh >> 3, h = bh & 7;
    int q0 = qb + g, q1 = qb + g + 8;
    size_t row0 = ((size_t)(b * AD + h * 64 + (q0 >> 4))) * NPOS + ((q0 & 15) << 6);
    size_t row1 = ((size_t)(b * AD + h * 64 + (q1 >> 4))) * NPOS + ((q1 & 15) << 6);
    #pragma unroll
    for (int ct = 0; ct < 8; ct++) {
        int c = ct * 8 + tig * 2;
        float2 v0 = make_float2(oc[ct][0] * inv0, oc[ct][1] * inv0);
        float2 v1 = make_float2(oc[ct][2] * inv1, oc[ct][3] * inv1);
        *reinterpret_cast<float2*>(g_A2 + row0 + c) = v0;
        *reinterpret_cast<float2*>(g_A2 + row1 + c) = v1;
    }
}

// ---------------------------------------------------------------------------
// Kernel 3: out GEMM (fp32)
// ---------------------------------------------------------------------------
__global__ __launch_bounds__(256) void out_gemm_kernel(
    const float* __restrict__ Wout, const float* __restrict__ bout)
{
    __shared__ float As[16][128];
    __shared__ float Bs[16][128];

    const int t  = threadIdx.x;
    const int m0 = blockIdx.x * 128;
    const int n0 = blockIdx.y * 128;
    const int bb = blockIdx.z;
    const int tm0 = (t >> 4) << 2;
    const int tn0 = (t & 15) << 2;

    float acc[8][8];
    #pragma unroll
    for (int i = 0; i < 8; i++)
        #pragma unroll
        for (int j = 0; j < 8; j++) acc[i][j] = 0.0f;

    const float4* A4 = reinterpret_cast<const float4*>(g_A2 + (size_t)bb * AD * NPOS);
    const float4* W4 = reinterpret_cast<const float4*>(Wout);

    for (int k0 = 0; k0 < AD; k0 += 16) {
        #pragma unroll
        for (int it = 0; it < 2; it++) {
            int idx = t + it * 256;
            int row = idx >> 5;
            int c4  = idx & 31;
            float4 a = A4[(size_t)(k0 + row) * (NPOS / 4) + (m0 >> 2) + c4];
            *reinterpret_cast<float4*>(&As[row][c4 << 2]) = a;
        }
        #pragma unroll
        for (int it = 0; it < 2; it++) {
            int idx = t + it * 256;
            int row = idx >> 5;
            int c4  = idx & 31;
            float4 b = W4[(size_t)(k0 + row) * (COUT / 4) + (n0 >> 2) + c4];
            *reinterpret_cast<float4*>(&Bs[row][c4 << 2]) = b;
        }
        __syncthreads();
        #pragma unroll
        for (int kk = 0; kk < 16; kk++) {
            float a[8], b[8];
            float4 a0 = *reinterpret_cast<const float4*>(&As[kk][tm0]);
            float4 a1 = *reinterpret_cast<const float4*>(&As[kk][tm0 + 64]);
            float4 b0 = *reinterpret_cast<const float4*>(&Bs[kk][tn0]);
            float4 b1 = *reinterpret_cast<const float4*>(&Bs[kk][tn0 + 64]);
            a[0]=a0.x; a[1]=a0.y; a[2]=a0.z; a[3]=a0.w;
            a[4]=a1.x; a[5]=a1.y; a[6]=a1.z; a[7]=a1.w;
            b[0]=b0.x; b[1]=b0.y; b[2]=b0.z; b[3]=b0.w;
            b[4]=b1.x; b[5]=b1.y; b[6]=b1.z; b[7]=b1.w;
            #pragma unroll
            for (int i = 0; i < 8; i++)
                #pragma unroll
                for (int j = 0; j < 8; j++)
                    acc[i][j] = fmaf(a[i], b[j], acc[i][j]);
        }
        __syncthreads();
    }

    #pragma unroll
    for (int ig = 0; ig < 2; ig++) {
        #pragma unroll
        for (int ii = 0; ii < 4; ii++) {
            int pos = m0 + ig * 64 + tm0 + ii;
            #pragma unroll
            for (int jg = 0; jg < 2; jg++) {
                int d = n0 + jg * 64 + tn0;
                float4 bv = *reinterpret_cast<const float4*>(&bout[d]);
                float4 v;
                v.x = acc[ig*4+ii][jg*4+0] + bv.x;
                v.y = acc[ig*4+ii][jg*4+1] + bv.y;
                v.z = acc[ig*4+ii][jg*4+2] + bv.z;
                v.w = acc[ig*4+ii][jg*4+3] + bv.w;
                *reinterpret_cast<float4*>(&g_Y[((size_t)bb*NPOS + pos)*COUT + d]) = v;
            }
        }
    }
}

// ---------------------------------------------------------------------------
// Kernel 4a/4b: two-stage deterministic GroupNorm reduction
// ---------------------------------------------------------------------------
__global__ __launch_bounds__(256) void gn_part_kernel()
{
    const int blk = blockIdx.x;
    const int b = blk >> 3, sl = blk & 7;
    const int t = threadIdx.x;
    const float4* Y4 = reinterpret_cast<const float4*>(g_Y + (size_t)b * NPOS * COUT) + sl * 8192;

    float s = 0.0f, ss = 0.0f;
    #pragma unroll 4
    for (int i = t; i < 8192; i += 256) {
        float4 v = Y4[i];
        s  += v.x + v.y + v.z + v.w;
        ss += v.x*v.x + v.y*v.y + v.z*v.z + v.w*v.w;
    }
    __shared__ float rs[256], rss[256];
    rs[t] = s; rss[t] = ss;
    __syncthreads();
    for (int st = 128; st > 0; st >>= 1) {
        if (t < st) { rs[t] += rs[t + st]; rss[t] += rss[t + st]; }
        __syncthreads();
    }
    if (t == 0) { g_part[blk*2] = rs[0]; g_part[blk*2+1] = rss[0]; }
}

__global__ void gn_final_kernel()
{
    int b = threadIdx.x;
    if (b < NB) {
        float s = 0.0f, ss = 0.0f;
        #pragma unroll
        for (int i = 0; i < 8; i++) {
            s  += g_part[(b*8 + i)*2];
            ss += g_part[(b*8 + i)*2 + 1];
        }
        const float inv_n = 1.0f / (float)(NPOS * COUT);
        float mean = s * inv_n;
        float var  = ss * inv_n - mean * mean;
        g_stats[2*b]     = mean;
        g_stats[2*b + 1] = rsqrtf(var + GN_EPS);
    }
}

// ---------------------------------------------------------------------------
// Kernel 5: normalize + affine
// ---------------------------------------------------------------------------
__global__ __launch_bounds__(256) void gn_norm_kernel(
    const float* __restrict__ gamma, const float* __restrict__ beta,
    float* __restrict__ out)
{
    int idx4 = blockIdx.x * 256 + threadIdx.x;
    int b  = idx4 >> 16;
    int d4 = idx4 & 63;

    float mean = g_stats[2*b];
    float rstd = g_stats[2*b + 1];

    float4 y  = reinterpret_cast<const float4*>(g_Y)[idx4];
    float4 g  = reinterpret_cast<const float4*>(gamma)[d4];
    float4 be = reinterpret_cast<const float4*>(beta)[d4];

    float4 r;
    r.x = (y.x - mean) * rstd * g.x + be.x;
    r.y = (y.y - mean) * rstd * g.y + be.y;
    r.z = (y.z - mean) * rstd * g.z + be.z;
    r.w = (y.w - mean) * rstd * g.w + be.w;
    reinterpret_cast<float4*>(out)[idx4] = r;
}

// ---------------------------------------------------------------------------
extern "C" void kernel_launch(void* const* d_in, const int* in_sizes, int n_in,
                              void* d_out, int out_size)
{
    const float* x      = (const float*)d_in[0];
    const float* w_qkv  = (const float*)d_in[1];
    const float* w_out  = (const float*)d_in[2];
    const float* b_out  = (const float*)d_in[3];
    const float* gamma  = (const float*)d_in[4];
    const float* beta   = (const float*)d_in[5];
    float* out = (float*)d_out;

    qkv_gemm_kernel<<<dim3(64, 12), 256>>>(x, w_qkv);
    attn_mma_kernel<<<dim3(16, 64), 128>>>();
    out_gemm_kernel<<<dim3(8, 2, 8), 256>>>(w_out, b_out);
    gn_part_kernel<<<64, 256>>>();
    gn_final_kernel<<<1, 32>>>();
    gn_norm_kernel<<<2048, 256>>>(gamma, beta, out);
}

// round 4
// speedup vs baseline: 4.8821x; 1.4358x over previous
#include <cuda_runtime.h>
#include <cuda_bf16.h>
#include <cstdint>

#define NB    8
#define NPOS  1024
#define CIN   256
#define HEADS 8
#define DH    64
#define AD    512
#define COUT  256
#define QK_SCALE 0.125f
#define GN_EPS 1e-5f

// ---------------------------------------------------------------------------
// helpers
// ---------------------------------------------------------------------------
__device__ __forceinline__ uint32_t smem_u32(const void* p) {
    uint32_t a;
    asm("{ .reg .u64 t; cvta.to.shared.u64 t, %1; cvt.u32.u64 %0, t; }" : "=r"(a) : "l"(p));
    return a;
}

__device__ __forceinline__ void split_pair(float a, float b, uint32_t& hi, uint32_t& lo)
{
    __nv_bfloat16 ah = __float2bfloat16(a);
    __nv_bfloat16 bh = __float2bfloat16(b);
    float al = a - __bfloat162float(ah);
    float bl = b - __bfloat162float(bh);
    __nv_bfloat16 alh = __float2bfloat16(al);
    __nv_bfloat16 blh = __float2bfloat16(bl);
    hi = ((uint32_t)__bfloat16_as_ushort(bh)  << 16) | (uint32_t)__bfloat16_as_ushort(ah);
    lo = ((uint32_t)__bfloat16_as_ushort(blh) << 16) | (uint32_t)__bfloat16_as_ushort(alh);
}

__device__ __forceinline__ void mma16816(float* c, const uint32_t* a, const uint32_t* b)
{
    asm volatile("mma.sync.aligned.m16n8k16.row.col.f32.bf16.bf16.f32 "
        "{%0,%1,%2,%3},{%4,%5,%6,%7},{%8,%9},{%0,%1,%2,%3};"
        : "+f"(c[0]), "+f"(c[1]), "+f"(c[2]), "+f"(c[3])
        : "r"(a[0]), "r"(a[1]), "r"(a[2]), "r"(a[3]), "r"(b[0]), "r"(b[1]));
}

__device__ __forceinline__ void ldsm4(uint32_t* r, uint32_t addr)
{
    asm volatile("ldmatrix.sync.aligned.m8n8.x4.shared.b16 {%0,%1,%2,%3}, [%4];"
        : "=r"(r[0]), "=r"(r[1]), "=r"(r[2]), "=r"(r[3]) : "r"(addr));
}
__device__ __forceinline__ void ldsm4t(uint32_t* r, uint32_t addr)
{
    asm volatile("ldmatrix.sync.aligned.m8n8.x4.trans.shared.b16 {%0,%1,%2,%3}, [%4];"
        : "=r"(r[0]), "=r"(r[1]), "=r"(r[2]), "=r"(r[3]) : "r"(addr));
}

// swizzled address in 64-row x 128-byte tile
__device__ __forceinline__ uint32_t sw_addr(uint32_t base, int row, int ch) {
    return base + row * 128 + ((ch ^ (row & 7)) << 4);
}
// A-frag (row-major source rows, non-trans) — ALSO serves trans B-frag (V tiles)
__device__ __forceinline__ uint32_t afrag_addr(uint32_t base, int r0, int chunk, int lane) {
    int row = r0 + (lane & 7) + ((lane >> 3) & 1) * 8;
    int ch  = 2 * chunk + (lane >> 4);
    return sw_addr(base, row, ch);
}
// B-frag non-trans (K/W tiles, rows = n)
__device__ __forceinline__ uint32_t bfrag_addr(uint32_t base, int n0, int kc, int lane) {
    int row = n0 + (lane & 7) + ((lane >> 4) & 1) * 8;
    int ch  = 2 * kc + ((lane >> 3) & 1);
    return sw_addr(base, row, ch);
}
// trans A-frag (source rows = k, cols = m): for A2 [ch][pos] tiles
__device__ __forceinline__ uint32_t afragT_addr(uint32_t base, int k0, int m0, int lane) {
    int row = k0 + (lane & 7) + ((lane >> 4) & 1) * 8;
    int ch  = (m0 >> 3) + ((lane >> 3) & 1);
    return sw_addr(base, row, ch);
}

// ---------------------------------------------------------------------------
// Scratch globals
// ---------------------------------------------------------------------------
__device__ __nv_bfloat16 g_Xh[NB * NPOS * CIN];          // [row][k]
__device__ __nv_bfloat16 g_Xl[NB * NPOS * CIN];
__device__ __nv_bfloat16 g_Wqh[3 * AD * CIN];            // [n][k] (transposed w_qkv)
__device__ __nv_bfloat16 g_Wql[3 * AD * CIN];
__device__ __nv_bfloat16 g_Woh[COUT * AD];               // [d][ch] (transposed w_out)
__device__ __nv_bfloat16 g_Wol[COUT * AD];
__device__ __nv_bfloat16 g_Qh[NB * HEADS * NPOS * DH];   // [bh][n][c] pre-scaled
__device__ __nv_bfloat16 g_Ql[NB * HEADS * NPOS * DH];
__device__ __nv_bfloat16 g_Kh[NB * HEADS * NPOS * DH];
__device__ __nv_bfloat16 g_Kl[NB * HEADS * NPOS * DH];
__device__ __nv_bfloat16 g_Vh[NB * HEADS * NPOS * DH];   // [bh][n][c]  (NOT transposed)
__device__ __nv_bfloat16 g_Vl[NB * HEADS * NPOS * DH];
__device__ __nv_bfloat16 g_A2h[NB * AD * NPOS];          // [b][ch][pos]
__device__ __nv_bfloat16 g_A2l[NB * AD * NPOS];
__device__ float g_Y[NB * NPOS * COUT];
__device__ float g_part[128];
__device__ float g_stats[2 * NB];

// ---------------------------------------------------------------------------
// Kernel 0a: X fp32 -> split bf16 (same layout)
// ---------------------------------------------------------------------------
__global__ __launch_bounds__(256) void conv_x_kernel(const float* __restrict__ X)
{
    int idx4 = blockIdx.x * 256 + threadIdx.x;        // 524288 float4
    float4 v = reinterpret_cast<const float4*>(X)[idx4];
    uint32_t h0, l0, h1, l1;
    split_pair(v.x, v.y, h0, l0);
    split_pair(v.z, v.w, h1, l1);
    uint2 hh = make_uint2(h0, h1), ll = make_uint2(l0, l1);
    reinterpret_cast<uint2*>(g_Xh)[idx4] = hh;
    reinterpret_cast<uint2*>(g_Xl)[idx4] = ll;
}

// ---------------------------------------------------------------------------
// Kernel 0b: weight transpose + split.  src [K][N] -> dst [N][K] split bf16.
// which: 0 = w_qkv (K=256,N=1536), 1 = w_out (K=512,N=256)
// ---------------------------------------------------------------------------
__global__ void conv_w_kernel(const float* __restrict__ src, int K, int N, int which)
{
    __shared__ float tile[32][33];
    int n0 = blockIdx.x * 32;
    int k0 = blockIdx.y * 32;
    int tx = threadIdx.x, ty = threadIdx.y;
    tile[ty][tx] = src[(size_t)(k0 + ty) * N + n0 + tx];
    __syncthreads();
    if (tx < 16) {
        __nv_bfloat16* dh = which ? g_Woh : g_Wqh;
        __nv_bfloat16* dl = which ? g_Wol : g_Wql;
        uint32_t hi, lo;
        split_pair(tile[2*tx][ty], tile[2*tx+1][ty], hi, lo);
        size_t off = (size_t)(n0 + ty) * K + k0 + 2*tx;
        *reinterpret_cast<uint32_t*>(&dh[off]) = hi;
        *reinterpret_cast<uint32_t*>(&dl[off]) = lo;
    }
}

// ---------------------------------------------------------------------------
// Kernel 1: QKV GEMM via mma.sync split bf16.
// C[8192,1536] = X[8192,256] @ Wqkv.  Grid (128 m-blocks, 24 n-blocks), 128 thr.
// Each block: 64x64 output tile, BK=64. Warp w: rows [w*16, w*16+16).
// ---------------------------------------------------------------------------
__global__ __launch_bounds__(128) void qkv_mma_kernel()
{
    __shared__ uint8_t Ah_s[8192], Al_s[8192], Bh_s[8192], Bl_s[8192];

    const int tid = threadIdx.x, lane = tid & 31, wid = tid >> 5;
    const int m_blk = blockIdx.x * 64;
    const int n_blk = blockIdx.y * 64;
    const int mw = wid * 16;
    const int g = lane >> 2, tig = lane & 3;

    const uint32_t sAh = smem_u32(Ah_s), sAl = smem_u32(Al_s);
    const uint32_t sBh = smem_u32(Bh_s), sBl = smem_u32(Bl_s);

    float acc[8][4];
    #pragma unroll
    for (int i = 0; i < 8; i++)
        #pragma unroll
        for (int j = 0; j < 4; j++) acc[i][j] = 0.0f;

    for (int k0 = 0; k0 < CIN; k0 += 64) {
        #pragma unroll
        for (int i = 0; i < 4; i++) {
            int idx = i * 128 + tid;
            int row = idx >> 3, ch = idx & 7;
            uint32_t dsto = (uint32_t)(row * 128 + ((ch ^ (row & 7)) << 4));
            *reinterpret_cast<uint4*>(Ah_s + dsto) =
                *reinterpret_cast<const uint4*>(g_Xh + (size_t)(m_blk + row) * CIN + k0 + ch*8);
            *reinterpret_cast<uint4*>(Al_s + dsto) =
                *reinterpret_cast<const uint4*>(g_Xl + (size_t)(m_blk + row) * CIN + k0 + ch*8);
            *reinterpret_cast<uint4*>(Bh_s + dsto) =
                *reinterpret_cast<const uint4*>(g_Wqh + (size_t)(n_blk + row) * CIN + k0 + ch*8);
            *reinterpret_cast<uint4*>(Bl_s + dsto) =
                *reinterpret_cast<const uint4*>(g_Wql + (size_t)(n_blk + row) * CIN + k0 + ch*8);
        }
        __syncthreads();

        #pragma unroll
        for (int kc = 0; kc < 4; kc++) {
            uint32_t ah4[4], al4[4];
            ldsm4(ah4, afrag_addr(sAh, mw, kc, lane));
            ldsm4(al4, afrag_addr(sAl, mw, kc, lane));
            #pragma unroll
            for (int nn = 0; nn < 4; nn++) {
                uint32_t bh4[4], bl4[4];
                ldsm4(bh4, bfrag_addr(sBh, nn*16, kc, lane));
                ldsm4(bl4, bfrag_addr(sBl, nn*16, kc, lane));
                mma16816(acc[2*nn],   ah4, bh4 + 0);
                mma16816(acc[2*nn],   ah4, bl4 + 0);
                mma16816(acc[2*nn],   al4, bh4 + 0);
                mma16816(acc[2*nn+1], ah4, bh4 + 2);
                mma16816(acc[2*nn+1], ah4, bl4 + 2);
                mma16816(acc[2*nn+1], al4, bh4 + 2);
            }
        }
        __syncthreads();
    }

    // epilogue: split into Q (scaled) / K / V
    const int which = n_blk >> 9;
    const int h = (n_blk >> 6) & 7;
    const int r0 = m_blk + mw + g;
    const int b_ = r0 >> 10;
    const int nr = r0 & 1023;
    const int bhh = b_ * HEADS + h;
    __nv_bfloat16 *dh, *dl;
    float sc = 1.0f;
    if (which == 0)      { dh = g_Qh; dl = g_Ql; sc = QK_SCALE; }
    else if (which == 1) { dh = g_Kh; dl = g_Kl; }
    else                 { dh = g_Vh; dl = g_Vl; }

    #pragma unroll
    for (int j = 0; j < 8; j++) {
        int c = j * 8 + tig * 2;
        uint32_t hi, lo;
        split_pair(acc[j][0] * sc, acc[j][1] * sc, hi, lo);
        size_t off0 = ((size_t)bhh * NPOS + nr) * DH + c;
        *reinterpret_cast<uint32_t*>(&dh[off0]) = hi;
        *reinterpret_cast<uint32_t*>(&dl[off0]) = lo;
        split_pair(acc[j][2] * sc, acc[j][3] * sc, hi, lo);
        size_t off1 = ((size_t)bhh * NPOS + nr + 8) * DH + c;
        *reinterpret_cast<uint32_t*>(&dh[off1]) = hi;
        *reinterpret_cast<uint32_t*>(&dl[off1]) = lo;
    }
}

// ---------------------------------------------------------------------------
// Kernel 2: FA2-style mma.sync attention (split bf16, no max subtraction).
// V B-frags via ldmatrix.trans from [keys][chan] tiles.
// Epilogue writes split-bf16 A2 [b][ch][pos].
// ---------------------------------------------------------------------------
__global__ __launch_bounds__(128) void attn_mma_kernel()
{
    __shared__ uint8_t Kh_s[8192], Kl_s[8192], Vh_s[8192], Vl_s[8192];

    const int tid  = threadIdx.x;
    const int lane = tid & 31;
    const int wid  = tid >> 5;
    const int bh   = blockIdx.y;
    const int qb   = blockIdx.x * 64 + wid * 16;
    const int g    = lane >> 2;
    const int tig  = lane & 3;

    uint32_t qh[4][4], ql[4][4];
    {
        const __nv_bfloat16* Qh = g_Qh + (size_t)bh * NPOS * DH;
        const __nv_bfloat16* Ql = g_Ql + (size_t)bh * NPOS * DH;
        int r = qb + g;
        #pragma unroll
        for (int kc = 0; kc < 4; kc++) {
            int c0 = kc * 16 + tig * 2;
            qh[kc][0] = *reinterpret_cast<const uint32_t*>(Qh + (size_t)r*DH + c0);
            qh[kc][1] = *reinterpret_cast<const uint32_t*>(Qh + (size_t)(r+8)*DH + c0);
            qh[kc][2] = *reinterpret_cast<const uint32_t*>(Qh + (size_t)r*DH + c0 + 8);
            qh[kc][3] = *reinterpret_cast<const uint32_t*>(Qh + (size_t)(r+8)*DH + c0 + 8);
            ql[kc][0] = *reinterpret_cast<const uint32_t*>(Ql + (size_t)r*DH + c0);
            ql[kc][1] = *reinterpret_cast<const uint32_t*>(Ql + (size_t)(r+8)*DH + c0);
            ql[kc][2] = *reinterpret_cast<const uint32_t*>(Ql + (size_t)r*DH + c0 + 8);
            ql[kc][3] = *reinterpret_cast<const uint32_t*>(Ql + (size_t)(r+8)*DH + c0 + 8);
        }
    }

    float oc[8][4];
    #pragma unroll
    for (int i = 0; i < 8; i++)
        #pragma unroll
        for (int j = 0; j < 4; j++) oc[i][j] = 0.0f;
    float lsum0 = 0.0f, lsum1 = 0.0f;

    const __nv_bfloat16* gKh = g_Kh + (size_t)bh * NPOS * DH;
    const __nv_bfloat16* gKl = g_Kl + (size_t)bh * NPOS * DH;
    const __nv_bfloat16* gVh = g_Vh + (size_t)bh * NPOS * DH;
    const __nv_bfloat16* gVl = g_Vl + (size_t)bh * NPOS * DH;

    const uint32_t sKh = smem_u32(Kh_s), sKl = smem_u32(Kl_s);
    const uint32_t sVh = smem_u32(Vh_s), sVl = smem_u32(Vl_s);

    for (int kt = 0; kt < 16; kt++) {
        #pragma unroll
        for (int i = 0; i < 4; i++) {
            int idx = i * 128 + tid;
            int row = idx >> 3, ch = idx & 7;
            uint32_t dsto = (uint32_t)(row * 128 + ((ch ^ (row & 7)) << 4));
            *reinterpret_cast<uint4*>(Kh_s + dsto) =
                *reinterpret_cast<const uint4*>(gKh + (size_t)(kt*64 + row)*DH + ch*8);
            *reinterpret_cast<uint4*>(Kl_s + dsto) =
                *reinterpret_cast<const uint4*>(gKl + (size_t)(kt*64 + row)*DH + ch*8);
            *reinterpret_cast<uint4*>(Vh_s + dsto) =
                *reinterpret_cast<const uint4*>(gVh + (size_t)(kt*64 + row)*DH + ch*8);
            *reinterpret_cast<uint4*>(Vl_s + dsto) =
                *reinterpret_cast<const uint4*>(gVl + (size_t)(kt*64 + row)*DH + ch*8);
        }
        __syncthreads();

        // ---- S = Qh*Kh + Qh*Kl + Ql*Kh ----
        float s[8][4];
        #pragma unroll
        for (int i = 0; i < 8; i++)
            #pragma unroll
            for (int j = 0; j < 4; j++) s[i][j] = 0.0f;

        #pragma unroll
        for (int np = 0; np < 4; np++) {
            #pragma unroll
            for (int kc = 0; kc < 4; kc++) {
                uint32_t bh4[4], bl4[4];
                ldsm4(bh4, bfrag_addr(sKh, np*16, kc, lane));
                ldsm4(bl4, bfrag_addr(sKl, np*16, kc, lane));
                mma16816(s[2*np],   qh[kc], bh4 + 0);
                mma16816(s[2*np],   qh[kc], bl4 + 0);
                mma16816(s[2*np],   ql[kc], bh4 + 0);
                mma16816(s[2*np+1], qh[kc], bh4 + 2);
                mma16816(s[2*np+1], qh[kc], bl4 + 2);
                mma16816(s[2*np+1], ql[kc], bh4 + 2);
            }
        }

        // ---- exp + pack P frags ----
        uint32_t ph[4][4], pl[4][4];
        #pragma unroll
        for (int np = 0; np < 4; np++) {
            float p0[4], p1[4];
            #pragma unroll
            for (int j = 0; j < 4; j++) {
                p0[j] = __expf(s[2*np][j]);
                p1[j] = __expf(s[2*np+1][j]);
            }
            lsum0 += p0[0] + p0[1] + p1[0] + p1[1];
            lsum1 += p0[2] + p0[3] + p1[2] + p1[3];
            split_pair(p0[0], p0[1], ph[np][0], pl[np][0]);
            split_pair(p0[2], p0[3], ph[np][1], pl[np][1]);
            split_pair(p1[0], p1[1], ph[np][2], pl[np][2]);
            split_pair(p1[2], p1[3], ph[np][3], pl[np][3]);
        }

        // ---- O += Ph*Vh + Ph*Vl + Pl*Vh  (V frags via ldmatrix.trans) ----
        #pragma unroll
        for (int vp = 0; vp < 4; vp++) {
            #pragma unroll
            for (int jc = 0; jc < 4; jc++) {
                uint32_t vh4[4], vl4[4];
                ldsm4t(vh4, afrag_addr(sVh, jc*16, vp, lane));
                ldsm4t(vl4, afrag_addr(sVl, jc*16, vp, lane));
                mma16816(oc[2*vp],   ph[jc], vh4 + 0);
                mma16816(oc[2*vp],   ph[jc], vl4 + 0);
                mma16816(oc[2*vp],   pl[jc], vh4 + 0);
                mma16816(oc[2*vp+1], ph[jc], vh4 + 2);
                mma16816(oc[2*vp+1], ph[jc], vl4 + 2);
                mma16816(oc[2*vp+1], pl[jc], vh4 + 2);
            }
        }
        __syncthreads();
    }

    // ---- normalize + write split A2 (permuted layout) ----
    lsum0 += __shfl_xor_sync(0xffffffffu, lsum0, 1);
    lsum0 += __shfl_xor_sync(0xffffffffu, lsum0, 2);
    lsum1 += __shfl_xor_sync(0xffffffffu, lsum1, 1);
    lsum1 += __shfl_xor_sync(0xffffffffu, lsum1, 2);
    float inv0 = 1.0f / lsum0;
    float inv1 = 1.0f / lsum1;

    int b = bh >> 3, h = bh & 7;
    int q0 = qb + g, q1 = qb + g + 8;
    size_t row0 = ((size_t)(b * AD + h * 64 + (q0 >> 4))) * NPOS + ((q0 & 15) << 6);
    size_t row1 = ((size_t)(b * AD + h * 64 + (q1 >> 4))) * NPOS + ((q1 & 15) << 6);
    #pragma unroll
    for (int ct = 0; ct < 8; ct++) {
        int c = ct * 8 + tig * 2;
        uint32_t hi, lo;
        split_pair(oc[ct][0] * inv0, oc[ct][1] * inv0, hi, lo);
        *reinterpret_cast<uint32_t*>(&g_A2h[row0 + c]) = hi;
        *reinterpret_cast<uint32_t*>(&g_A2l[row0 + c]) = lo;
        split_pair(oc[ct][2] * inv1, oc[ct][3] * inv1, hi, lo);
        *reinterpret_cast<uint32_t*>(&g_A2h[row1 + c]) = hi;
        *reinterpret_cast<uint32_t*>(&g_A2l[row1 + c]) = lo;
    }
}

// ---------------------------------------------------------------------------
// Kernel 3: out GEMM via mma.sync. Per b: Y[pos,d] = sum_ch A2[ch][pos]*Wout[ch][d] + b.
// A-frags via ldmatrix.trans from A2 [ch][pos] tiles. Grid (16, 4, 8), 128 thr.
// ---------------------------------------------------------------------------
__global__ __launch_bounds__(128) void out_mma_kernel(const float* __restrict__ bout)
{
    __shared__ uint8_t Ah_s[8192], Al_s[8192], Bh_s[8192], Bl_s[8192];

    const int tid = threadIdx.x, lane = tid & 31, wid = tid >> 5;
    const int m_blk = blockIdx.x * 64;   // pos
    const int n_blk = blockIdx.y * 64;   // d
    const int bb = blockIdx.z;
    const int mw = wid * 16;
    const int g = lane >> 2, tig = lane & 3;

    const uint32_t sAh = smem_u32(Ah_s), sAl = smem_u32(Al_s);
    const uint32_t sBh = smem_u32(Bh_s), sBl = smem_u32(Bl_s);

    float acc[8][4];
    #pragma unroll
    for (int i = 0; i < 8; i++)
        #pragma unroll
        for (int j = 0; j < 4; j++) acc[i][j] = 0.0f;

    const __nv_bfloat16* A2h = g_A2h + (size_t)bb * AD * NPOS;
    const __nv_bfloat16* A2l = g_A2l + (size_t)bb * AD * NPOS;

    for (int k0 = 0; k0 < AD; k0 += 64) {
        #pragma unroll
        for (int i = 0; i < 4; i++) {
            int idx = i * 128 + tid;
            int row = idx >> 3, ch = idx & 7;
            uint32_t dsto = (uint32_t)(row * 128 + ((ch ^ (row & 7)) << 4));
            *reinterpret_cast<uint4*>(Ah_s + dsto) =
                *reinterpret_cast<const uint4*>(A2h + (size_t)(k0 + row) * NPOS + m_blk + ch*8);
            *reinterpret_cast<uint4*>(Al_s + dsto) =
                *reinterpret_cast<const uint4*>(A2l + (size_t)(k0 + row) * NPOS + m_blk + ch*8);
            *reinterpret_cast<uint4*>(Bh_s + dsto) =
                *reinterpret_cast<const uint4*>(g_Woh + (size_t)(n_blk + row) * AD + k0 + ch*8);
            *reinterpret_cast<uint4*>(Bl_s + dsto) =
                *reinterpret_cast<const uint4*>(g_Wol + (size_t)(n_blk + row) * AD + k0 + ch*8);
        }
        __syncthreads();

        #pragma unroll
        for (int kc = 0; kc < 4; kc++) {
            uint32_t ah4[4], al4[4];
            ldsm4t(ah4, afragT_addr(sAh, kc*16, mw, lane));
            ldsm4t(al4, afragT_addr(sAl, kc*16, mw, lane));
            #pragma unroll
            for (int nn = 0; nn < 4; nn++) {
                uint32_t bh4[4], bl4[4];
                ldsm4(bh4, bfrag_addr(sBh, nn*16, kc, lane));
                ldsm4(bl4, bfrag_addr(sBl, nn*16, kc, lane));
                mma16816(acc[2*nn],   ah4, bh4 + 0);
                mma16816(acc[2*nn],   ah4, bl4 + 0);
                mma16816(acc[2*nn],   al4, bh4 + 0);
                mma16816(acc[2*nn+1], ah4, bh4 + 2);
                mma16816(acc[2*nn+1], ah4, bl4 + 2);
                mma16816(acc[2*nn+1], al4, bh4 + 2);
            }
        }
        __syncthreads();
    }

    const int r0 = m_blk + mw + g;
    #pragma unroll
    for (int j = 0; j < 8; j++) {
        int d = n_blk + j * 8 + tig * 2;
        float2 bv = *reinterpret_cast<const float2*>(&bout[d]);
        float2 v0 = make_float2(acc[j][0] + bv.x, acc[j][1] + bv.y);
        float2 v1 = make_float2(acc[j][2] + bv.x, acc[j][3] + bv.y);
        *reinterpret_cast<float2*>(&g_Y[((size_t)bb*NPOS + r0)*COUT + d]) = v0;
        *reinterpret_cast<float2*>(&g_Y[((size_t)bb*NPOS + r0 + 8)*COUT + d]) = v1;
    }
}

// ---------------------------------------------------------------------------
// GroupNorm (two-stage reduce + normalize)
// ---------------------------------------------------------------------------
__global__ __launch_bounds__(256) void gn_part_kernel()
{
    const int blk = blockIdx.x;
    const int b = blk >> 3, sl = blk & 7;
    const int t = threadIdx.x;
    const float4* Y4 = reinterpret_cast<const float4*>(g_Y + (size_t)b * NPOS * COUT) + sl * 8192;

    float s = 0.0f, ss = 0.0f;
    #pragma unroll 4
    for (int i = t; i < 8192; i += 256) {
        float4 v = Y4[i];
        s  += v.x + v.y + v.z + v.w;
        ss += v.x*v.x + v.y*v.y + v.z*v.z + v.w*v.w;
    }
    __shared__ float rs[256], rss[256];
    rs[t] = s; rss[t] = ss;
    __syncthreads();
    for (int st = 128; st > 0; st >>= 1) {
        if (t < st) { rs[t] += rs[t + st]; rss[t] += rss[t + st]; }
        __syncthreads();
    }
    if (t == 0) { g_part[blk*2] = rs[0]; g_part[blk*2+1] = rss[0]; }
}

__global__ void gn_final_kernel()
{
    int b = threadIdx.x;
    if (b < NB) {
        float s = 0.0f, ss = 0.0f;
        #pragma unroll
        for (int i = 0; i < 8; i++) {
            s  += g_part[(b*8 + i)*2];
            ss += g_part[(b*8 + i)*2 + 1];
        }
        const float inv_n = 1.0f / (float)(NPOS * COUT);
        float mean = s * inv_n;
        float var  = ss * inv_n - mean * mean;
        g_stats[2*b]     = mean;
        g_stats[2*b + 1] = rsqrtf(var + GN_EPS);
    }
}

__global__ __launch_bounds__(256) void gn_norm_kernel(
    const float* __restrict__ gamma, const float* __restrict__ beta,
    float* __restrict__ out)
{
    int idx4 = blockIdx.x * 256 + threadIdx.x;
    int b  = idx4 >> 16;
    int d4 = idx4 & 63;

    float mean = g_stats[2*b];
    float rstd = g_stats[2*b + 1];

    float4 y  = reinterpret_cast<const float4*>(g_Y)[idx4];
    float4 g  = reinterpret_cast<const float4*>(gamma)[d4];
    float4 be = reinterpret_cast<const float4*>(beta)[d4];

    float4 r;
    r.x = (y.x - mean) * rstd * g.x + be.x;
    r.y = (y.y - mean) * rstd * g.y + be.y;
    r.z = (y.z - mean) * rstd * g.z + be.z;
    r.w = (y.w - mean) * rstd * g.w + be.w;
    reinterpret_cast<float4*>(out)[idx4] = r;
}

// ---------------------------------------------------------------------------
extern "C" void kernel_launch(void* const* d_in, const int* in_sizes, int n_in,
                              void* d_out, int out_size)
{
    const float* x      = (const float*)d_in[0];
    const float* w_qkv  = (const float*)d_in[1];
    const float* w_out  = (const float*)d_in[2];
    const float* b_out  = (const float*)d_in[3];
    const float* gamma  = (const float*)d_in[4];
    const float* beta   = (const float*)d_in[5];
    float* out = (float*)d_out;

    conv_x_kernel<<<2048, 256>>>(x);
    conv_w_kernel<<<dim3(48, 8),  dim3(32, 32)>>>(w_qkv, CIN, 3*AD, 0);
    conv_w_kernel<<<dim3(8, 16),  dim3(32, 32)>>>(w_out, AD, COUT, 1);
    qkv_mma_kernel<<<dim3(128, 24), 128>>>();
    attn_mma_kernel<<<dim3(16, 64), 128>>>();
    out_mma_kernel<<<dim3(16, 4, 8), 128>>>(b_out);
    gn_part_kernel<<<64, 256>>>();
    gn_final_kernel<<<1, 32>>>();
    gn_norm_kernel<<<2048, 256>>>(gamma, beta, out);
}

// round 5
// speedup vs baseline: 4.9389x; 1.0116x over previous
#include <cuda_runtime.h>
#include <cuda_bf16.h>
#include <cstdint>

#define NB    8
#define NPOS  1024
#define CIN   256
#define HEADS 8
#define DH    64
#define AD    512
#define COUT  256
#define QK_SCALE 0.125f
#define GN_EPS 1e-5f

// ---------------------------------------------------------------------------
// helpers
// ---------------------------------------------------------------------------
__device__ __forceinline__ uint32_t smem_u32(const void* p) {
    uint32_t a;
    asm("{ .reg .u64 t; cvta.to.shared.u64 t, %1; cvt.u32.u64 %0, t; }" : "=r"(a) : "l"(p));
    return a;
}

__device__ __forceinline__ void split_pair(float a, float b, uint32_t& hi, uint32_t& lo)
{
    __nv_bfloat16 ah = __float2bfloat16(a);
    __nv_bfloat16 bh = __float2bfloat16(b);
    float al = a - __bfloat162float(ah);
    float bl = b - __bfloat162float(bh);
    __nv_bfloat16 alh = __float2bfloat16(al);
    __nv_bfloat16 blh = __float2bfloat16(bl);
    hi = ((uint32_t)__bfloat16_as_ushort(bh)  << 16) | (uint32_t)__bfloat16_as_ushort(ah);
    lo = ((uint32_t)__bfloat16_as_ushort(blh) << 16) | (uint32_t)__bfloat16_as_ushort(alh);
}

__device__ __forceinline__ void mma16816(float* c, const uint32_t* a, const uint32_t* b)
{
    asm volatile("mma.sync.aligned.m16n8k16.row.col.f32.bf16.bf16.f32 "
        "{%0,%1,%2,%3},{%4,%5,%6,%7},{%8,%9},{%0,%1,%2,%3};"
        : "+f"(c[0]), "+f"(c[1]), "+f"(c[2]), "+f"(c[3])
        : "r"(a[0]), "r"(a[1]), "r"(a[2]), "r"(a[3]), "r"(b[0]), "r"(b[1]));
}

__device__ __forceinline__ void ldsm4(uint32_t* r, uint32_t addr)
{
    asm volatile("ldmatrix.sync.aligned.m8n8.x4.shared.b16 {%0,%1,%2,%3}, [%4];"
        : "=r"(r[0]), "=r"(r[1]), "=r"(r[2]), "=r"(r[3]) : "r"(addr));
}
__device__ __forceinline__ void ldsm4t(uint32_t* r, uint32_t addr)
{
    asm volatile("ldmatrix.sync.aligned.m8n8.x4.trans.shared.b16 {%0,%1,%2,%3}, [%4];"
        : "=r"(r[0]), "=r"(r[1]), "=r"(r[2]), "=r"(r[3]) : "r"(addr));
}

// ---- 128B-row swizzled tiles (8 chunks of 16B per row) ----
__device__ __forceinline__ uint32_t sw_addr(uint32_t base, int row, int ch) {
    return base + row * 128 + ((ch ^ (row & 7)) << 4);
}
// A-frag m16k16 (non-trans, rows = m); also trans-B frag for V tiles
__device__ __forceinline__ uint32_t afrag_addr(uint32_t base, int r0, int chunk, int lane) {
    int row = r0 + (lane & 7) + ((lane >> 3) & 1) * 8;
    int ch  = 2 * chunk + (lane >> 4);
    return sw_addr(base, row, ch);
}
// B-frag n16k16 (non-trans, rows = n)
__device__ __forceinline__ uint32_t bfrag_addr(uint32_t base, int n0, int kc, int lane) {
    int row = n0 + (lane & 7) + ((lane >> 4) & 1) * 8;
    int ch  = 2 * kc + ((lane >> 3) & 1);
    return sw_addr(base, row, ch);
}

// ---- 256B-row swizzled tiles (16 chunks/row) for the A2 [ch][pos] staging ----
__device__ __forceinline__ uint32_t sw256_addr(uint32_t base, int row, int ch) {
    return base + row * 256 + (((ch & 8) | ((ch & 7) ^ (row & 7))) << 4);
}
// trans A-frag m16k16 from [k][m] tile with 256B rows
__device__ __forceinline__ uint32_t afragT256_addr(uint32_t base, int k0, int m0, int lane) {
    int row = k0 + (lane & 7) + ((lane >> 4) & 1) * 8;
    int ch  = (m0 >> 3) + ((lane >> 3) & 1);
    return sw256_addr(base, row, ch);
}

// ---------------------------------------------------------------------------
// Scratch globals
// ---------------------------------------------------------------------------
__device__ __nv_bfloat16 g_Xh[NB * NPOS * CIN];
__device__ __nv_bfloat16 g_Xl[NB * NPOS * CIN];
__device__ __nv_bfloat16 g_Wqh[3 * AD * CIN];            // [n][k]
__device__ __nv_bfloat16 g_Wql[3 * AD * CIN];
__device__ __nv_bfloat16 g_Woh[COUT * AD];               // [d][ch]
__device__ __nv_bfloat16 g_Wol[COUT * AD];
__device__ __nv_bfloat16 g_Qh[NB * HEADS * NPOS * DH];
__device__ __nv_bfloat16 g_Ql[NB * HEADS * NPOS * DH];
__device__ __nv_bfloat16 g_Kh[NB * HEADS * NPOS * DH];
__device__ __nv_bfloat16 g_Kl[NB * HEADS * NPOS * DH];
__device__ __nv_bfloat16 g_Vh[NB * HEADS * NPOS * DH];
__device__ __nv_bfloat16 g_Vl[NB * HEADS * NPOS * DH];
__device__ __nv_bfloat16 g_A2h[NB * AD * NPOS];          // [b][ch][pos]
__device__ __nv_bfloat16 g_A2l[NB * AD * NPOS];
__device__ float g_Y[NB * NPOS * COUT];
__device__ float g_part[128];
__device__ float g_stats[2 * NB];

// ---------------------------------------------------------------------------
// Kernel 0a: X -> split bf16
// ---------------------------------------------------------------------------
__global__ __launch_bounds__(256) void conv_x_kernel(const float* __restrict__ X)
{
    int idx4 = blockIdx.x * 256 + threadIdx.x;
    float4 v = reinterpret_cast<const float4*>(X)[idx4];
    uint32_t h0, l0, h1, l1;
    split_pair(v.x, v.y, h0, l0);
    split_pair(v.z, v.w, h1, l1);
    reinterpret_cast<uint2*>(g_Xh)[idx4] = make_uint2(h0, h1);
    reinterpret_cast<uint2*>(g_Xl)[idx4] = make_uint2(l0, l1);
}

// ---------------------------------------------------------------------------
// Kernel 0b: weight transpose + split. src [K][N] -> dst [N][K].
// ---------------------------------------------------------------------------
__global__ void conv_w_kernel(const float* __restrict__ src, int K, int N, int which)
{
    __shared__ float tile[32][33];
    int n0 = blockIdx.x * 32;
    int k0 = blockIdx.y * 32;
    int tx = threadIdx.x, ty = threadIdx.y;
    tile[ty][tx] = src[(size_t)(k0 + ty) * N + n0 + tx];
    __syncthreads();
    if (tx < 16) {
        __nv_bfloat16* dh = which ? g_Woh : g_Wqh;
        __nv_bfloat16* dl = which ? g_Wol : g_Wql;
        uint32_t hi, lo;
        split_pair(tile[2*tx][ty], tile[2*tx+1][ty], hi, lo);
        size_t off = (size_t)(n0 + ty) * K + k0 + 2*tx;
        *reinterpret_cast<uint32_t*>(&dh[off]) = hi;
        *reinterpret_cast<uint32_t*>(&dl[off]) = lo;
    }
}

// ---------------------------------------------------------------------------
// Kernel 1: QKV GEMM. Block 128m x 64n, 4 warps (2m x 2n), warp tile 64x32.
// Grid (64, 24).
// ---------------------------------------------------------------------------
__global__ __launch_bounds__(128, 3) void qkv_mma_kernel()
{
    __shared__ uint8_t Ah_s[16384], Al_s[16384], Bh_s[8192], Bl_s[8192];

    const int tid = threadIdx.x, lane = tid & 31, wid = tid >> 5;
    const int m_blk = blockIdx.x * 128;
    const int n_blk = blockIdx.y * 64;
    const int mw = (wid >> 1) * 64;      // 0 or 64
    const int nw = (wid & 1) * 32;       // 0 or 32
    const int g = lane >> 2, tig = lane & 3;

    const uint32_t sAh = smem_u32(Ah_s), sAl = smem_u32(Al_s);
    const uint32_t sBh = smem_u32(Bh_s), sBl = smem_u32(Bl_s);

    float acc[4][4][4];   // [mf][n8][frag]
    #pragma unroll
    for (int i = 0; i < 4; i++)
        #pragma unroll
        for (int j = 0; j < 4; j++)
            #pragma unroll
            for (int k = 0; k < 4; k++) acc[i][j][k] = 0.0f;

    for (int k0 = 0; k0 < CIN; k0 += 64) {
        #pragma unroll
        for (int i = 0; i < 8; i++) {
            int idx = i * 128 + tid;
            int row = idx >> 3, ch = idx & 7;
            uint32_t dsto = (uint32_t)(row * 128 + ((ch ^ (row & 7)) << 4));
            *reinterpret_cast<uint4*>(Ah_s + dsto) =
                *reinterpret_cast<const uint4*>(g_Xh + (size_t)(m_blk + row) * CIN + k0 + ch*8);
            *reinterpret_cast<uint4*>(Al_s + dsto) =
                *reinterpret_cast<const uint4*>(g_Xl + (size_t)(m_blk + row) * CIN + k0 + ch*8);
        }
        #pragma unroll
        for (int i = 0; i < 4; i++) {
            int idx = i * 128 + tid;
            int row = idx >> 3, ch = idx & 7;
            uint32_t dsto = (uint32_t)(row * 128 + ((ch ^ (row & 7)) << 4));
            *reinterpret_cast<uint4*>(Bh_s + dsto) =
                *reinterpret_cast<const uint4*>(g_Wqh + (size_t)(n_blk + row) * CIN + k0 + ch*8);
            *reinterpret_cast<uint4*>(Bl_s + dsto) =
                *reinterpret_cast<const uint4*>(g_Wql + (size_t)(n_blk + row) * CIN + k0 + ch*8);
        }
        __syncthreads();

        #pragma unroll
        for (int kc = 0; kc < 4; kc++) {
            uint32_t ah[4][4], al[4][4];
            #pragma unroll
            for (int mf = 0; mf < 4; mf++) {
                ldsm4(ah[mf], afrag_addr(sAh, mw + mf*16, kc, lane));
                ldsm4(al[mf], afrag_addr(sAl, mw + mf*16, kc, lane));
            }
            #pragma unroll
            for (int nf = 0; nf < 2; nf++) {
                uint32_t bh4[4], bl4[4];
                ldsm4(bh4, bfrag_addr(sBh, nw + nf*16, kc, lane));
                ldsm4(bl4, bfrag_addr(sBl, nw + nf*16, kc, lane));
                #pragma unroll
                for (int mf = 0; mf < 4; mf++) {
                    mma16816(acc[mf][2*nf],   ah[mf], bh4 + 0);
                    mma16816(acc[mf][2*nf],   ah[mf], bl4 + 0);
                    mma16816(acc[mf][2*nf],   al[mf], bh4 + 0);
                    mma16816(acc[mf][2*nf+1], ah[mf], bh4 + 2);
                    mma16816(acc[mf][2*nf+1], ah[mf], bl4 + 2);
                    mma16816(acc[mf][2*nf+1], al[mf], bh4 + 2);
                }
            }
        }
        __syncthreads();
    }

    // epilogue: block covers exactly one head's 64 dims (or one third's slice)
    const int which = n_blk >> 9;
    const int h = (n_blk >> 6) & 7;
    __nv_bfloat16 *dh, *dl;
    float sc = 1.0f;
    if (which == 0)      { dh = g_Qh; dl = g_Ql; sc = QK_SCALE; }
    else if (which == 1) { dh = g_Kh; dl = g_Kl; }
    else                 { dh = g_Vh; dl = g_Vl; }

    #pragma unroll
    for (int mf = 0; mf < 4; mf++) {
        int r0 = m_blk + mw + mf*16 + g;
        int b_ = r0 >> 10;
        int nr = r0 & 1023;
        size_t rb0 = ((size_t)(b_ * HEADS + h) * NPOS + nr) * DH;
        size_t rb1 = rb0 + 8 * DH;
        #pragma unroll
        for (int j = 0; j < 4; j++) {
            int c = nw + j * 8 + tig * 2;
            uint32_t hi, lo;
            split_pair(acc[mf][j][0] * sc, acc[mf][j][1] * sc, hi, lo);
            *reinterpret_cast<uint32_t*>(&dh[rb0 + c]) = hi;
            *reinterpret_cast<uint32_t*>(&dl[rb0 + c]) = lo;
            split_pair(acc[mf][j][2] * sc, acc[mf][j][3] * sc, hi, lo);
            *reinterpret_cast<uint32_t*>(&dh[rb1 + c]) = hi;
            *reinterpret_cast<uint32_t*>(&dl[rb1 + c]) = lo;
        }
    }
}

// ---------------------------------------------------------------------------
// Kernel 2: FA2-style mma.sync attention (unchanged from R4)
// ---------------------------------------------------------------------------
__global__ __launch_bounds__(128) void attn_mma_kernel()
{
    __shared__ uint8_t Kh_s[8192], Kl_s[8192], Vh_s[8192], Vl_s[8192];

    const int tid  = threadIdx.x;
    const int lane = tid & 31;
    const int wid  = tid >> 5;
    const int bh   = blockIdx.y;
    const int qb   = blockIdx.x * 64 + wid * 16;
    const int g    = lane >> 2;
    const int tig  = lane & 3;

    uint32_t qh[4][4], ql[4][4];
    {
        const __nv_bfloat16* Qh = g_Qh + (size_t)bh * NPOS * DH;
        const __nv_bfloat16* Ql = g_Ql + (size_t)bh * NPOS * DH;
        int r = qb + g;
        #pragma unroll
        for (int kc = 0; kc < 4; kc++) {
            int c0 = kc * 16 + tig * 2;
            qh[kc][0] = *reinterpret_cast<const uint32_t*>(Qh + (size_t)r*DH + c0);
            qh[kc][1] = *reinterpret_cast<const uint32_t*>(Qh + (size_t)(r+8)*DH + c0);
            qh[kc][2] = *reinterpret_cast<const uint32_t*>(Qh + (size_t)r*DH + c0 + 8);
            qh[kc][3] = *reinterpret_cast<const uint32_t*>(Qh + (size_t)(r+8)*DH + c0 + 8);
            ql[kc][0] = *reinterpret_cast<const uint32_t*>(Ql + (size_t)r*DH + c0);
            ql[kc][1] = *reinterpret_cast<const uint32_t*>(Ql + (size_t)(r+8)*DH + c0);
            ql[kc][2] = *reinterpret_cast<const uint32_t*>(Ql + (size_t)r*DH + c0 + 8);
            ql[kc][3] = *reinterpret_cast<const uint32_t*>(Ql + (size_t)(r+8)*DH + c0 + 8);
        }
    }

    float oc[8][4];
    #pragma unroll
    for (int i = 0; i < 8; i++)
        #pragma unroll
        for (int j = 0; j < 4; j++) oc[i][j] = 0.0f;
    float lsum0 = 0.0f, lsum1 = 0.0f;

    const __nv_bfloat16* gKh = g_Kh + (size_t)bh * NPOS * DH;
    const __nv_bfloat16* gKl = g_Kl + (size_t)bh * NPOS * DH;
    const __nv_bfloat16* gVh = g_Vh + (size_t)bh * NPOS * DH;
    const __nv_bfloat16* gVl = g_Vl + (size_t)bh * NPOS * DH;

    const uint32_t sKh = smem_u32(Kh_s), sKl = smem_u32(Kl_s);
    const uint32_t sVh = smem_u32(Vh_s), sVl = smem_u32(Vl_s);

    for (int kt = 0; kt < 16; kt++) {
        #pragma unroll
        for (int i = 0; i < 4; i++) {
            int idx = i * 128 + tid;
            int row = idx >> 3, ch = idx & 7;
            uint32_t dsto = (uint32_t)(row * 128 + ((ch ^ (row & 7)) << 4));
            *reinterpret_cast<uint4*>(Kh_s + dsto) =
                *reinterpret_cast<const uint4*>(gKh + (size_t)(kt*64 + row)*DH + ch*8);
            *reinterpret_cast<uint4*>(Kl_s + dsto) =
                *reinterpret_cast<const uint4*>(gKl + (size_t)(kt*64 + row)*DH + ch*8);
            *reinterpret_cast<uint4*>(Vh_s + dsto) =
                *reinterpret_cast<const uint4*>(gVh + (size_t)(kt*64 + row)*DH + ch*8);
            *reinterpret_cast<uint4*>(Vl_s + dsto) =
                *reinterpret_cast<const uint4*>(gVl + (size_t)(kt*64 + row)*DH + ch*8);
        }
        __syncthreads();

        float s[8][4];
        #pragma unroll
        for (int i = 0; i < 8; i++)
            #pragma unroll
            for (int j = 0; j < 4; j++) s[i][j] = 0.0f;

        #pragma unroll
        for (int np = 0; np < 4; np++) {
            #pragma unroll
            for (int kc = 0; kc < 4; kc++) {
                uint32_t bh4[4], bl4[4];
                ldsm4(bh4, bfrag_addr(sKh, np*16, kc, lane));
                ldsm4(bl4, bfrag_addr(sKl, np*16, kc, lane));
                mma16816(s[2*np],   qh[kc], bh4 + 0);
                mma16816(s[2*np],   qh[kc], bl4 + 0);
                mma16816(s[2*np],   ql[kc], bh4 + 0);
                mma16816(s[2*np+1], qh[kc], bh4 + 2);
                mma16816(s[2*np+1], qh[kc], bl4 + 2);
                mma16816(s[2*np+1], ql[kc], bh4 + 2);
            }
        }

        uint32_t ph[4][4], pl[4][4];
        #pragma unroll
        for (int np = 0; np < 4; np++) {
            float p0[4], p1[4];
            #pragma unroll
            for (int j = 0; j < 4; j++) {
                p0[j] = __expf(s[2*np][j]);
                p1[j] = __expf(s[2*np+1][j]);
            }
            lsum0 += p0[0] + p0[1] + p1[0] + p1[1];
            lsum1 += p0[2] + p0[3] + p1[2] + p1[3];
            split_pair(p0[0], p0[1], ph[np][0], pl[np][0]);
            split_pair(p0[2], p0[3], ph[np][1], pl[np][1]);
            split_pair(p1[0], p1[1], ph[np][2], pl[np][2]);
            split_pair(p1[2], p1[3], ph[np][3], pl[np][3]);
        }

        #pragma unroll
        for (int vp = 0; vp < 4; vp++) {
            #pragma unroll
            for (int jc = 0; jc < 4; jc++) {
                uint32_t vh4[4], vl4[4];
                ldsm4t(vh4, afrag_addr(sVh, jc*16, vp, lane));
                ldsm4t(vl4, afrag_addr(sVl, jc*16, vp, lane));
                mma16816(oc[2*vp],   ph[jc], vh4 + 0);
                mma16816(oc[2*vp],   ph[jc], vl4 + 0);
                mma16816(oc[2*vp],   pl[jc], vh4 + 0);
                mma16816(oc[2*vp+1], ph[jc], vh4 + 2);
                mma16816(oc[2*vp+1], ph[jc], vl4 + 2);
                mma16816(oc[2*vp+1], pl[jc], vh4 + 2);
            }
        }
        __syncthreads();
    }

    lsum0 += __shfl_xor_sync(0xffffffffu, lsum0, 1);
    lsum0 += __shfl_xor_sync(0xffffffffu, lsum0, 2);
    lsum1 += __shfl_xor_sync(0xffffffffu, lsum1, 1);
    lsum1 += __shfl_xor_sync(0xffffffffu, lsum1, 2);
    float inv0 = 1.0f / lsum0;
    float inv1 = 1.0f / lsum1;

    int b = bh >> 3, h = bh & 7;
    int q0 = qb + g, q1 = qb + g + 8;
    size_t row0 = ((size_t)(b * AD + h * 64 + (q0 >> 4))) * NPOS + ((q0 & 15) << 6);
    size_t row1 = ((size_t)(b * AD + h * 64 + (q1 >> 4))) * NPOS + ((q1 & 15) << 6);
    #pragma unroll
    for (int ct = 0; ct < 8; ct++) {
        int c = ct * 8 + tig * 2;
        uint32_t hi, lo;
        split_pair(oc[ct][0] * inv0, oc[ct][1] * inv0, hi, lo);
        *reinterpret_cast<uint32_t*>(&g_A2h[row0 + c]) = hi;
        *reinterpret_cast<uint32_t*>(&g_A2l[row0 + c]) = lo;
        split_pair(oc[ct][2] * inv1, oc[ct][3] * inv1, hi, lo);
        *reinterpret_cast<uint32_t*>(&g_A2h[row1 + c]) = hi;
        *reinterpret_cast<uint32_t*>(&g_A2l[row1 + c]) = lo;
    }
}

// ---------------------------------------------------------------------------
// Kernel 3: out GEMM. Block 128pos x 64d, warp tile 64x32. Grid (8, 4, 8).
// A-frags via ldmatrix.trans from A2 [ch][pos] tiles staged with 256B rows.
// ---------------------------------------------------------------------------
__global__ __launch_bounds__(128, 3) void out_mma_kernel(const float* __restrict__ bout)
{
    __shared__ uint8_t Ah_s[16384], Al_s[16384], Bh_s[8192], Bl_s[8192];

    const int tid = threadIdx.x, lane = tid & 31, wid = tid >> 5;
    const int m_blk = blockIdx.x * 128;  // pos
    const int n_blk = blockIdx.y * 64;   // d
    const int bb = blockIdx.z;
    const int mw = (wid >> 1) * 64;
    const int nw = (wid & 1) * 32;
    const int g = lane >> 2, tig = lane & 3;

    const uint32_t sAh = smem_u32(Ah_s), sAl = smem_u32(Al_s);
    const uint32_t sBh = smem_u32(Bh_s), sBl = smem_u32(Bl_s);

    float acc[4][4][4];
    #pragma unroll
    for (int i = 0; i < 4; i++)
        #pragma unroll
        for (int j = 0; j < 4; j++)
            #pragma unroll
            for (int k = 0; k < 4; k++) acc[i][j][k] = 0.0f;

    const __nv_bfloat16* A2h = g_A2h + (size_t)bb * AD * NPOS;
    const __nv_bfloat16* A2l = g_A2l + (size_t)bb * AD * NPOS;

    for (int k0 = 0; k0 < AD; k0 += 64) {
        // A tile: 64 ch-rows x 128 pos (256B rows, 16 chunks)
        #pragma unroll
        for (int i = 0; i < 8; i++) {
            int idx = i * 128 + tid;           // 1024 chunks
            int row = idx >> 4, ch = idx & 15;
            uint32_t dsto = (uint32_t)(row * 256 + (((ch & 8) | ((ch & 7) ^ (row & 7))) << 4));
            *reinterpret_cast<uint4*>(Ah_s + dsto) =
                *reinterpret_cast<const uint4*>(A2h + (size_t)(k0 + row) * NPOS + m_blk + ch*8);
            *reinterpret_cast<uint4*>(Al_s + dsto) =
                *reinterpret_cast<const uint4*>(A2l + (size_t)(k0 + row) * NPOS + m_blk + ch*8);
        }
        // B tile: 64 d-rows x 64 ch (128B rows)
        #pragma unroll
        for (int i = 0; i < 4; i++) {
            int idx = i * 128 + tid;
            int row = idx >> 3, ch = idx & 7;
            uint32_t dsto = (uint32_t)(row * 128 + ((ch ^ (row & 7)) << 4));
            *reinterpret_cast<uint4*>(Bh_s + dsto) =
                *reinterpret_cast<const uint4*>(g_Woh + (size_t)(n_blk + row) * AD + k0 + ch*8);
            *reinterpret_cast<uint4*>(Bl_s + dsto) =
                *reinterpret_cast<const uint4*>(g_Wol + (size_t)(n_blk + row) * AD + k0 + ch*8);
        }
        __syncthreads();

        #pragma unroll
        for (int kc = 0; kc < 4; kc++) {
            uint32_t ah[4][4], al[4][4];
            #pragma unroll
            for (int mf = 0; mf < 4; mf++) {
                ldsm4t(ah[mf], afragT256_addr(sAh, kc*16, mw + mf*16, lane));
                ldsm4t(al[mf], afragT256_addr(sAl, kc*16, mw + mf*16, lane));
            }
            #pragma unroll
            for (int nf = 0; nf < 2; nf++) {
                uint32_t bh4[4], bl4[4];
                ldsm4(bh4, bfrag_addr(sBh, nw + nf*16, kc, lane));
                ldsm4(bl4, bfrag_addr(sBl, nw + nf*16, kc, lane));
                #pragma unroll
                for (int mf = 0; mf < 4; mf++) {
                    mma16816(acc[mf][2*nf],   ah[mf], bh4 + 0);
                    mma16816(acc[mf][2*nf],   ah[mf], bl4 + 0);
                    mma16816(acc[mf][2*nf],   al[mf], bh4 + 0);
                    mma16816(acc[mf][2*nf+1], ah[mf], bh4 + 2);
                    mma16816(acc[mf][2*nf+1], ah[mf], bl4 + 2);
                    mma16816(acc[mf][2*nf+1], al[mf], bh4 + 2);
                }
            }
        }
        __syncthreads();
    }

    #pragma unroll
    for (int mf = 0; mf < 4; mf++) {
        int r0 = m_blk + mw + mf*16 + g;
        #pragma unroll
        for (int j = 0; j < 4; j++) {
            int d = n_blk + nw + j * 8 + tig * 2;
            float2 bv = *reinterpret_cast<const float2*>(&bout[d]);
            float2 v0 = make_float2(acc[mf][j][0] + bv.x, acc[mf][j][1] + bv.y);
            float2 v1 = make_float2(acc[mf][j][2] + bv.x, acc[mf][j][3] + bv.y);
            *reinterpret_cast<float2*>(&g_Y[((size_t)bb*NPOS + r0)*COUT + d]) = v0;
            *reinterpret_cast<float2*>(&g_Y[((size_t)bb*NPOS + r0 + 8)*COUT + d]) = v1;
        }
    }
}

// ---------------------------------------------------------------------------
// GroupNorm
// ---------------------------------------------------------------------------
__global__ __launch_bounds__(256) void gn_part_kernel()
{
    const int blk = blockIdx.x;
    const int b = blk >> 3, sl = blk & 7;
    const int t = threadIdx.x;
    const float4* Y4 = reinterpret_cast<const float4*>(g_Y + (size_t)b * NPOS * COUT) + sl * 8192;

    float s = 0.0f, ss = 0.0f;
    #pragma unroll 4
    for (int i = t; i < 8192; i += 256) {
        float4 v = Y4[i];
        s  += v.x + v.y + v.z + v.w;
        ss += v.x*v.x + v.y*v.y + v.z*v.z + v.w*v.w;
    }
    __shared__ float rs[256], rss[256];
    rs[t] = s; rss[t] = ss;
    __syncthreads();
    for (int st = 128; st > 0; st >>= 1) {
        if (t < st) { rs[t] += rs[t + st]; rss[t] += rss[t + st]; }
        __syncthreads();
    }
    if (t == 0) { g_part[blk*2] = rs[0]; g_part[blk*2+1] = rss[0]; }
}

__global__ void gn_final_kernel()
{
    int b = threadIdx.x;
    if (b < NB) {
        float s = 0.0f, ss = 0.0f;
        #pragma unroll
        for (int i = 0; i < 8; i++) {
            s  += g_part[(b*8 + i)*2];
            ss += g_part[(b*8 + i)*2 + 1];
        }
        const float inv_n = 1.0f / (float)(NPOS * COUT);
        float mean = s * inv_n;
        float var  = ss * inv_n - mean * mean;
        g_stats[2*b]     = mean;
        g_stats[2*b + 1] = rsqrtf(var + GN_EPS);
    }
}

__global__ __launch_bounds__(256) void gn_norm_kernel(
    const float* __restrict__ gamma, const float* __restrict__ beta,
    float* __restrict__ out)
{
    int idx4 = blockIdx.x * 256 + threadIdx.x;
    int b  = idx4 >> 16;
    int d4 = idx4 & 63;

    float mean = g_stats[2*b];
    float rstd = g_stats[2*b + 1];

    float4 y  = reinterpret_cast<const float4*>(g_Y)[idx4];
    float4 g  = reinterpret_cast<const float4*>(gamma)[d4];
    float4 be = reinterpret_cast<const float4*>(beta)[d4];

    float4 r;
    r.x = (y.x - mean) * rstd * g.x + be.x;
    r.y = (y.y - mean) * rstd * g.y + be.y;
    r.z = (y.z - mean) * rstd * g.z + be.z;
    r.w = (y.w - mean) * rstd * g.w + be.w;
    reinterpret_cast<float4*>(out)[idx4] = r;
}

// ---------------------------------------------------------------------------
extern "C" void kernel_launch(void* const* d_in, const int* in_sizes, int n_in,
                              void* d_out, int out_size)
{
    const float* x      = (const float*)d_in[0];
    const float* w_qkv  = (const float*)d_in[1];
    const float* w_out  = (const float*)d_in[2];
    const float* b_out  = (const float*)d_in[3];
    const float* gamma  = (const float*)d_in[4];
    const float* beta   = (const float*)d_in[5];
    float* out = (float*)d_out;

    conv_x_kernel<<<2048, 256>>>(x);
    conv_w_kernel<<<dim3(48, 8),  dim3(32, 32)>>>(w_qkv, CIN, 3*AD, 0);
    conv_w_kernel<<<dim3(8, 16),  dim3(32, 32)>>>(w_out, AD, COUT, 1);
    qkv_mma_kernel<<<dim3(64, 24), 128>>>();
    attn_mma_kernel<<<dim3(16, 64), 128>>>();
    out_mma_kernel<<<dim3(8, 4, 8), 128>>>(b_out);
    gn_part_kernel<<<64, 256>>>();
    gn_final_kernel<<<1, 32>>>();
    gn_norm_kernel<<<2048, 256>>>(gamma, beta, out);
}

// round 6
// speedup vs baseline: 5.5192x; 1.1175x over previous
#include <cuda_runtime.h>
#include <cuda_bf16.h>
#include <cstdint>

#define NB    8
#define NPOS  1024
#define CIN   256
#define HEADS 8
#define DH    64
#define AD    512
#define COUT  256
#define QK_SCALE 0.125f
#define GN_EPS 1e-5f

// ---------------------------------------------------------------------------
// helpers
// ---------------------------------------------------------------------------
__device__ __forceinline__ uint32_t smem_u32(const void* p) {
    uint32_t a;
    asm("{ .reg .u64 t; cvta.to.shared.u64 t, %1; cvt.u32.u64 %0, t; }" : "=r"(a) : "l"(p));
    return a;
}

__device__ __forceinline__ void split_pair(float a, float b, uint32_t& hi, uint32_t& lo)
{
    __nv_bfloat16 ah = __float2bfloat16(a);
    __nv_bfloat16 bh = __float2bfloat16(b);
    float al = a - __bfloat162float(ah);
    float bl = b - __bfloat162float(bh);
    __nv_bfloat16 alh = __float2bfloat16(al);
    __nv_bfloat16 blh = __float2bfloat16(bl);
    hi = ((uint32_t)__bfloat16_as_ushort(bh)  << 16) | (uint32_t)__bfloat16_as_ushort(ah);
    lo = ((uint32_t)__bfloat16_as_ushort(blh) << 16) | (uint32_t)__bfloat16_as_ushort(alh);
}

__device__ __forceinline__ void mma16816(float* c, const uint32_t* a, const uint32_t* b)
{
    asm volatile("mma.sync.aligned.m16n8k16.row.col.f32.bf16.bf16.f32 "
        "{%0,%1,%2,%3},{%4,%5,%6,%7},{%8,%9},{%0,%1,%2,%3};"
        : "+f"(c[0]), "+f"(c[1]), "+f"(c[2]), "+f"(c[3])
        : "r"(a[0]), "r"(a[1]), "r"(a[2]), "r"(a[3]), "r"(b[0]), "r"(b[1]));
}

__device__ __forceinline__ void ldsm4(uint32_t* r, uint32_t addr)
{
    asm volatile("ldmatrix.sync.aligned.m8n8.x4.shared.b16 {%0,%1,%2,%3}, [%4];"
        : "=r"(r[0]), "=r"(r[1]), "=r"(r[2]), "=r"(r[3]) : "r"(addr));
}
__device__ __forceinline__ void ldsm4t(uint32_t* r, uint32_t addr)
{
    asm volatile("ldmatrix.sync.aligned.m8n8.x4.trans.shared.b16 {%0,%1,%2,%3}, [%4];"
        : "=r"(r[0]), "=r"(r[1]), "=r"(r[2]), "=r"(r[3]) : "r"(addr));
}

__device__ __forceinline__ void cp16(uint32_t dst, const void* src)
{
    asm volatile("cp.async.cg.shared.global [%0], [%1], 16;" :: "r"(dst), "l"(src));
}

// ---- 128B-row swizzled tiles ----
__device__ __forceinline__ uint32_t sw_addr(uint32_t base, int row, int ch) {
    return base + row * 128 + ((ch ^ (row & 7)) << 4);
}
__device__ __forceinline__ uint32_t afrag_addr(uint32_t base, int r0, int chunk, int lane) {
    int row = r0 + (lane & 7) + ((lane >> 3) & 1) * 8;
    int ch  = 2 * chunk + (lane >> 4);
    return sw_addr(base, row, ch);
}
__device__ __forceinline__ uint32_t bfrag_addr(uint32_t base, int n0, int kc, int lane) {
    int row = n0 + (lane & 7) + ((lane >> 4) & 1) * 8;
    int ch  = 2 * kc + ((lane >> 3) & 1);
    return sw_addr(base, row, ch);
}
// ---- 256B-row swizzled tiles ----
__device__ __forceinline__ uint32_t sw256_addr(uint32_t base, int row, int ch) {
    return base + row * 256 + (((ch & 8) | ((ch & 7) ^ (row & 7))) << 4);
}
__device__ __forceinline__ uint32_t afragT256_addr(uint32_t base, int k0, int m0, int lane) {
    int row = k0 + (lane & 7) + ((lane >> 4) & 1) * 8;
    int ch  = (m0 >> 3) + ((lane >> 3) & 1);
    return sw256_addr(base, row, ch);
}

// ---------------------------------------------------------------------------
// Scratch globals
// ---------------------------------------------------------------------------
__device__ __nv_bfloat16 g_Xh[NB * NPOS * CIN];
__device__ __nv_bfloat16 g_Xl[NB * NPOS * CIN];
__device__ __nv_bfloat16 g_Wqh[3 * AD * CIN];
__device__ __nv_bfloat16 g_Wql[3 * AD * CIN];
__device__ __nv_bfloat16 g_Woh[COUT * AD];
__device__ __nv_bfloat16 g_Wol[COUT * AD];
__device__ __nv_bfloat16 g_Qh[NB * HEADS * NPOS * DH];
__device__ __nv_bfloat16 g_Ql[NB * HEADS * NPOS * DH];
__device__ __nv_bfloat16 g_Kh[NB * HEADS * NPOS * DH];
__device__ __nv_bfloat16 g_Kl[NB * HEADS * NPOS * DH];
__device__ __nv_bfloat16 g_Vh[NB * HEADS * NPOS * DH];
__device__ __nv_bfloat16 g_Vl[NB * HEADS * NPOS * DH];
__device__ __nv_bfloat16 g_A2h[NB * AD * NPOS];
__device__ __nv_bfloat16 g_A2l[NB * AD * NPOS];
__device__ float g_Y[NB * NPOS * COUT];
__device__ float g_part[512];                      // 256 out-blocks x (sum, sumsq)
__device__ float g_stats[2 * NB];

// ---------------------------------------------------------------------------
// Kernel 0a: X -> split bf16
// ---------------------------------------------------------------------------
__global__ __launch_bounds__(256) void conv_x_kernel(const float* __restrict__ X)
{
    int idx4 = blockIdx.x * 256 + threadIdx.x;
    float4 v = reinterpret_cast<const float4*>(X)[idx4];
    uint32_t h0, l0, h1, l1;
    split_pair(v.x, v.y, h0, l0);
    split_pair(v.z, v.w, h1, l1);
    reinterpret_cast<uint2*>(g_Xh)[idx4] = make_uint2(h0, h1);
    reinterpret_cast<uint2*>(g_Xl)[idx4] = make_uint2(l0, l1);
}

// ---------------------------------------------------------------------------
// Kernel 0b: weight transpose + split. src [K][N] -> dst [N][K].
// ---------------------------------------------------------------------------
__global__ void conv_w_kernel(const float* __restrict__ src, int K, int N, int which)
{
    __shared__ float tile[32][33];
    int n0 = blockIdx.x * 32;
    int k0 = blockIdx.y * 32;
    int tx = threadIdx.x, ty = threadIdx.y;
    tile[ty][tx] = src[(size_t)(k0 + ty) * N + n0 + tx];
    __syncthreads();
    if (tx < 16) {
        __nv_bfloat16* dh = which ? g_Woh : g_Wqh;
        __nv_bfloat16* dl = which ? g_Wol : g_Wql;
        uint32_t hi, lo;
        split_pair(tile[2*tx][ty], tile[2*tx+1][ty], hi, lo);
        size_t off = (size_t)(n0 + ty) * K + k0 + 2*tx;
        *reinterpret_cast<uint32_t*>(&dh[off]) = hi;
        *reinterpret_cast<uint32_t*>(&dl[off]) = lo;
    }
}

// ---------------------------------------------------------------------------
// Kernel 1: QKV GEMM. Block 128m x 64n, warp tile 64x32. Product-major MMAs.
// ---------------------------------------------------------------------------
__global__ __launch_bounds__(128, 3) void qkv_mma_kernel()
{
    __shared__ uint8_t Ah_s[16384], Al_s[16384], Bh_s[8192], Bl_s[8192];

    const int tid = threadIdx.x, lane = tid & 31, wid = tid >> 5;
    const int m_blk = blockIdx.x * 128;
    const int n_blk = blockIdx.y * 64;
    const int mw = (wid >> 1) * 64;
    const int nw = (wid & 1) * 32;
    const int g = lane >> 2, tig = lane & 3;

    const uint32_t sAh = smem_u32(Ah_s), sAl = smem_u32(Al_s);
    const uint32_t sBh = smem_u32(Bh_s), sBl = smem_u32(Bl_s);

    float acc[4][4][4];
    #pragma unroll
    for (int i = 0; i < 4; i++)
        #pragma unroll
        for (int j = 0; j < 4; j++)
            #pragma unroll
            for (int k = 0; k < 4; k++) acc[i][j][k] = 0.0f;

    for (int k0 = 0; k0 < CIN; k0 += 64) {
        #pragma unroll
        for (int i = 0; i < 8; i++) {
            int idx = i * 128 + tid;
            int row = idx >> 3, ch = idx & 7;
            uint32_t dsto = (uint32_t)(row * 128 + ((ch ^ (row & 7)) << 4));
            *reinterpret_cast<uint4*>(Ah_s + dsto) =
                *reinterpret_cast<const uint4*>(g_Xh + (size_t)(m_blk + row) * CIN + k0 + ch*8);
            *reinterpret_cast<uint4*>(Al_s + dsto) =
                *reinterpret_cast<const uint4*>(g_Xl + (size_t)(m_blk + row) * CIN + k0 + ch*8);
        }
        #pragma unroll
        for (int i = 0; i < 4; i++) {
            int idx = i * 128 + tid;
            int row = idx >> 3, ch = idx & 7;
            uint32_t dsto = (uint32_t)(row * 128 + ((ch ^ (row & 7)) << 4));
            *reinterpret_cast<uint4*>(Bh_s + dsto) =
                *reinterpret_cast<const uint4*>(g_Wqh + (size_t)(n_blk + row) * CIN + k0 + ch*8);
            *reinterpret_cast<uint4*>(Bl_s + dsto) =
                *reinterpret_cast<const uint4*>(g_Wql + (size_t)(n_blk + row) * CIN + k0 + ch*8);
        }
        __syncthreads();

        #pragma unroll
        for (int kc = 0; kc < 4; kc++) {
            uint32_t ah[4][4], al[4][4], bh[2][4], bl[2][4];
            #pragma unroll
            for (int mf = 0; mf < 4; mf++) {
                ldsm4(ah[mf], afrag_addr(sAh, mw + mf*16, kc, lane));
                ldsm4(al[mf], afrag_addr(sAl, mw + mf*16, kc, lane));
            }
            #pragma unroll
            for (int nf = 0; nf < 2; nf++) {
                ldsm4(bh[nf], bfrag_addr(sBh, nw + nf*16, kc, lane));
                ldsm4(bl[nf], bfrag_addr(sBl, nw + nf*16, kc, lane));
            }
            // product-major: hi*hi, hi*lo, lo*hi — each acc touched once per group
            #pragma unroll
            for (int mf = 0; mf < 4; mf++)
                #pragma unroll
                for (int nf = 0; nf < 2; nf++) {
                    mma16816(acc[mf][2*nf],   ah[mf], bh[nf] + 0);
                    mma16816(acc[mf][2*nf+1], ah[mf], bh[nf] + 2);
                }
            #pragma unroll
            for (int mf = 0; mf < 4; mf++)
                #pragma unroll
                for (int nf = 0; nf < 2; nf++) {
                    mma16816(acc[mf][2*nf],   ah[mf], bl[nf] + 0);
                    mma16816(acc[mf][2*nf+1], ah[mf], bl[nf] + 2);
                }
            #pragma unroll
            for (int mf = 0; mf < 4; mf++)
                #pragma unroll
                for (int nf = 0; nf < 2; nf++) {
                    mma16816(acc[mf][2*nf],   al[mf], bh[nf] + 0);
                    mma16816(acc[mf][2*nf+1], al[mf], bh[nf] + 2);
                }
        }
        __syncthreads();
    }

    const int which = n_blk >> 9;
    const int h = (n_blk >> 6) & 7;
    __nv_bfloat16 *dh, *dl;
    float sc = 1.0f;
    if (which == 0)      { dh = g_Qh; dl = g_Ql; sc = QK_SCALE; }
    else if (which == 1) { dh = g_Kh; dl = g_Kl; }
    else                 { dh = g_Vh; dl = g_Vl; }

    #pragma unroll
    for (int mf = 0; mf < 4; mf++) {
        int r0 = m_blk + mw + mf*16 + g;
        int b_ = r0 >> 10;
        int nr = r0 & 1023;
        size_t rb0 = ((size_t)(b_ * HEADS + h) * NPOS + nr) * DH;
        size_t rb1 = rb0 + 8 * DH;
        #pragma unroll
        for (int j = 0; j < 4; j++) {
            int c = nw + j * 8 + tig * 2;
            uint32_t hi, lo;
            split_pair(acc[mf][j][0] * sc, acc[mf][j][1] * sc, hi, lo);
            *reinterpret_cast<uint32_t*>(&dh[rb0 + c]) = hi;
            *reinterpret_cast<uint32_t*>(&dl[rb0 + c]) = lo;
            split_pair(acc[mf][j][2] * sc, acc[mf][j][3] * sc, hi, lo);
            *reinterpret_cast<uint32_t*>(&dh[rb1 + c]) = hi;
            *reinterpret_cast<uint32_t*>(&dl[rb1 + c]) = lo;
        }
    }
}

// ---------------------------------------------------------------------------
// Kernel 2: attention — cp.async double-buffered tiles + product-major MMAs.
// Dynamic smem: 2 stages x (Kh|Kl|Vh|Vl) x 8192B = 64 KB.
// ---------------------------------------------------------------------------
__global__ __launch_bounds__(128) void attn_mma_kernel()
{
    extern __shared__ uint8_t dyn_s[];

    const int tid  = threadIdx.x;
    const int lane = tid & 31;
    const int wid  = tid >> 5;
    const int bh   = blockIdx.y;
    const int qb   = blockIdx.x * 64 + wid * 16;
    const int g    = lane >> 2;
    const int tig  = lane & 3;

    const __nv_bfloat16* gKh = g_Kh + (size_t)bh * NPOS * DH;
    const __nv_bfloat16* gKl = g_Kl + (size_t)bh * NPOS * DH;
    const __nv_bfloat16* gVh = g_Vh + (size_t)bh * NPOS * DH;
    const __nv_bfloat16* gVl = g_Vl + (size_t)bh * NPOS * DH;

    const uint32_t sbase = smem_u32(dyn_s);

    // Q fragments from gmem
    uint32_t qh[4][4], ql[4][4];
    {
        const __nv_bfloat16* Qh = g_Qh + (size_t)bh * NPOS * DH;
        const __nv_bfloat16* Ql = g_Ql + (size_t)bh * NPOS * DH;
        int r = qb + g;
        #pragma unroll
        for (int kc = 0; kc < 4; kc++) {
            int c0 = kc * 16 + tig * 2;
            qh[kc][0] = *reinterpret_cast<const uint32_t*>(Qh + (size_t)r*DH + c0);
            qh[kc][1] = *reinterpret_cast<const uint32_t*>(Qh + (size_t)(r+8)*DH + c0);
            qh[kc][2] = *reinterpret_cast<const uint32_t*>(Qh + (size_t)r*DH + c0 + 8);
            qh[kc][3] = *reinterpret_cast<const uint32_t*>(Qh + (size_t)(r+8)*DH + c0 + 8);
            ql[kc][0] = *reinterpret_cast<const uint32_t*>(Ql + (size_t)r*DH + c0);
            ql[kc][1] = *reinterpret_cast<const uint32_t*>(Ql + (size_t)(r+8)*DH + c0);
            ql[kc][2] = *reinterpret_cast<const uint32_t*>(Ql + (size_t)r*DH + c0 + 8);
            ql[kc][3] = *reinterpret_cast<const uint32_t*>(Ql + (size_t)(r+8)*DH + c0 + 8);
        }
    }

    float oc[8][4];
    #pragma unroll
    for (int i = 0; i < 8; i++)
        #pragma unroll
        for (int j = 0; j < 4; j++) oc[i][j] = 0.0f;
    float lsum0 = 0.0f, lsum1 = 0.0f;

    // prefetch of one stage (4 arrays, 4 chunks/thread each)
    auto preload = [&](int kt, int buf) {
        uint32_t b0 = sbase + buf * 32768;
        #pragma unroll
        for (int i = 0; i < 4; i++) {
            int idx = i * 128 + tid;
            int row = idx >> 3, ch = idx & 7;
            uint32_t dsto = (uint32_t)(row * 128 + ((ch ^ (row & 7)) << 4));
            size_t go = (size_t)(kt * 64 + row) * DH + ch * 8;
            cp16(b0 + dsto,         gKh + go);
            cp16(b0 + 8192 + dsto,  gKl + go);
            cp16(b0 + 16384 + dsto, gVh + go);
            cp16(b0 + 24576 + dsto, gVl + go);
        }
        asm volatile("cp.async.commit_group;" ::: "memory");
    };

    preload(0, 0);

    for (int kt = 0; kt < 16; kt++) {
        const int cur = kt & 1;
        if (kt < 15) {
            preload(kt + 1, cur ^ 1);
            asm volatile("cp.async.wait_group 1;" ::: "memory");
        } else {
            asm volatile("cp.async.wait_group 0;" ::: "memory");
        }
        __syncthreads();

        const uint32_t sKh = sbase + cur * 32768;
        const uint32_t sKl = sKh + 8192;
        const uint32_t sVh = sKh + 16384;
        const uint32_t sVl = sKh + 24576;

        // ---- S = Qh*Kh + Qh*Kl + Ql*Kh (product-major) ----
        float s[8][4];
        #pragma unroll
        for (int i = 0; i < 8; i++)
            #pragma unroll
            for (int j = 0; j < 4; j++) s[i][j] = 0.0f;

        #pragma unroll
        for (int kc = 0; kc < 4; kc++) {
            uint32_t kh[4][4], kl[4][4];
            #pragma unroll
            for (int np = 0; np < 4; np++) {
                ldsm4(kh[np], bfrag_addr(sKh, np*16, kc, lane));
                ldsm4(kl[np], bfrag_addr(sKl, np*16, kc, lane));
            }
            #pragma unroll
            for (int np = 0; np < 4; np++) {
                mma16816(s[2*np],   qh[kc], kh[np] + 0);
                mma16816(s[2*np+1], qh[kc], kh[np] + 2);
            }
            #pragma unroll
            for (int np = 0; np < 4; np++) {
                mma16816(s[2*np],   qh[kc], kl[np] + 0);
                mma16816(s[2*np+1], qh[kc], kl[np] + 2);
            }
            #pragma unroll
            for (int np = 0; np < 4; np++) {
                mma16816(s[2*np],   ql[kc], kh[np] + 0);
                mma16816(s[2*np+1], ql[kc], kh[np] + 2);
            }
        }

        // ---- exp + pack P ----
        uint32_t ph[4][4], pl[4][4];
        #pragma unroll
        for (int np = 0; np < 4; np++) {
            float p0[4], p1[4];
            #pragma unroll
            for (int j = 0; j < 4; j++) {
                p0[j] = __expf(s[2*np][j]);
                p1[j] = __expf(s[2*np+1][j]);
            }
            lsum0 += p0[0] + p0[1] + p1[0] + p1[1];
            lsum1 += p0[2] + p0[3] + p1[2] + p1[3];
            split_pair(p0[0], p0[1], ph[np][0], pl[np][0]);
            split_pair(p0[2], p0[3], ph[np][1], pl[np][1]);
            split_pair(p1[0], p1[1], ph[np][2], pl[np][2]);
            split_pair(p1[2], p1[3], ph[np][3], pl[np][3]);
        }

        // ---- O += P*V (product-major; V frags via ldmatrix.trans) ----
        #pragma unroll
        for (int jc = 0; jc < 4; jc++) {
            uint32_t vh[4][4], vl[4][4];
            #pragma unroll
            for (int vp = 0; vp < 4; vp++) {
                ldsm4t(vh[vp], afrag_addr(sVh, jc*16, vp, lane));
                ldsm4t(vl[vp], afrag_addr(sVl, jc*16, vp, lane));
            }
            #pragma unroll
            for (int vp = 0; vp < 4; vp++) {
                mma16816(oc[2*vp],   ph[jc], vh[vp] + 0);
                mma16816(oc[2*vp+1], ph[jc], vh[vp] + 2);
            }
            #pragma unroll
            for (int vp = 0; vp < 4; vp++) {
                mma16816(oc[2*vp],   ph[jc], vl[vp] + 0);
                mma16816(oc[2*vp+1], ph[jc], vl[vp] + 2);
            }
            #pragma unroll
            for (int vp = 0; vp < 4; vp++) {
                mma16816(oc[2*vp],   pl[jc], vh[vp] + 0);
                mma16816(oc[2*vp+1], pl[jc], vh[vp] + 2);
            }
        }
        __syncthreads();
    }

    lsum0 += __shfl_xor_sync(0xffffffffu, lsum0, 1);
    lsum0 += __shfl_xor_sync(0xffffffffu, lsum0, 2);
    lsum1 += __shfl_xor_sync(0xffffffffu, lsum1, 1);
    lsum1 += __shfl_xor_sync(0xffffffffu, lsum1, 2);
    float inv0 = 1.0f / lsum0;
    float inv1 = 1.0f / lsum1;

    int b = bh >> 3, h = bh & 7;
    int q0 = qb + g, q1 = qb + g + 8;
    size_t row0 = ((size_t)(b * AD + h * 64 + (q0 >> 4))) * NPOS + ((q0 & 15) << 6);
    size_t row1 = ((size_t)(b * AD + h * 64 + (q1 >> 4))) * NPOS + ((q1 & 15) << 6);
    #pragma unroll
    for (int ct = 0; ct < 8; ct++) {
        int c = ct * 8 + tig * 2;
        uint32_t hi, lo;
        split_pair(oc[ct][0] * inv0, oc[ct][1] * inv0, hi, lo);
        *reinterpret_cast<uint32_t*>(&g_A2h[row0 + c]) = hi;
        *reinterpret_cast<uint32_t*>(&g_A2l[row0 + c]) = lo;
        split_pair(oc[ct][2] * inv1, oc[ct][3] * inv1, hi, lo);
        *reinterpret_cast<uint32_t*>(&g_A2h[row1 + c]) = hi;
        *reinterpret_cast<uint32_t*>(&g_A2l[row1 + c]) = lo;
    }
}

// ---------------------------------------------------------------------------
// Kernel 3: out GEMM + fused GN partial reduction (deterministic).
// ---------------------------------------------------------------------------
__global__ __launch_bounds__(128, 3) void out_mma_kernel(const float* __restrict__ bout)
{
    __shared__ uint8_t Ah_s[16384], Al_s[16384], Bh_s[8192], Bl_s[8192];

    const int tid = threadIdx.x, lane = tid & 31, wid = tid >> 5;
    const int m_blk = blockIdx.x * 128;
    const int n_blk = blockIdx.y * 64;
    const int bb = blockIdx.z;
    const int mw = (wid >> 1) * 64;
    const int nw = (wid & 1) * 32;
    const int g = lane >> 2, tig = lane & 3;

    const uint32_t sAh = smem_u32(Ah_s), sAl = smem_u32(Al_s);
    const uint32_t sBh = smem_u32(Bh_s), sBl = smem_u32(Bl_s);

    float acc[4][4][4];
    #pragma unroll
    for (int i = 0; i < 4; i++)
        #pragma unroll
        for (int j = 0; j < 4; j++)
            #pragma unroll
            for (int k = 0; k < 4; k++) acc[i][j][k] = 0.0f;

    const __nv_bfloat16* A2h = g_A2h + (size_t)bb * AD * NPOS;
    const __nv_bfloat16* A2l = g_A2l + (size_t)bb * AD * NPOS;

    for (int k0 = 0; k0 < AD; k0 += 64) {
        #pragma unroll
        for (int i = 0; i < 8; i++) {
            int idx = i * 128 + tid;
            int row = idx >> 4, ch = idx & 15;
            uint32_t dsto = (uint32_t)(row * 256 + (((ch & 8) | ((ch & 7) ^ (row & 7))) << 4));
            *reinterpret_cast<uint4*>(Ah_s + dsto) =
                *reinterpret_cast<const uint4*>(A2h + (size_t)(k0 + row) * NPOS + m_blk + ch*8);
            *reinterpret_cast<uint4*>(Al_s + dsto) =
                *reinterpret_cast<const uint4*>(A2l + (size_t)(k0 + row) * NPOS + m_blk + ch*8);
        }
        #pragma unroll
        for (int i = 0; i < 4; i++) {
            int idx = i * 128 + tid;
            int row = idx >> 3, ch = idx & 7;
            uint32_t dsto = (uint32_t)(row * 128 + ((ch ^ (row & 7)) << 4));
            *reinterpret_cast<uint4*>(Bh_s + dsto) =
                *reinterpret_cast<const uint4*>(g_Woh + (size_t)(n_blk + row) * AD + k0 + ch*8);
            *reinterpret_cast<uint4*>(Bl_s + dsto) =
                *reinterpret_cast<const uint4*>(g_Wol + (size_t)(n_blk + row) * AD + k0 + ch*8);
        }
        __syncthreads();

        #pragma unroll
        for (int kc = 0; kc < 4; kc++) {
            uint32_t ah[4][4], al[4][4], bh[2][4], bl[2][4];
            #pragma unroll
            for (int mf = 0; mf < 4; mf++) {
                ldsm4t(ah[mf], afragT256_addr(sAh, kc*16, mw + mf*16, lane));
                ldsm4t(al[mf], afragT256_addr(sAl, kc*16, mw + mf*16, lane));
            }
            #pragma unroll
            for (int nf = 0; nf < 2; nf++) {
                ldsm4(bh[nf], bfrag_addr(sBh, nw + nf*16, kc, lane));
                ldsm4(bl[nf], bfrag_addr(sBl, nw + nf*16, kc, lane));
            }
            #pragma unroll
            for (int mf = 0; mf < 4; mf++)
                #pragma unroll
                for (int nf = 0; nf < 2; nf++) {
                    mma16816(acc[mf][2*nf],   ah[mf], bh[nf] + 0);
                    mma16816(acc[mf][2*nf+1], ah[mf], bh[nf] + 2);
                }
            #pragma unroll
            for (int mf = 0; mf < 4; mf++)
                #pragma unroll
                for (int nf = 0; nf < 2; nf++) {
                    mma16816(acc[mf][2*nf],   ah[mf], bl[nf] + 0);
                    mma16816(acc[mf][2*nf+1], ah[mf], bl[nf] + 2);
                }
            #pragma unroll
            for (int mf = 0; mf < 4; mf++)
                #pragma unroll
                for (int nf = 0; nf < 2; nf++) {
                    mma16816(acc[mf][2*nf],   al[mf], bh[nf] + 0);
                    mma16816(acc[mf][2*nf+1], al[mf], bh[nf] + 2);
                }
        }
        __syncthreads();
    }

    // epilogue: bias + store + per-thread GN partial
    float psum = 0.0f, psq = 0.0f;
    #pragma unroll
    for (int mf = 0; mf < 4; mf++) {
        int r0 = m_blk + mw + mf*16 + g;
        #pragma unroll
        for (int j = 0; j < 4; j++) {
            int d = n_blk + nw + j * 8 + tig * 2;
            float2 bv = *reinterpret_cast<const float2*>(&bout[d]);
            float2 v0 = make_float2(acc[mf][j][0] + bv.x, acc[mf][j][1] + bv.y);
            float2 v1 = make_float2(acc[mf][j][2] + bv.x, acc[mf][j][3] + bv.y);
            *reinterpret_cast<float2*>(&g_Y[((size_t)bb*NPOS + r0)*COUT + d]) = v0;
            *reinterpret_cast<float2*>(&g_Y[((size_t)bb*NPOS + r0 + 8)*COUT + d]) = v1;
            psum += v0.x + v0.y + v1.x + v1.y;
            psq  += v0.x*v0.x + v0.y*v0.y + v1.x*v1.x + v1.y*v1.y;
        }
    }

    // block reduction reusing B smem (all B reads finished at last __syncthreads)
    float* rs  = reinterpret_cast<float*>(Bh_s);
    float* rss = rs + 128;
    rs[tid] = psum; rss[tid] = psq;
    __syncthreads();
    for (int st = 64; st > 0; st >>= 1) {
        if (tid < st) { rs[tid] += rs[tid + st]; rss[tid] += rss[tid + st]; }
        __syncthreads();
    }
    if (tid == 0) {
        int p = bb * 32 + blockIdx.x * 4 + blockIdx.y;
        g_part[2*p]   = rs[0];
        g_part[2*p+1] = rss[0];
    }
}

// ---------------------------------------------------------------------------
// GN final + normalize
// ---------------------------------------------------------------------------
__global__ void gn_final_kernel()
{
    int b = threadIdx.x;
    if (b < NB) {
        float s = 0.0f, ss = 0.0f;
        #pragma unroll
        for (int i = 0; i < 32; i++) {
            s  += g_part[2*(b*32 + i)];
            ss += g_part[2*(b*32 + i) + 1];
        }
        const float inv_n = 1.0f / (float)(NPOS * COUT);
        float mean = s * inv_n;
        float var  = ss * inv_n - mean * mean;
        g_stats[2*b]     = mean;
        g_stats[2*b + 1] = rsqrtf(var + GN_EPS);
    }
}

__global__ __launch_bounds__(256) void gn_norm_kernel(
    const float* __restrict__ gamma, const float* __restrict__ beta,
    float* __restrict__ out)
{
    int idx4 = blockIdx.x * 256 + threadIdx.x;
    int b  = idx4 >> 16;
    int d4 = idx4 & 63;

    float mean = g_stats[2*b];
    float rstd = g_stats[2*b + 1];

    float4 y  = reinterpret_cast<const float4*>(g_Y)[idx4];
    float4 g  = reinterpret_cast<const float4*>(gamma)[d4];
    float4 be = reinterpret_cast<const float4*>(beta)[d4];

    float4 r;
    r.x = (y.x - mean) * rstd * g.x + be.x;
    r.y = (y.y - mean) * rstd * g.y + be.y;
    r.z = (y.z - mean) * rstd * g.z + be.z;
    r.w = (y.w - mean) * rstd * g.w + be.w;
    reinterpret_cast<float4*>(out)[idx4] = r;
}

// ---------------------------------------------------------------------------
extern "C" void kernel_launch(void* const* d_in, const int* in_sizes, int n_in,
                              void* d_out, int out_size)
{
    const float* x      = (const float*)d_in[0];
    const float* w_qkv  = (const float*)d_in[1];
    const float* w_out  = (const float*)d_in[2];
    const float* b_out  = (const float*)d_in[3];
    const float* gamma  = (const float*)d_in[4];
    const float* beta   = (const float*)d_in[5];
    float* out = (float*)d_out;

    static int attn_smem_set = 0;
    if (!attn_smem_set) {
        cudaFuncSetAttribute(attn_mma_kernel,
                             cudaFuncAttributeMaxDynamicSharedMemorySize, 65536);
        attn_smem_set = 1;
    }

    conv_x_kernel<<<2048, 256>>>(x);
    conv_w_kernel<<<dim3(48, 8),  dim3(32, 32)>>>(w_qkv, CIN, 3*AD, 0);
    conv_w_kernel<<<dim3(8, 16),  dim3(32, 32)>>>(w_out, AD, COUT, 1);
    qkv_mma_kernel<<<dim3(64, 24), 128>>>();
    attn_mma_kernel<<<dim3(16, 64), 128, 65536>>>();
    out_mma_kernel<<<dim3(8, 4, 8), 128>>>(b_out);
    gn_final_kernel<<<1, 32>>>();
    gn_norm_kernel<<<2048, 256>>>(gamma, beta, out);
}

// round 7
// speedup vs baseline: 5.9060x; 1.0701x over previous
#include <cuda_runtime.h>
#include <cuda_bf16.h>
#include <cstdint>

#define NB    8
#define NPOS  1024
#define CIN   256
#define HEADS 8
#define DH    64
#define AD    512
#define COUT  256
#define QK_SCALE 0.125f
#define GN_EPS 1e-5f

// ---------------------------------------------------------------------------
// helpers
// ---------------------------------------------------------------------------
__device__ __forceinline__ uint32_t smem_u32(const void* p) {
    uint32_t a;
    asm("{ .reg .u64 t; cvta.to.shared.u64 t, %1; cvt.u32.u64 %0, t; }" : "=r"(a) : "l"(p));
    return a;
}

__device__ __forceinline__ void split_pair(float a, float b, uint32_t& hi, uint32_t& lo)
{
    __nv_bfloat16 ah = __float2bfloat16(a);
    __nv_bfloat16 bh = __float2bfloat16(b);
    float al = a - __bfloat162float(ah);
    float bl = b - __bfloat162float(bh);
    __nv_bfloat16 alh = __float2bfloat16(al);
    __nv_bfloat16 blh = __float2bfloat16(bl);
    hi = ((uint32_t)__bfloat16_as_ushort(bh)  << 16) | (uint32_t)__bfloat16_as_ushort(ah);
    lo = ((uint32_t)__bfloat16_as_ushort(blh) << 16) | (uint32_t)__bfloat16_as_ushort(alh);
}

__device__ __forceinline__ void mma16816(float* c, const uint32_t* a, const uint32_t* b)
{
    asm volatile("mma.sync.aligned.m16n8k16.row.col.f32.bf16.bf16.f32 "
        "{%0,%1,%2,%3},{%4,%5,%6,%7},{%8,%9},{%0,%1,%2,%3};"
        : "+f"(c[0]), "+f"(c[1]), "+f"(c[2]), "+f"(c[3])
        : "r"(a[0]), "r"(a[1]), "r"(a[2]), "r"(a[3]), "r"(b[0]), "r"(b[1]));
}

__device__ __forceinline__ void ldsm4(uint32_t* r, uint32_t addr)
{
    asm volatile("ldmatrix.sync.aligned.m8n8.x4.shared.b16 {%0,%1,%2,%3}, [%4];"
        : "=r"(r[0]), "=r"(r[1]), "=r"(r[2]), "=r"(r[3]) : "r"(addr));
}
__device__ __forceinline__ void ldsm4t(uint32_t* r, uint32_t addr)
{
    asm volatile("ldmatrix.sync.aligned.m8n8.x4.trans.shared.b16 {%0,%1,%2,%3}, [%4];"
        : "=r"(r[0]), "=r"(r[1]), "=r"(r[2]), "=r"(r[3]) : "r"(addr));
}

__device__ __forceinline__ void cp16(uint32_t dst, const void* src)
{
    asm volatile("cp.async.cg.shared.global [%0], [%1], 16;" :: "r"(dst), "l"(src));
}

// ---- 128B-row swizzled tiles (rows are 128B of k / 64 bf16) ----
__device__ __forceinline__ uint32_t sw_addr(uint32_t base, int row, int ch) {
    return base + row * 128 + ((ch ^ (row & 7)) << 4);
}
__device__ __forceinline__ uint32_t afrag_addr(uint32_t base, int r0, int chunk, int lane) {
    int row = r0 + (lane & 7) + ((lane >> 3) & 1) * 8;
    int ch  = 2 * chunk + (lane >> 4);
    return sw_addr(base, row, ch);
}
__device__ __forceinline__ uint32_t bfrag_addr(uint32_t base, int n0, int kc, int lane) {
    int row = n0 + (lane & 7) + ((lane >> 4) & 1) * 8;
    int ch  = 2 * kc + ((lane >> 3) & 1);
    return sw_addr(base, row, ch);
}

// ---- packed 64B-row tiles (BK=32): 2 logical rows per 128B physical row ----
__device__ __forceinline__ uint32_t swp_off(int lrow, int ch) {   // ch in 0..3
    int prow = lrow >> 1;
    int cp = ((lrow & 1) << 2) | ch;
    return (uint32_t)(prow * 128 + ((cp ^ (prow & 7)) << 4));
}
__device__ __forceinline__ uint32_t afragP_addr(uint32_t base, int r0, int kc, int lane) {
    int lrow = r0 + (lane & 7) + ((lane >> 3) & 1) * 8;
    int ch   = 2 * kc + (lane >> 4);
    return base + swp_off(lrow, ch);
}
__device__ __forceinline__ uint32_t bfragP_addr(uint32_t base, int n0, int kc, int lane) {
    int lrow = n0 + (lane & 7) + ((lane >> 4) & 1) * 8;
    int ch   = 2 * kc + ((lane >> 3) & 1);
    return base + swp_off(lrow, ch);
}

// ---- 256B-row swizzled tiles (A2 [ch][pos] staging) ----
__device__ __forceinline__ uint32_t sw256_off(int row, int ch) {  // ch in 0..15
    return (uint32_t)(row * 256 + (((ch & 8) | ((ch & 7) ^ (row & 7))) << 4));
}
__device__ __forceinline__ uint32_t afragT256_addr(uint32_t base, int k0, int m0, int lane) {
    int row = k0 + (lane & 7) + ((lane >> 4) & 1) * 8;
    int ch  = (m0 >> 3) + ((lane >> 3) & 1);
    return base + sw256_off(row, ch);
}

// ---------------------------------------------------------------------------
// Scratch globals
// ---------------------------------------------------------------------------
__device__ __nv_bfloat16 g_Xh[NB * NPOS * CIN];
__device__ __nv_bfloat16 g_Xl[NB * NPOS * CIN];
__device__ __nv_bfloat16 g_Wqh[3 * AD * CIN];
__device__ __nv_bfloat16 g_Wql[3 * AD * CIN];
__device__ __nv_bfloat16 g_Woh[COUT * AD];
__device__ __nv_bfloat16 g_Wol[COUT * AD];
__device__ __nv_bfloat16 g_Qh[NB * HEADS * NPOS * DH];
__device__ __nv_bfloat16 g_Ql[NB * HEADS * NPOS * DH];
__device__ __nv_bfloat16 g_Kh[NB * HEADS * NPOS * DH];
__device__ __nv_bfloat16 g_Kl[NB * HEADS * NPOS * DH];
__device__ __nv_bfloat16 g_Vh[NB * HEADS * NPOS * DH];
__device__ __nv_bfloat16 g_Vl[NB * HEADS * NPOS * DH];
__device__ __nv_bfloat16 g_A2h[NB * AD * NPOS];
__device__ __nv_bfloat16 g_A2l[NB * AD * NPOS];
__device__ float g_Y[NB * NPOS * COUT];
__device__ float g_part[512];
__device__ float g_stats[2 * NB];

// ---------------------------------------------------------------------------
// Kernel 0a: X -> split bf16
// ---------------------------------------------------------------------------
__global__ __launch_bounds__(256) void conv_x_kernel(const float* __restrict__ X)
{
    int idx4 = blockIdx.x * 256 + threadIdx.x;
    float4 v = reinterpret_cast<const float4*>(X)[idx4];
    uint32_t h0, l0, h1, l1;
    split_pair(v.x, v.y, h0, l0);
    split_pair(v.z, v.w, h1, l1);
    reinterpret_cast<uint2*>(g_Xh)[idx4] = make_uint2(h0, h1);
    reinterpret_cast<uint2*>(g_Xl)[idx4] = make_uint2(l0, l1);
}

// ---------------------------------------------------------------------------
// Kernel 0b: weight transpose + split. src [K][N] -> dst [N][K].
// ---------------------------------------------------------------------------
__global__ void conv_w_kernel(const float* __restrict__ src, int K, int N, int which)
{
    __shared__ float tile[32][33];
    int n0 = blockIdx.x * 32;
    int k0 = blockIdx.y * 32;
    int tx = threadIdx.x, ty = threadIdx.y;
    tile[ty][tx] = src[(size_t)(k0 + ty) * N + n0 + tx];
    __syncthreads();
    if (tx < 16) {
        __nv_bfloat16* dh = which ? g_Woh : g_Wqh;
        __nv_bfloat16* dl = which ? g_Wol : g_Wql;
        uint32_t hi, lo;
        split_pair(tile[2*tx][ty], tile[2*tx+1][ty], hi, lo);
        size_t off = (size_t)(n0 + ty) * K + k0 + 2*tx;
        *reinterpret_cast<uint32_t*>(&dh[off]) = hi;
        *reinterpret_cast<uint32_t*>(&dl[off]) = lo;
    }
}

// ---------------------------------------------------------------------------
// Kernel 1: QKV GEMM. Block 128m x 64n, warp tile 64x32, BK=32,
// cp.async double-buffered (2 x 24KB stages). Grid (64, 24).
// Stage layout: Ah[0,8K) Al[8K,16K) Bh[16K,20K) Bl[20K,24K)
// ---------------------------------------------------------------------------
__global__ __launch_bounds__(128, 3) void qkv_mma_kernel()
{
    extern __shared__ uint8_t dyn_q[];
    const uint32_t sbase = smem_u32(dyn_q);

    const int tid = threadIdx.x, lane = tid & 31, wid = tid >> 5;
    const int m_blk = blockIdx.x * 128;
    const int n_blk = blockIdx.y * 64;
    const int mw = (wid >> 1) * 64;
    const int nw = (wid & 1) * 32;
    const int g = lane >> 2, tig = lane & 3;

    float acc[4][4][4];
    #pragma unroll
    for (int i = 0; i < 4; i++)
        #pragma unroll
        for (int j = 0; j < 4; j++)
            #pragma unroll
            for (int k = 0; k < 4; k++) acc[i][j][k] = 0.0f;

    auto preload = [&](int ks, int buf) {
        uint32_t b0 = sbase + buf * 24576;
        int k0 = ks * 32;
        // A: 128 logical rows x 4 chunks, hi+lo
        #pragma unroll
        for (int i = 0; i < 4; i++) {
            int idx = i * 128 + tid;
            int lrow = idx >> 2, ch = idx & 3;
            uint32_t off = swp_off(lrow, ch);
            size_t go = (size_t)(m_blk + lrow) * CIN + k0 + ch * 8;
            cp16(b0 + off,        g_Xh + go);
            cp16(b0 + 8192 + off, g_Xl + go);
        }
        // B: 64 logical rows x 4 chunks, hi+lo
        #pragma unroll
        for (int i = 0; i < 2; i++) {
            int idx = i * 128 + tid;
            int lrow = idx >> 2, ch = idx & 3;
            uint32_t off = swp_off(lrow, ch);
            size_t go = (size_t)(n_blk + lrow) * CIN + k0 + ch * 8;
            cp16(b0 + 16384 + off, g_Wqh + go);
            cp16(b0 + 20480 + off, g_Wql + go);
        }
        asm volatile("cp.async.commit_group;" ::: "memory");
    };

    preload(0, 0);

    for (int s = 0; s < 8; s++) {
        if (s < 7) {
            preload(s + 1, (s + 1) & 1);
            asm volatile("cp.async.wait_group 1;" ::: "memory");
        } else {
            asm volatile("cp.async.wait_group 0;" ::: "memory");
        }
        __syncthreads();

        uint32_t b0 = sbase + (s & 1) * 24576;
        const uint32_t sAh = b0, sAl = b0 + 8192, sBh = b0 + 16384, sBl = b0 + 20480;

        #pragma unroll
        for (int kc = 0; kc < 2; kc++) {
            uint32_t ah[4][4], al[4][4], bh[2][4], bl[2][4];
            #pragma unroll
            for (int mf = 0; mf < 4; mf++) {
                ldsm4(ah[mf], afragP_addr(sAh, mw + mf*16, kc, lane));
                ldsm4(al[mf], afragP_addr(sAl, mw + mf*16, kc, lane));
            }
            #pragma unroll
            for (int nf = 0; nf < 2; nf++) {
                ldsm4(bh[nf], bfragP_addr(sBh, nw + nf*16, kc, lane));
                ldsm4(bl[nf], bfragP_addr(sBl, nw + nf*16, kc, lane));
            }
            #pragma unroll
            for (int mf = 0; mf < 4; mf++)
                #pragma unroll
                for (int nf = 0; nf < 2; nf++) {
                    mma16816(acc[mf][2*nf],   ah[mf], bh[nf] + 0);
                    mma16816(acc[mf][2*nf+1], ah[mf], bh[nf] + 2);
                }
            #pragma unroll
            for (int mf = 0; mf < 4; mf++)
                #pragma unroll
                for (int nf = 0; nf < 2; nf++) {
                    mma16816(acc[mf][2*nf],   ah[mf], bl[nf] + 0);
                    mma16816(acc[mf][2*nf+1], ah[mf], bl[nf] + 2);
                }
            #pragma unroll
            for (int mf = 0; mf < 4; mf++)
                #pragma unroll
                for (int nf = 0; nf < 2; nf++) {
                    mma16816(acc[mf][2*nf],   al[mf], bh[nf] + 0);
                    mma16816(acc[mf][2*nf+1], al[mf], bh[nf] + 2);
                }
        }
        __syncthreads();
    }

    const int which = n_blk >> 9;
    const int h = (n_blk >> 6) & 7;
    __nv_bfloat16 *dh, *dl;
    float sc = 1.0f;
    if (which == 0)      { dh = g_Qh; dl = g_Ql; sc = QK_SCALE; }
    else if (which == 1) { dh = g_Kh; dl = g_Kl; }
    else                 { dh = g_Vh; dl = g_Vl; }

    #pragma unroll
    for (int mf = 0; mf < 4; mf++) {
        int r0 = m_blk + mw + mf*16 + g;
        int b_ = r0 >> 10;
        int nr = r0 & 1023;
        size_t rb0 = ((size_t)(b_ * HEADS + h) * NPOS + nr) * DH;
        size_t rb1 = rb0 + 8 * DH;
        #pragma unroll
        for (int j = 0; j < 4; j++) {
            int c = nw + j * 8 + tig * 2;
            uint32_t hi, lo;
            split_pair(acc[mf][j][0] * sc, acc[mf][j][1] * sc, hi, lo);
            *reinterpret_cast<uint32_t*>(&dh[rb0 + c]) = hi;
            *reinterpret_cast<uint32_t*>(&dl[rb0 + c]) = lo;
            split_pair(acc[mf][j][2] * sc, acc[mf][j][3] * sc, hi, lo);
            *reinterpret_cast<uint32_t*>(&dh[rb1 + c]) = hi;
            *reinterpret_cast<uint32_t*>(&dl[rb1 + c]) = lo;
        }
    }
}

// ---------------------------------------------------------------------------
// Kernel 2: attention — cp.async double-buffered, product-major (from R6).
// ---------------------------------------------------------------------------
__global__ __launch_bounds__(128) void attn_mma_kernel()
{
    extern __shared__ uint8_t dyn_s[];

    const int tid  = threadIdx.x;
    const int lane = tid & 31;
    const int wid  = tid >> 5;
    const int bh   = blockIdx.y;
    const int qb   = blockIdx.x * 64 + wid * 16;
    const int g    = lane >> 2;
    const int tig  = lane & 3;

    const __nv_bfloat16* gKh = g_Kh + (size_t)bh * NPOS * DH;
    const __nv_bfloat16* gKl = g_Kl + (size_t)bh * NPOS * DH;
    const __nv_bfloat16* gVh = g_Vh + (size_t)bh * NPOS * DH;
    const __nv_bfloat16* gVl = g_Vl + (size_t)bh * NPOS * DH;

    const uint32_t sbase = smem_u32(dyn_s);

    uint32_t qh[4][4], ql[4][4];
    {
        const __nv_bfloat16* Qh = g_Qh + (size_t)bh * NPOS * DH;
        const __nv_bfloat16* Ql = g_Ql + (size_t)bh * NPOS * DH;
        int r = qb + g;
        #pragma unroll
        for (int kc = 0; kc < 4; kc++) {
            int c0 = kc * 16 + tig * 2;
            qh[kc][0] = *reinterpret_cast<const uint32_t*>(Qh + (size_t)r*DH + c0);
            qh[kc][1] = *reinterpret_cast<const uint32_t*>(Qh + (size_t)(r+8)*DH + c0);
            qh[kc][2] = *reinterpret_cast<const uint32_t*>(Qh + (size_t)r*DH + c0 + 8);
            qh[kc][3] = *reinterpret_cast<const uint32_t*>(Qh + (size_t)(r+8)*DH + c0 + 8);
            ql[kc][0] = *reinterpret_cast<const uint32_t*>(Ql + (size_t)r*DH + c0);
            ql[kc][1] = *reinterpret_cast<const uint32_t*>(Ql + (size_t)(r+8)*DH + c0);
            ql[kc][2] = *reinterpret_cast<const uint32_t*>(Ql + (size_t)r*DH + c0 + 8);
            ql[kc][3] = *reinterpret_cast<const uint32_t*>(Ql + (size_t)(r+8)*DH + c0 + 8);
        }
    }

    float oc[8][4];
    #pragma unroll
    for (int i = 0; i < 8; i++)
        #pragma unroll
        for (int j = 0; j < 4; j++) oc[i][j] = 0.0f;
    float lsum0 = 0.0f, lsum1 = 0.0f;

    auto preload = [&](int kt, int buf) {
        uint32_t b0 = sbase + buf * 32768;
        #pragma unroll
        for (int i = 0; i < 4; i++) {
            int idx = i * 128 + tid;
            int row = idx >> 3, ch = idx & 7;
            uint32_t dsto = (uint32_t)(row * 128 + ((ch ^ (row & 7)) << 4));
            size_t go = (size_t)(kt * 64 + row) * DH + ch * 8;
            cp16(b0 + dsto,         gKh + go);
            cp16(b0 + 8192 + dsto,  gKl + go);
            cp16(b0 + 16384 + dsto, gVh + go);
            cp16(b0 + 24576 + dsto, gVl + go);
        }
        asm volatile("cp.async.commit_group;" ::: "memory");
    };

    preload(0, 0);

    for (int kt = 0; kt < 16; kt++) {
        const int cur = kt & 1;
        if (kt < 15) {
            preload(kt + 1, cur ^ 1);
            asm volatile("cp.async.wait_group 1;" ::: "memory");
        } else {
            asm volatile("cp.async.wait_group 0;" ::: "memory");
        }
        __syncthreads();

        const uint32_t sKh = sbase + cur * 32768;
        const uint32_t sKl = sKh + 8192;
        const uint32_t sVh = sKh + 16384;
        const uint32_t sVl = sKh + 24576;

        float s[8][4];
        #pragma unroll
        for (int i = 0; i < 8; i++)
            #pragma unroll
            for (int j = 0; j < 4; j++) s[i][j] = 0.0f;

        #pragma unroll
        for (int kc = 0; kc < 4; kc++) {
            uint32_t kh[4][4], kl[4][4];
            #pragma unroll
            for (int np = 0; np < 4; np++) {
                ldsm4(kh[np], bfrag_addr(sKh, np*16, kc, lane));
                ldsm4(kl[np], bfrag_addr(sKl, np*16, kc, lane));
            }
            #pragma unroll
            for (int np = 0; np < 4; np++) {
                mma16816(s[2*np],   qh[kc], kh[np] + 0);
                mma16816(s[2*np+1], qh[kc], kh[np] + 2);
            }
            #pragma unroll
            for (int np = 0; np < 4; np++) {
                mma16816(s[2*np],   qh[kc], kl[np] + 0);
                mma16816(s[2*np+1], qh[kc], kl[np] + 2);
            }
            #pragma unroll
            for (int np = 0; np < 4; np++) {
                mma16816(s[2*np],   ql[kc], kh[np] + 0);
                mma16816(s[2*np+1], ql[kc], kh[np] + 2);
            }
        }

        uint32_t ph[4][4], pl[4][4];
        #pragma unroll
        for (int np = 0; np < 4; np++) {
            float p0[4], p1[4];
            #pragma unroll
            for (int j = 0; j < 4; j++) {
                p0[j] = __expf(s[2*np][j]);
                p1[j] = __expf(s[2*np+1][j]);
            }
            lsum0 += p0[0] + p0[1] + p1[0] + p1[1];
            lsum1 += p0[2] + p0[3] + p1[2] + p1[3];
            split_pair(p0[0], p0[1], ph[np][0], pl[np][0]);
            split_pair(p0[2], p0[3], ph[np][1], pl[np][1]);
            split_pair(p1[0], p1[1], ph[np][2], pl[np][2]);
            split_pair(p1[2], p1[3], ph[np][3], pl[np][3]);
        }

        #pragma unroll
        for (int jc = 0; jc < 4; jc++) {
            uint32_t vh[4][4], vl[4][4];
            #pragma unroll
            for (int vp = 0; vp < 4; vp++) {
                ldsm4t(vh[vp], afrag_addr(sVh, jc*16, vp, lane));
                ldsm4t(vl[vp], afrag_addr(sVl, jc*16, vp, lane));
            }
            #pragma unroll
            for (int vp = 0; vp < 4; vp++) {
                mma16816(oc[2*vp],   ph[jc], vh[vp] + 0);
                mma16816(oc[2*vp+1], ph[jc], vh[vp] + 2);
            }
            #pragma unroll
            for (int vp = 0; vp < 4; vp++) {
                mma16816(oc[2*vp],   ph[jc], vl[vp] + 0);
                mma16816(oc[2*vp+1], ph[jc], vl[vp] + 2);
            }
            #pragma unroll
            for (int vp = 0; vp < 4; vp++) {
                mma16816(oc[2*vp],   pl[jc], vh[vp] + 0);
                mma16816(oc[2*vp+1], pl[jc], vh[vp] + 2);
            }
        }
        __syncthreads();
    }

    lsum0 += __shfl_xor_sync(0xffffffffu, lsum0, 1);
    lsum0 += __shfl_xor_sync(0xffffffffu, lsum0, 2);
    lsum1 += __shfl_xor_sync(0xffffffffu, lsum1, 1);
    lsum1 += __shfl_xor_sync(0xffffffffu, lsum1, 2);
    float inv0 = 1.0f / lsum0;
    float inv1 = 1.0f / lsum1;

    int b = bh >> 3, h = bh & 7;
    int q0 = qb + g, q1 = qb + g + 8;
    size_t row0 = ((size_t)(b * AD + h * 64 + (q0 >> 4))) * NPOS + ((q0 & 15) << 6);
    size_t row1 = ((size_t)(b * AD + h * 64 + (q1 >> 4))) * NPOS + ((q1 & 15) << 6);
    #pragma unroll
    for (int ct = 0; ct < 8; ct++) {
        int c = ct * 8 + tig * 2;
        uint32_t hi, lo;
        split_pair(oc[ct][0] * inv0, oc[ct][1] * inv0, hi, lo);
        *reinterpret_cast<uint32_t*>(&g_A2h[row0 + c]) = hi;
        *reinterpret_cast<uint32_t*>(&g_A2l[row0 + c]) = lo;
        split_pair(oc[ct][2] * inv1, oc[ct][3] * inv1, hi, lo);
        *reinterpret_cast<uint32_t*>(&g_A2h[row1 + c]) = hi;
        *reinterpret_cast<uint32_t*>(&g_A2l[row1 + c]) = lo;
    }
}

// ---------------------------------------------------------------------------
// Kernel 3: out GEMM + fused GN partials. BK=32, cp.async double-buffered.
// Stage: A2h[0,8K) A2l[8K,16K) Bh[16K,20K) Bl[20K,24K). Grid (8, 4, 8).
// ---------------------------------------------------------------------------
__global__ __launch_bounds__(128, 3) void out_mma_kernel(const float* __restrict__ bout)
{
    extern __shared__ uint8_t dyn_o[];
    const uint32_t sbase = smem_u32(dyn_o);

    const int tid = threadIdx.x, lane = tid & 31, wid = tid >> 5;
    const int m_blk = blockIdx.x * 128;
    const int n_blk = blockIdx.y * 64;
    const int bb = blockIdx.z;
    const int mw = (wid >> 1) * 64;
    const int nw = (wid & 1) * 32;
    const int g = lane >> 2, tig = lane & 3;

    float acc[4][4][4];
    #pragma unroll
    for (int i = 0; i < 4; i++)
        #pragma unroll
        for (int j = 0; j < 4; j++)
            #pragma unroll
            for (int k = 0; k < 4; k++) acc[i][j][k] = 0.0f;

    const __nv_bfloat16* A2h = g_A2h + (size_t)bb * AD * NPOS;
    const __nv_bfloat16* A2l = g_A2l + (size_t)bb * AD * NPOS;

    auto preload = [&](int ks, int buf) {
        uint32_t b0 = sbase + buf * 24576;
        int k0 = ks * 32;
        // A: 32 k-rows x 16 chunks (256B rows), hi+lo
        #pragma unroll
        for (int i = 0; i < 4; i++) {
            int idx = i * 128 + tid;
            int row = idx >> 4, ch = idx & 15;
            uint32_t off = sw256_off(row, ch);
            size_t go = (size_t)(k0 + row) * NPOS + m_blk + ch * 8;
            cp16(b0 + off,        A2h + go);
            cp16(b0 + 8192 + off, A2l + go);
        }
        // B: 64 logical d-rows x 4 chunks (packed 64B rows), hi+lo
        #pragma unroll
        for (int i = 0; i < 2; i++) {
            int idx = i * 128 + tid;
            int lrow = idx >> 2, ch = idx & 3;
            uint32_t off = swp_off(lrow, ch);
            size_t go = (size_t)(n_blk + lrow) * AD + k0 + ch * 8;
            cp16(b0 + 16384 + off, g_Woh + go);
            cp16(b0 + 20480 + off, g_Wol + go);
        }
        asm volatile("cp.async.commit_group;" ::: "memory");
    };

    preload(0, 0);

    for (int s = 0; s < 16; s++) {
        if (s < 15) {
            preload(s + 1, (s + 1) & 1);
            asm volatile("cp.async.wait_group 1;" ::: "memory");
        } else {
            asm volatile("cp.async.wait_group 0;" ::: "memory");
        }
        __syncthreads();

        uint32_t b0 = sbase + (s & 1) * 24576;
        const uint32_t sAh = b0, sAl = b0 + 8192, sBh = b0 + 16384, sBl = b0 + 20480;

        #pragma unroll
        for (int kc = 0; kc < 2; kc++) {
            uint32_t ah[4][4], al[4][4], bh[2][4], bl[2][4];
            #pragma unroll
            for (int mf = 0; mf < 4; mf++) {
                ldsm4t(ah[mf], afragT256_addr(sAh, kc*16, mw + mf*16, lane));
                ldsm4t(al[mf], afragT256_addr(sAl, kc*16, mw + mf*16, lane));
            }
            #pragma unroll
            for (int nf = 0; nf < 2; nf++) {
                ldsm4(bh[nf], bfragP_addr(sBh, nw + nf*16, kc, lane));
                ldsm4(bl[nf], bfragP_addr(sBl, nw + nf*16, kc, lane));
            }
            #pragma unroll
            for (int mf = 0; mf < 4; mf++)
                #pragma unroll
                for (int nf = 0; nf < 2; nf++) {
                    mma16816(acc[mf][2*nf],   ah[mf], bh[nf] + 0);
                    mma16816(acc[mf][2*nf+1], ah[mf], bh[nf] + 2);
                }
            #pragma unroll
            for (int mf = 0; mf < 4; mf++)
                #pragma unroll
                for (int nf = 0; nf < 2; nf++) {
                    mma16816(acc[mf][2*nf],   ah[mf], bl[nf] + 0);
                    mma16816(acc[mf][2*nf+1], ah[mf], bl[nf] + 2);
                }
            #pragma unroll
            for (int mf = 0; mf < 4; mf++)
                #pragma unroll
                for (int nf = 0; nf < 2; nf++) {
                    mma16816(acc[mf][2*nf],   al[mf], bh[nf] + 0);
                    mma16816(acc[mf][2*nf+1], al[mf], bh[nf] + 2);
                }
        }
        __syncthreads();
    }

    float psum = 0.0f, psq = 0.0f;
    #pragma unroll
    for (int mf = 0; mf < 4; mf++) {
        int r0 = m_blk + mw + mf*16 + g;
        #pragma unroll
        for (int j = 0; j < 4; j++) {
            int d = n_blk + nw + j * 8 + tig * 2;
            float2 bv = *reinterpret_cast<const float2*>(&bout[d]);
            float2 v0 = make_float2(acc[mf][j][0] + bv.x, acc[mf][j][1] + bv.y);
            float2 v1 = make_float2(acc[mf][j][2] + bv.x, acc[mf][j][3] + bv.y);
            *reinterpret_cast<float2*>(&g_Y[((size_t)bb*NPOS + r0)*COUT + d]) = v0;
            *reinterpret_cast<float2*>(&g_Y[((size_t)bb*NPOS + r0 + 8)*COUT + d]) = v1;
            psum += v0.x + v0.y + v1.x + v1.y;
            psq  += v0.x*v0.x + v0.y*v0.y + v1.x*v1.x + v1.y*v1.y;
        }
    }

    float* rs  = reinterpret_cast<float*>(dyn_o);
    float* rss = rs + 128;
    rs[tid] = psum; rss[tid] = psq;
    __syncthreads();
    for (int st = 64; st > 0; st >>= 1) {
        if (tid < st) { rs[tid] += rs[tid + st]; rss[tid] += rss[tid + st]; }
        __syncthreads();
    }
    if (tid == 0) {
        int p = bb * 32 + blockIdx.x * 4 + blockIdx.y;
        g_part[2*p]   = rs[0];
        g_part[2*p+1] = rss[0];
    }
}

// ---------------------------------------------------------------------------
// GN final + normalize
// ---------------------------------------------------------------------------
__global__ void gn_final_kernel()
{
    int b = threadIdx.x;
    if (b < NB) {
        float s = 0.0f, ss = 0.0f;
        #pragma unroll
        for (int i = 0; i < 32; i++) {
            s  += g_part[2*(b*32 + i)];
            ss += g_part[2*(b*32 + i) + 1];
        }
        const float inv_n = 1.0f / (float)(NPOS * COUT);
        float mean = s * inv_n;
        float var  = ss * inv_n - mean * mean;
        g_stats[2*b]     = mean;
        g_stats[2*b + 1] = rsqrtf(var + GN_EPS);
    }
}

__global__ __launch_bounds__(256) void gn_norm_kernel(
    const float* __restrict__ gamma, const float* __restrict__ beta,
    float* __restrict__ out)
{
    int idx4 = blockIdx.x * 256 + threadIdx.x;
    int b  = idx4 >> 16;
    int d4 = idx4 & 63;

    float mean = g_stats[2*b];
    float rstd = g_stats[2*b + 1];

    float4 y  = reinterpret_cast<const float4*>(g_Y)[idx4];
    float4 g  = reinterpret_cast<const float4*>(gamma)[d4];
    float4 be = reinterpret_cast<const float4*>(beta)[d4];

    float4 r;
    r.x = (y.x - mean) * rstd * g.x + be.x;
    r.y = (y.y - mean) * rstd * g.y + be.y;
    r.z = (y.z - mean) * rstd * g.z + be.z;
    r.w = (y.w - mean) * rstd * g.w + be.w;
    reinterpret_cast<float4*>(out)[idx4] = r;
}

// ---------------------------------------------------------------------------
extern "C" void kernel_launch(void* const* d_in, const int* in_sizes, int n_in,
                              void* d_out, int out_size)
{
    const float* x      = (const float*)d_in[0];
    const float* w_qkv  = (const float*)d_in[1];
    const float* w_out  = (const float*)d_in[2];
    const float* b_out  = (const float*)d_in[3];
    const float* gamma  = (const float*)d_in[4];
    const float* beta   = (const float*)d_in[5];
    float* out = (float*)d_out;

    static int smem_set = 0;
    if (!smem_set) {
        cudaFuncSetAttribute(attn_mma_kernel,
                             cudaFuncAttributeMaxDynamicSharedMemorySize, 65536);
        cudaFuncSetAttribute(qkv_mma_kernel,
                             cudaFuncAttributeMaxDynamicSharedMemorySize, 49152);
        cudaFuncSetAttribute(out_mma_kernel,
                             cudaFuncAttributeMaxDynamicSharedMemorySize, 49152);
        smem_set = 1;
    }

    conv_x_kernel<<<2048, 256>>>(x);
    conv_w_kernel<<<dim3(48, 8),  dim3(32, 32)>>>(w_qkv, CIN, 3*AD, 0);
    conv_w_kernel<<<dim3(8, 16),  dim3(32, 32)>>>(w_out, AD, COUT, 1);
    qkv_mma_kernel<<<dim3(64, 24), 128, 49152>>>();
    attn_mma_kernel<<<dim3(16, 64), 128, 65536>>>();
    out_mma_kernel<<<dim3(8, 4, 8), 128, 49152>>>(b_out);
    gn_final_kernel<<<1, 32>>>();
    gn_norm_kernel<<<2048, 256>>>(gamma, beta, out);
}

// round 8
// speedup vs baseline: 5.9177x; 1.0020x over previous
#include <cuda_runtime.h>
#include <cuda_bf16.h>
#include <cstdint>

#define NB    8
#define NPOS  1024
#define CIN   256
#define HEADS 8
#define DH    64
#define AD    512
#define COUT  256
#define QK_SCALE 0.125f
#define GN_EPS 1e-5f

// ---------------------------------------------------------------------------
// helpers
// ---------------------------------------------------------------------------
__device__ __forceinline__ uint32_t smem_u32(const void* p) {
    uint32_t a;
    asm("{ .reg .u64 t; cvta.to.shared.u64 t, %1; cvt.u32.u64 %0, t; }" : "=r"(a) : "l"(p));
    return a;
}

__device__ __forceinline__ void split_pair(float a, float b, uint32_t& hi, uint32_t& lo)
{
    __nv_bfloat16 ah = __float2bfloat16(a);
    __nv_bfloat16 bh = __float2bfloat16(b);
    float al = a - __bfloat162float(ah);
    float bl = b - __bfloat162float(bh);
    __nv_bfloat16 alh = __float2bfloat16(al);
    __nv_bfloat16 blh = __float2bfloat16(bl);
    hi = ((uint32_t)__bfloat16_as_ushort(bh)  << 16) | (uint32_t)__bfloat16_as_ushort(ah);
    lo = ((uint32_t)__bfloat16_as_ushort(blh) << 16) | (uint32_t)__bfloat16_as_ushort(alh);
}

__device__ __forceinline__ void mma16816(float* c, const uint32_t* a, const uint32_t* b)
{
    asm volatile("mma.sync.aligned.m16n8k16.row.col.f32.bf16.bf16.f32 "
        "{%0,%1,%2,%3},{%4,%5,%6,%7},{%8,%9},{%0,%1,%2,%3};"
        : "+f"(c[0]), "+f"(c[1]), "+f"(c[2]), "+f"(c[3])
        : "r"(a[0]), "r"(a[1]), "r"(a[2]), "r"(a[3]), "r"(b[0]), "r"(b[1]));
}

__device__ __forceinline__ void ldsm4(uint32_t* r, uint32_t addr)
{
    asm volatile("ldmatrix.sync.aligned.m8n8.x4.shared.b16 {%0,%1,%2,%3}, [%4];"
        : "=r"(r[0]), "=r"(r[1]), "=r"(r[2]), "=r"(r[3]) : "r"(addr));
}
__device__ __forceinline__ void ldsm4t(uint32_t* r, uint32_t addr)
{
    asm volatile("ldmatrix.sync.aligned.m8n8.x4.trans.shared.b16 {%0,%1,%2,%3}, [%4];"
        : "=r"(r[0]), "=r"(r[1]), "=r"(r[2]), "=r"(r[3]) : "r"(addr));
}

__device__ __forceinline__ void cp16(uint32_t dst, const void* src)
{
    asm volatile("cp.async.cg.shared.global [%0], [%1], 16;" :: "r"(dst), "l"(src));
}

// ---- 128B-row swizzled tiles ----
__device__ __forceinline__ uint32_t sw_addr(uint32_t base, int row, int ch) {
    return base + row * 128 + ((ch ^ (row & 7)) << 4);
}
__device__ __forceinline__ uint32_t afrag_addr(uint32_t base, int r0, int chunk, int lane) {
    int row = r0 + (lane & 7) + ((lane >> 3) & 1) * 8;
    int ch  = 2 * chunk + (lane >> 4);
    return sw_addr(base, row, ch);
}
__device__ __forceinline__ uint32_t bfrag_addr(uint32_t base, int n0, int kc, int lane) {
    int row = n0 + (lane & 7) + ((lane >> 4) & 1) * 8;
    int ch  = 2 * kc + ((lane >> 3) & 1);
    return sw_addr(base, row, ch);
}
// trans A-frag from [k][m] tile with 128B rows (m range 0..63)
__device__ __forceinline__ uint32_t afragT128_addr(uint32_t base, int k0, int m0, int lane) {
    int row = k0 + (lane & 7) + ((lane >> 4) & 1) * 8;
    int ch  = (m0 >> 3) + ((lane >> 3) & 1);
    return sw_addr(base, row, ch);
}

// ---- packed 64B-row tiles (BK=32) ----
__device__ __forceinline__ uint32_t swp_off(int lrow, int ch) {
    int prow = lrow >> 1;
    int cp = ((lrow & 1) << 2) | ch;
    return (uint32_t)(prow * 128 + ((cp ^ (prow & 7)) << 4));
}
__device__ __forceinline__ uint32_t afragP_addr(uint32_t base, int r0, int kc, int lane) {
    int lrow = r0 + (lane & 7) + ((lane >> 3) & 1) * 8;
    int ch   = 2 * kc + (lane >> 4);
    return base + swp_off(lrow, ch);
}
__device__ __forceinline__ uint32_t bfragP_addr(uint32_t base, int n0, int kc, int lane) {
    int lrow = n0 + (lane & 7) + ((lane >> 4) & 1) * 8;
    int ch   = 2 * kc + ((lane >> 3) & 1);
    return base + swp_off(lrow, ch);
}

// ---------------------------------------------------------------------------
// Scratch globals
// ---------------------------------------------------------------------------
__device__ __nv_bfloat16 g_Xh[NB * NPOS * CIN];
__device__ __nv_bfloat16 g_Xl[NB * NPOS * CIN];
__device__ __nv_bfloat16 g_Wqh[3 * AD * CIN];
__device__ __nv_bfloat16 g_Wql[3 * AD * CIN];
__device__ __nv_bfloat16 g_Woh[COUT * AD];
__device__ __nv_bfloat16 g_Wol[COUT * AD];
__device__ __nv_bfloat16 g_Qh[NB * HEADS * NPOS * DH];
__device__ __nv_bfloat16 g_Ql[NB * HEADS * NPOS * DH];
__device__ __nv_bfloat16 g_Kh[NB * HEADS * NPOS * DH];
__device__ __nv_bfloat16 g_Kl[NB * HEADS * NPOS * DH];
__device__ __nv_bfloat16 g_Vh[NB * HEADS * NPOS * DH];
__device__ __nv_bfloat16 g_Vl[NB * HEADS * NPOS * DH];
__device__ __nv_bfloat16 g_A2h[NB * AD * NPOS];
__device__ __nv_bfloat16 g_A2l[NB * AD * NPOS];
__device__ float g_Y[NB * NPOS * COUT];
__device__ float g_part[1024];
__device__ float g_stats[2 * NB];

// ---------------------------------------------------------------------------
// Kernel 0a: X -> split bf16
// ---------------------------------------------------------------------------
__global__ __launch_bounds__(256) void conv_x_kernel(const float* __restrict__ X)
{
    int idx4 = blockIdx.x * 256 + threadIdx.x;
    float4 v = reinterpret_cast<const float4*>(X)[idx4];
    uint32_t h0, l0, h1, l1;
    split_pair(v.x, v.y, h0, l0);
    split_pair(v.z, v.w, h1, l1);
    reinterpret_cast<uint2*>(g_Xh)[idx4] = make_uint2(h0, h1);
    reinterpret_cast<uint2*>(g_Xl)[idx4] = make_uint2(l0, l1);
}

// ---------------------------------------------------------------------------
// Kernel 0b: weight transpose + split. src [K][N] -> dst [N][K].
// ---------------------------------------------------------------------------
__global__ void conv_w_kernel(const float* __restrict__ src, int K, int N, int which)
{
    __shared__ float tile[32][33];
    int n0 = blockIdx.x * 32;
    int k0 = blockIdx.y * 32;
    int tx = threadIdx.x, ty = threadIdx.y;
    tile[ty][tx] = src[(size_t)(k0 + ty) * N + n0 + tx];
    __syncthreads();
    if (tx < 16) {
        __nv_bfloat16* dh = which ? g_Woh : g_Wqh;
        __nv_bfloat16* dl = which ? g_Wol : g_Wql;
        uint32_t hi, lo;
        split_pair(tile[2*tx][ty], tile[2*tx+1][ty], hi, lo);
        size_t off = (size_t)(n0 + ty) * K + k0 + 2*tx;
        *reinterpret_cast<uint32_t*>(&dh[off]) = hi;
        *reinterpret_cast<uint32_t*>(&dl[off]) = lo;
    }
}

// ---------------------------------------------------------------------------
// Kernel 1: QKV GEMM. Block 128m x 64n, warp 64x32, BK=32, 4 CTAs/SM.
// Single-barrier double-buffered cp.async pipeline. Grid (64, 24).
// Stage: Ah[0,8K) Al[8K,16K) Bh[16K,20K) Bl[20K,24K)
// ---------------------------------------------------------------------------
__global__ __launch_bounds__(128, 4) void qkv_mma_kernel()
{
    extern __shared__ uint8_t dyn_q[];
    const uint32_t sbase = smem_u32(dyn_q);

    const int tid = threadIdx.x, lane = tid & 31, wid = tid >> 5;
    const int m_blk = blockIdx.x * 128;
    const int n_blk = blockIdx.y * 64;
    const int mw = (wid >> 1) * 64;
    const int nw = (wid & 1) * 32;
    const int g = lane >> 2, tig = lane & 3;

    float acc[4][4][4];
    #pragma unroll
    for (int i = 0; i < 4; i++)
        #pragma unroll
        for (int j = 0; j < 4; j++)
            #pragma unroll
            for (int k = 0; k < 4; k++) acc[i][j][k] = 0.0f;

    auto preload = [&](int ks, int buf) {
        uint32_t b0 = sbase + buf * 24576;
        int k0 = ks * 32;
        #pragma unroll
        for (int i = 0; i < 4; i++) {
            int idx = i * 128 + tid;
            int lrow = idx >> 2, ch = idx & 3;
            uint32_t off = swp_off(lrow, ch);
            size_t go = (size_t)(m_blk + lrow) * CIN + k0 + ch * 8;
            cp16(b0 + off,        g_Xh + go);
            cp16(b0 + 8192 + off, g_Xl + go);
        }
        #pragma unroll
        for (int i = 0; i < 2; i++) {
            int idx = i * 128 + tid;
            int lrow = idx >> 2, ch = idx & 3;
            uint32_t off = swp_off(lrow, ch);
            size_t go = (size_t)(n_blk + lrow) * CIN + k0 + ch * 8;
            cp16(b0 + 16384 + off, g_Wqh + go);
            cp16(b0 + 20480 + off, g_Wql + go);
        }
        asm volatile("cp.async.commit_group;" ::: "memory");
    };

    preload(0, 0);

    for (int s = 0; s < 8; s++) {
        asm volatile("cp.async.wait_group 0;" ::: "memory");
        __syncthreads();
        if (s < 7) preload(s + 1, (s + 1) & 1);

        uint32_t b0 = sbase + (s & 1) * 24576;
        const uint32_t sAh = b0, sAl = b0 + 8192, sBh = b0 + 16384, sBl = b0 + 20480;

        #pragma unroll
        for (int kc = 0; kc < 2; kc++) {
            uint32_t bh0[4], bl0[4], bh1[4], bl1[4];
            ldsm4(bh0, bfragP_addr(sBh, nw,      kc, lane));
            ldsm4(bh1, bfragP_addr(sBh, nw + 16, kc, lane));
            ldsm4(bl0, bfragP_addr(sBl, nw,      kc, lane));
            ldsm4(bl1, bfragP_addr(sBl, nw + 16, kc, lane));
            #pragma unroll
            for (int mf = 0; mf < 4; mf++) {
                uint32_t ah[4], al[4];
                ldsm4(ah, afragP_addr(sAh, mw + mf*16, kc, lane));
                ldsm4(al, afragP_addr(sAl, mw + mf*16, kc, lane));
                mma16816(acc[mf][0], ah, bh0 + 0); mma16816(acc[mf][1], ah, bh0 + 2);
                mma16816(acc[mf][2], ah, bh1 + 0); mma16816(acc[mf][3], ah, bh1 + 2);
                mma16816(acc[mf][0], ah, bl0 + 0); mma16816(acc[mf][1], ah, bl0 + 2);
                mma16816(acc[mf][2], ah, bl1 + 0); mma16816(acc[mf][3], ah, bl1 + 2);
                mma16816(acc[mf][0], al, bh0 + 0); mma16816(acc[mf][1], al, bh0 + 2);
                mma16816(acc[mf][2], al, bh1 + 0); mma16816(acc[mf][3], al, bh1 + 2);
            }
        }
    }

    const int which = n_blk >> 9;
    const int h = (n_blk >> 6) & 7;
    __nv_bfloat16 *dh, *dl;
    float sc = 1.0f;
    if (which == 0)      { dh = g_Qh; dl = g_Ql; sc = QK_SCALE; }
    else if (which == 1) { dh = g_Kh; dl = g_Kl; }
    else                 { dh = g_Vh; dl = g_Vl; }

    #pragma unroll
    for (int mf = 0; mf < 4; mf++) {
        int r0 = m_blk + mw + mf*16 + g;
        int b_ = r0 >> 10;
        int nr = r0 & 1023;
        size_t rb0 = ((size_t)(b_ * HEADS + h) * NPOS + nr) * DH;
        size_t rb1 = rb0 + 8 * DH;
        #pragma unroll
        for (int j = 0; j < 4; j++) {
            int c = nw + j * 8 + tig * 2;
            uint32_t hi, lo;
            split_pair(acc[mf][j][0] * sc, acc[mf][j][1] * sc, hi, lo);
            *reinterpret_cast<uint32_t*>(&dh[rb0 + c]) = hi;
            *reinterpret_cast<uint32_t*>(&dl[rb0 + c]) = lo;
            split_pair(acc[mf][j][2] * sc, acc[mf][j][3] * sc, hi, lo);
            *reinterpret_cast<uint32_t*>(&dh[rb1 + c]) = hi;
            *reinterpret_cast<uint32_t*>(&dl[rb1 + c]) = lo;
        }
    }
}

// ---------------------------------------------------------------------------
// Kernel 2: attention — single-barrier cp.async pipeline, product-major.
// ---------------------------------------------------------------------------
__global__ __launch_bounds__(128) void attn_mma_kernel()
{
    extern __shared__ uint8_t dyn_s[];

    const int tid  = threadIdx.x;
    const int lane = tid & 31;
    const int wid  = tid >> 5;
    const int bh   = blockIdx.y;
    const int qb   = blockIdx.x * 64 + wid * 16;
    const int g    = lane >> 2;
    const int tig  = lane & 3;

    const __nv_bfloat16* gKh = g_Kh + (size_t)bh * NPOS * DH;
    const __nv_bfloat16* gKl = g_Kl + (size_t)bh * NPOS * DH;
    const __nv_bfloat16* gVh = g_Vh + (size_t)bh * NPOS * DH;
    const __nv_bfloat16* gVl = g_Vl + (size_t)bh * NPOS * DH;

    const uint32_t sbase = smem_u32(dyn_s);

    uint32_t qh[4][4], ql[4][4];
    {
        const __nv_bfloat16* Qh = g_Qh + (size_t)bh * NPOS * DH;
        const __nv_bfloat16* Ql = g_Ql + (size_t)bh * NPOS * DH;
        int r = qb + g;
        #pragma unroll
        for (int kc = 0; kc < 4; kc++) {
            int c0 = kc * 16 + tig * 2;
            qh[kc][0] = *reinterpret_cast<const uint32_t*>(Qh + (size_t)r*DH + c0);
            qh[kc][1] = *reinterpret_cast<const uint32_t*>(Qh + (size_t)(r+8)*DH + c0);
            qh[kc][2] = *reinterpret_cast<const uint32_t*>(Qh + (size_t)r*DH + c0 + 8);
            qh[kc][3] = *reinterpret_cast<const uint32_t*>(Qh + (size_t)(r+8)*DH + c0 + 8);
            ql[kc][0] = *reinterpret_cast<const uint32_t*>(Ql + (size_t)r*DH + c0);
            ql[kc][1] = *reinterpret_cast<const uint32_t*>(Ql + (size_t)(r+8)*DH + c0);
            ql[kc][2] = *reinterpret_cast<const uint32_t*>(Ql + (size_t)r*DH + c0 + 8);
            ql[kc][3] = *reinterpret_cast<const uint32_t*>(Ql + (size_t)(r+8)*DH + c0 + 8);
        }
    }

    float oc[8][4];
    #pragma unroll
    for (int i = 0; i < 8; i++)
        #pragma unroll
        for (int j = 0; j < 4; j++) oc[i][j] = 0.0f;
    float lsum0 = 0.0f, lsum1 = 0.0f;

    auto preload = [&](int kt, int buf) {
        uint32_t b0 = sbase + buf * 32768;
        #pragma unroll
        for (int i = 0; i < 4; i++) {
            int idx = i * 128 + tid;
            int row = idx >> 3, ch = idx & 7;
            uint32_t dsto = (uint32_t)(row * 128 + ((ch ^ (row & 7)) << 4));
            size_t go = (size_t)(kt * 64 + row) * DH + ch * 8;
            cp16(b0 + dsto,         gKh + go);
            cp16(b0 + 8192 + dsto,  gKl + go);
            cp16(b0 + 16384 + dsto, gVh + go);
            cp16(b0 + 24576 + dsto, gVl + go);
        }
        asm volatile("cp.async.commit_group;" ::: "memory");
    };

    preload(0, 0);

    for (int kt = 0; kt < 16; kt++) {
        asm volatile("cp.async.wait_group 0;" ::: "memory");
        __syncthreads();
        if (kt < 15) preload(kt + 1, (kt + 1) & 1);

        const uint32_t sKh = sbase + (kt & 1) * 32768;
        const uint32_t sKl = sKh + 8192;
        const uint32_t sVh = sKh + 16384;
        const uint32_t sVl = sKh + 24576;

        float s[8][4];
        #pragma unroll
        for (int i = 0; i < 8; i++)
            #pragma unroll
            for (int j = 0; j < 4; j++) s[i][j] = 0.0f;

        #pragma unroll
        for (int kc = 0; kc < 4; kc++) {
            uint32_t kh[4][4], kl[4][4];
            #pragma unroll
            for (int np = 0; np < 4; np++) {
                ldsm4(kh[np], bfrag_addr(sKh, np*16, kc, lane));
                ldsm4(kl[np], bfrag_addr(sKl, np*16, kc, lane));
            }
            #pragma unroll
            for (int np = 0; np < 4; np++) {
                mma16816(s[2*np],   qh[kc], kh[np] + 0);
                mma16816(s[2*np+1], qh[kc], kh[np] + 2);
            }
            #pragma unroll
            for (int np = 0; np < 4; np++) {
                mma16816(s[2*np],   qh[kc], kl[np] + 0);
                mma16816(s[2*np+1], qh[kc], kl[np] + 2);
            }
            #pragma unroll
            for (int np = 0; np < 4; np++) {
                mma16816(s[2*np],   ql[kc], kh[np] + 0);
                mma16816(s[2*np+1], ql[kc], kh[np] + 2);
            }
        }

        uint32_t ph[4][4], pl[4][4];
        #pragma unroll
        for (int np = 0; np < 4; np++) {
            float p0[4], p1[4];
            #pragma unroll
            for (int j = 0; j < 4; j++) {
                p0[j] = __expf(s[2*np][j]);
                p1[j] = __expf(s[2*np+1][j]);
            }
            lsum0 += p0[0] + p0[1] + p1[0] + p1[1];
            lsum1 += p0[2] + p0[3] + p1[2] + p1[3];
            split_pair(p0[0], p0[1], ph[np][0], pl[np][0]);
            split_pair(p0[2], p0[3], ph[np][1], pl[np][1]);
            split_pair(p1[0], p1[1], ph[np][2], pl[np][2]);
            split_pair(p1[2], p1[3], ph[np][3], pl[np][3]);
        }

        #pragma unroll
        for (int jc = 0; jc < 4; jc++) {
            uint32_t vh[4][4], vl[4][4];
            #pragma unroll
            for (int vp = 0; vp < 4; vp++) {
                ldsm4t(vh[vp], afrag_addr(sVh, jc*16, vp, lane));
                ldsm4t(vl[vp], afrag_addr(sVl, jc*16, vp, lane));
            }
            #pragma unroll
            for (int vp = 0; vp < 4; vp++) {
                mma16816(oc[2*vp],   ph[jc], vh[vp] + 0);
                mma16816(oc[2*vp+1], ph[jc], vh[vp] + 2);
            }
            #pragma unroll
            for (int vp = 0; vp < 4; vp++) {
                mma16816(oc[2*vp],   ph[jc], vl[vp] + 0);
                mma16816(oc[2*vp+1], ph[jc], vl[vp] + 2);
            }
            #pragma unroll
            for (int vp = 0; vp < 4; vp++) {
                mma16816(oc[2*vp],   pl[jc], vh[vp] + 0);
                mma16816(oc[2*vp+1], pl[jc], vh[vp] + 2);
            }
        }
    }

    lsum0 += __shfl_xor_sync(0xffffffffu, lsum0, 1);
    lsum0 += __shfl_xor_sync(0xffffffffu, lsum0, 2);
    lsum1 += __shfl_xor_sync(0xffffffffu, lsum1, 1);
    lsum1 += __shfl_xor_sync(0xffffffffu, lsum1, 2);
    float inv0 = 1.0f / lsum0;
    float inv1 = 1.0f / lsum1;

    int b = bh >> 3, h = bh & 7;
    int q0 = qb + g, q1 = qb + g + 8;
    size_t row0 = ((size_t)(b * AD + h * 64 + (q0 >> 4))) * NPOS + ((q0 & 15) << 6);
    size_t row1 = ((size_t)(b * AD + h * 64 + (q1 >> 4))) * NPOS + ((q1 & 15) << 6);
    #pragma unroll
    for (int ct = 0; ct < 8; ct++) {
        int c = ct * 8 + tig * 2;
        uint32_t hi, lo;
        split_pair(oc[ct][0] * inv0, oc[ct][1] * inv0, hi, lo);
        *reinterpret_cast<uint32_t*>(&g_A2h[row0 + c]) = hi;
        *reinterpret_cast<uint32_t*>(&g_A2l[row0 + c]) = lo;
        split_pair(oc[ct][2] * inv1, oc[ct][3] * inv1, hi, lo);
        *reinterpret_cast<uint32_t*>(&g_A2h[row1 + c]) = hi;
        *reinterpret_cast<uint32_t*>(&g_A2l[row1 + c]) = lo;
    }
}

// ---------------------------------------------------------------------------
// Kernel 3: out GEMM + fused GN partials. Block 64pos x 64d, warp 32x32,
// BK=32, single-barrier pipeline. Grid (16, 4, 8).
// Stage: Ah[0,4K) Al[4K,8K) Bh[8K,12K) Bl[12K,16K); 2 stages = 32KB.
// ---------------------------------------------------------------------------
__global__ __launch_bounds__(128, 4) void out_mma_kernel(const float* __restrict__ bout)
{
    extern __shared__ uint8_t dyn_o[];
    const uint32_t sbase = smem_u32(dyn_o);

    const int tid = threadIdx.x, lane = tid & 31, wid = tid >> 5;
    const int m_blk = blockIdx.x * 64;
    const int n_blk = blockIdx.y * 64;
    const int bb = blockIdx.z;
    const int mw = (wid >> 1) * 32;
    const int nw = (wid & 1) * 32;
    const int g = lane >> 2, tig = lane & 3;

    float acc[2][4][4];
    #pragma unroll
    for (int i = 0; i < 2; i++)
        #pragma unroll
        for (int j = 0; j < 4; j++)
            #pragma unroll
            for (int k = 0; k < 4; k++) acc[i][j][k] = 0.0f;

    const __nv_bfloat16* A2h = g_A2h + (size_t)bb * AD * NPOS;
    const __nv_bfloat16* A2l = g_A2l + (size_t)bb * AD * NPOS;

    auto preload = [&](int ks, int buf) {
        uint32_t b0 = sbase + buf * 16384;
        int k0 = ks * 32;
        // A: 32 k-rows x 8 chunks (128B rows), hi+lo
        #pragma unroll
        for (int i = 0; i < 2; i++) {
            int idx = i * 128 + tid;
            int row = idx >> 3, ch = idx & 7;
            uint32_t off = (uint32_t)(row * 128 + ((ch ^ (row & 7)) << 4));
            size_t go = (size_t)(k0 + row) * NPOS + m_blk + ch * 8;
            cp16(b0 + off,        A2h + go);
            cp16(b0 + 4096 + off, A2l + go);
        }
        // B: 64 logical d-rows x 4 chunks (packed 64B rows), hi+lo
        #pragma unroll
        for (int i = 0; i < 2; i++) {
            int idx = i * 128 + tid;
            int lrow = idx >> 2, ch = idx & 3;
            uint32_t off = swp_off(lrow, ch);
            size_t go = (size_t)(n_blk + lrow) * AD + k0 + ch * 8;
            cp16(b0 + 8192 + off,  g_Woh + go);
            cp16(b0 + 12288 + off, g_Wol + go);
        }
        asm volatile("cp.async.commit_group;" ::: "memory");
    };

    preload(0, 0);

    for (int s = 0; s < 16; s++) {
        asm volatile("cp.async.wait_group 0;" ::: "memory");
        __syncthreads();
        if (s < 15) preload(s + 1, (s + 1) & 1);

        uint32_t b0 = sbase + (s & 1) * 16384;
        const uint32_t sAh = b0, sAl = b0 + 4096, sBh = b0 + 8192, sBl = b0 + 12288;

        #pragma unroll
        for (int kc = 0; kc < 2; kc++) {
            uint32_t bh0[4], bl0[4], bh1[4], bl1[4];
            ldsm4(bh0, bfragP_addr(sBh, nw,      kc, lane));
            ldsm4(bh1, bfragP_addr(sBh, nw + 16, kc, lane));
            ldsm4(bl0, bfragP_addr(sBl, nw,      kc, lane));
            ldsm4(bl1, bfragP_addr(sBl, nw + 16, kc, lane));
            #pragma unroll
            for (int mf = 0; mf < 2; mf++) {
                uint32_t ah[4], al[4];
                ldsm4t(ah, afragT128_addr(sAh, kc*16, mw + mf*16, lane));
                ldsm4t(al, afragT128_addr(sAl, kc*16, mw + mf*16, lane));
                mma16816(acc[mf][0], ah, bh0 + 0); mma16816(acc[mf][1], ah, bh0 + 2);
                mma16816(acc[mf][2], ah, bh1 + 0); mma16816(acc[mf][3], ah, bh1 + 2);
                mma16816(acc[mf][0], ah, bl0 + 0); mma16816(acc[mf][1], ah, bl0 + 2);
                mma16816(acc[mf][2], ah, bl1 + 0); mma16816(acc[mf][3], ah, bl1 + 2);
                mma16816(acc[mf][0], al, bh0 + 0); mma16816(acc[mf][1], al, bh0 + 2);
                mma16816(acc[mf][2], al, bh1 + 0); mma16816(acc[mf][3], al, bh1 + 2);
            }
        }
    }

    float psum = 0.0f, psq = 0.0f;
    #pragma unroll
    for (int mf = 0; mf < 2; mf++) {
        int r0 = m_blk + mw + mf*16 + g;
        #pragma unroll
        for (int j = 0; j < 4; j++) {
            int d = n_blk + nw + j * 8 + tig * 2;
            float2 bv = *reinterpret_cast<const float2*>(&bout[d]);
            float2 v0 = make_float2(acc[mf][j][0] + bv.x, acc[mf][j][1] + bv.y);
            float2 v1 = make_float2(acc[mf][j][2] + bv.x, acc[mf][j][3] + bv.y);
            *reinterpret_cast<float2*>(&g_Y[((size_t)bb*NPOS + r0)*COUT + d]) = v0;
            *reinterpret_cast<float2*>(&g_Y[((size_t)bb*NPOS + r0 + 8)*COUT + d]) = v1;
            psum += v0.x + v0.y + v1.x + v1.y;
            psq  += v0.x*v0.x + v0.y*v0.y + v1.x*v1.x + v1.y*v1.y;
        }
    }

    __syncthreads();   // all warps done reading stage smem before reuse
    float* rs  = reinterpret_cast<float*>(dyn_o);
    float* rss = rs + 128;
    rs[tid] = psum; rss[tid] = psq;
    __syncthreads();
    for (int st = 64; st > 0; st >>= 1) {
        if (tid < st) { rs[tid] += rs[tid + st]; rss[tid] += rss[tid + st]; }
        __syncthreads();
    }
    if (tid == 0) {
        int p = bb * 64 + blockIdx.x * 4 + blockIdx.y;
        g_part[2*p]   = rs[0];
        g_part[2*p+1] = rss[0];
    }
}

// ---------------------------------------------------------------------------
// GN final + normalize
// ---------------------------------------------------------------------------
__global__ void gn_final_kernel()
{
    int b = threadIdx.x;
    if (b < NB) {
        float s = 0.0f, ss = 0.0f;
        #pragma unroll
        for (int i = 0; i < 64; i++) {
            s  += g_part[2*(b*64 + i)];
            ss += g_part[2*(b*64 + i) + 1];
        }
        const float inv_n = 1.0f / (float)(NPOS * COUT);
        float mean = s * inv_n;
        float var  = ss * inv_n - mean * mean;
        g_stats[2*b]     = mean;
        g_stats[2*b + 1] = rsqrtf(var + GN_EPS);
    }
}

__global__ __launch_bounds__(256) void gn_norm_kernel(
    const float* __restrict__ gamma, const float* __restrict__ beta,
    float* __restrict__ out)
{
    int idx4 = blockIdx.x * 256 + threadIdx.x;
    int b  = idx4 >> 16;
    int d4 = idx4 & 63;

    float mean = g_stats[2*b];
    float rstd = g_stats[2*b + 1];

    float4 y  = reinterpret_cast<const float4*>(g_Y)[idx4];
    float4 g  = reinterpret_cast<const float4*>(gamma)[d4];
    float4 be = reinterpret_cast<const float4*>(beta)[d4];

    float4 r;
    r.x = (y.x - mean) * rstd * g.x + be.x;
    r.y = (y.y - mean) * rstd * g.y + be.y;
    r.z = (y.z - mean) * rstd * g.z + be.z;
    r.w = (y.w - mean) * rstd * g.w + be.w;
    reinterpret_cast<float4*>(out)[idx4] = r;
}

// ---------------------------------------------------------------------------
extern "C" void kernel_launch(void* const* d_in, const int* in_sizes, int n_in,
                              void* d_out, int out_size)
{
    const float* x      = (const float*)d_in[0];
    const float* w_qkv  = (const float*)d_in[1];
    const float* w_out  = (const float*)d_in[2];
    const float* b_out  = (const float*)d_in[3];
    const float* gamma  = (const float*)d_in[4];
    const float* beta   = (const float*)d_in[5];
    float* out = (float*)d_out;

    static int smem_set = 0;
    if (!smem_set) {
        cudaFuncSetAttribute(attn_mma_kernel,
                             cudaFuncAttributeMaxDynamicSharedMemorySize, 65536);
        cudaFuncSetAttribute(qkv_mma_kernel,
                             cudaFuncAttributeMaxDynamicSharedMemorySize, 49152);
        cudaFuncSetAttribute(out_mma_kernel,
                             cudaFuncAttributeMaxDynamicSharedMemorySize, 32768);
        smem_set = 1;
    }

    conv_x_kernel<<<2048, 256>>>(x);
    conv_w_kernel<<<dim3(48, 8),  dim3(32, 32)>>>(w_qkv, CIN, 3*AD, 0);
    conv_w_kernel<<<dim3(8, 16),  dim3(32, 32)>>>(w_out, AD, COUT, 1);
    qkv_mma_kernel<<<dim3(64, 24), 128, 49152>>>();
    attn_mma_kernel<<<dim3(16, 64), 128, 65536>>>();
    out_mma_kernel<<<dim3(16, 4, 8), 128, 32768>>>(b_out);
    gn_final_kernel<<<1, 32>>>();
    gn_norm_kernel<<<2048, 256>>>(gamma, beta, out);
}

// round 9
// speedup vs baseline: 6.0689x; 1.0255x over previous
#include <cuda_runtime.h>
#include <cuda_bf16.h>
#include <cstdint>

#define NB    8
#define NPOS  1024
#define CIN   256
#define HEADS 8
#define DH    64
#define AD    512
#define COUT  256
#define QK_SCALE 0.125f
#define GN_EPS 1e-5f

// ---------------------------------------------------------------------------
// helpers
// ---------------------------------------------------------------------------
__device__ __forceinline__ uint32_t smem_u32(const void* p) {
    uint32_t a;
    asm("{ .reg .u64 t; cvta.to.shared.u64 t, %1; cvt.u32.u64 %0, t; }" : "=r"(a) : "l"(p));
    return a;
}

__device__ __forceinline__ void split_pair(float a, float b, uint32_t& hi, uint32_t& lo)
{
    __nv_bfloat16 ah = __float2bfloat16(a);
    __nv_bfloat16 bh = __float2bfloat16(b);
    float al = a - __bfloat162float(ah);
    float bl = b - __bfloat162float(bh);
    __nv_bfloat16 alh = __float2bfloat16(al);
    __nv_bfloat16 blh = __float2bfloat16(bl);
    hi = ((uint32_t)__bfloat16_as_ushort(bh)  << 16) | (uint32_t)__bfloat16_as_ushort(ah);
    lo = ((uint32_t)__bfloat16_as_ushort(blh) << 16) | (uint32_t)__bfloat16_as_ushort(alh);
}

__device__ __forceinline__ void mma16816(float* c, const uint32_t* a, const uint32_t* b)
{
    asm volatile("mma.sync.aligned.m16n8k16.row.col.f32.bf16.bf16.f32 "
        "{%0,%1,%2,%3},{%4,%5,%6,%7},{%8,%9},{%0,%1,%2,%3};"
        : "+f"(c[0]), "+f"(c[1]), "+f"(c[2]), "+f"(c[3])
        : "r"(a[0]), "r"(a[1]), "r"(a[2]), "r"(a[3]), "r"(b[0]), "r"(b[1]));
}

__device__ __forceinline__ void ldsm4(uint32_t* r, uint32_t addr)
{
    asm volatile("ldmatrix.sync.aligned.m8n8.x4.shared.b16 {%0,%1,%2,%3}, [%4];"
        : "=r"(r[0]), "=r"(r[1]), "=r"(r[2]), "=r"(r[3]) : "r"(addr));
}
__device__ __forceinline__ void ldsm4t(uint32_t* r, uint32_t addr)
{
    asm volatile("ldmatrix.sync.aligned.m8n8.x4.trans.shared.b16 {%0,%1,%2,%3}, [%4];"
        : "=r"(r[0]), "=r"(r[1]), "=r"(r[2]), "=r"(r[3]) : "r"(addr));
}

__device__ __forceinline__ void cp16(uint32_t dst, const void* src)
{
    asm volatile("cp.async.cg.shared.global [%0], [%1], 16;" :: "r"(dst), "l"(src));
}

// ---- 128B-row swizzled tiles ----
__device__ __forceinline__ uint32_t sw_addr(uint32_t base, int row, int ch) {
    return base + row * 128 + ((ch ^ (row & 7)) << 4);
}
__device__ __forceinline__ uint32_t afrag_addr(uint32_t base, int r0, int chunk, int lane) {
    int row = r0 + (lane & 7) + ((lane >> 3) & 1) * 8;
    int ch  = 2 * chunk + (lane >> 4);
    return sw_addr(base, row, ch);
}
__device__ __forceinline__ uint32_t bfrag_addr(uint32_t base, int n0, int kc, int lane) {
    int row = n0 + (lane & 7) + ((lane >> 4) & 1) * 8;
    int ch  = 2 * kc + ((lane >> 3) & 1);
    return sw_addr(base, row, ch);
}
__device__ __forceinline__ uint32_t afragT128_addr(uint32_t base, int k0, int m0, int lane) {
    int row = k0 + (lane & 7) + ((lane >> 4) & 1) * 8;
    int ch  = (m0 >> 3) + ((lane >> 3) & 1);
    return sw_addr(base, row, ch);
}
// ---- packed 64B-row tiles (BK=32) ----
__device__ __forceinline__ uint32_t swp_off(int lrow, int ch) {
    int prow = lrow >> 1;
    int cp = ((lrow & 1) << 2) | ch;
    return (uint32_t)(prow * 128 + ((cp ^ (prow & 7)) << 4));
}
__device__ __forceinline__ uint32_t bfragP_addr(uint32_t base, int n0, int kc, int lane) {
    int lrow = n0 + (lane & 7) + ((lane >> 4) & 1) * 8;
    int ch   = 2 * kc + ((lane >> 3) & 1);
    return base + swp_off(lrow, ch);
}

// ---------------------------------------------------------------------------
// Scratch globals
// ---------------------------------------------------------------------------
// Fragment-packed X: [mt(512)][kcg(16)][32 x uint4]  (A-frag layout)
__device__ uint4 g_Xfh[512 * 16 * 32];
__device__ uint4 g_Xfl[512 * 16 * 32];
// Fragment-packed w_qkv: [nt(96)][kcg(16)][32 x uint4]  (B-frag layout)
__device__ uint4 g_Wqfh[96 * 16 * 32];
__device__ uint4 g_Wqfl[96 * 16 * 32];
// w_out transposed [d][ch] (old layout, consumed via smem by out_mma)
__device__ __nv_bfloat16 g_Woh[COUT * AD];
__device__ __nv_bfloat16 g_Wol[COUT * AD];
__device__ __nv_bfloat16 g_Qh[NB * HEADS * NPOS * DH];
__device__ __nv_bfloat16 g_Ql[NB * HEADS * NPOS * DH];
__device__ __nv_bfloat16 g_Kh[NB * HEADS * NPOS * DH];
__device__ __nv_bfloat16 g_Kl[NB * HEADS * NPOS * DH];
__device__ __nv_bfloat16 g_Vh[NB * HEADS * NPOS * DH];
__device__ __nv_bfloat16 g_Vl[NB * HEADS * NPOS * DH];
__device__ __nv_bfloat16 g_A2h[NB * AD * NPOS];
__device__ __nv_bfloat16 g_A2l[NB * AD * NPOS];
__device__ float g_Y[NB * NPOS * COUT];
__device__ float g_part[1024];
__device__ float g_stats[2 * NB];

// ---------------------------------------------------------------------------
// Kernel 0a: X -> split bf16 in A-frag-packed layout.
// Element (m,k): lane=(m&7)*4+((k&7)>>1), reg=((m&8)>>3)|((k&8)>>2).
// ---------------------------------------------------------------------------
__global__ __launch_bounds__(256) void conv_x_kernel(const float* __restrict__ X)
{
    int idx4 = blockIdx.x * 256 + threadIdx.x;       // 524288 float4
    int m  = idx4 >> 6;
    int c4 = (idx4 & 63) * 4;
    float4 v = reinterpret_cast<const float4*>(X)[idx4];

    uint32_t* Xh = reinterpret_cast<uint32_t*>(g_Xfh);
    uint32_t* Xl = reinterpret_cast<uint32_t*>(g_Xfl);

    int mt = m >> 4;
    #pragma unroll
    for (int p = 0; p < 2; p++) {
        int c = c4 + p * 2;
        float va = p ? v.z : v.x;
        float vb = p ? v.w : v.y;
        uint32_t hi, lo;
        split_pair(va, vb, hi, lo);
        int kcg = c >> 4;
        int lane = (m & 7) * 4 + ((c & 7) >> 1);
        int reg  = ((m & 8) >> 3) | ((c & 8) >> 2);
        size_t off = ((size_t)(mt * 16 + kcg) * 32 + lane) * 4 + reg;
        Xh[off] = hi;
        Xl[off] = lo;
    }
}

// ---------------------------------------------------------------------------
// Kernel 0b: weight transpose + split.
// which=0: w_qkv -> B-frag packed g_Wqf  (element (n,k): lane=(n&7)*4+((k&7)>>1),
//          reg=((k&8)>>3)|((n&8)>>2))
// which=1: w_out -> linear [d][ch] g_Wo (old path)
// ---------------------------------------------------------------------------
__global__ void conv_w_kernel(const float* __restrict__ src, int K, int N, int which)
{
    __shared__ float tile[32][33];
    int n0 = blockIdx.x * 32;
    int k0 = blockIdx.y * 32;
    int tx = threadIdx.x, ty = threadIdx.y;
    tile[ty][tx] = src[(size_t)(k0 + ty) * N + n0 + tx];
    __syncthreads();
    if (tx < 16) {
        uint32_t hi, lo;
        split_pair(tile[2*tx][ty], tile[2*tx+1][ty], hi, lo);
        int k = k0 + 2 * tx;
        int n = n0 + ty;
        if (which == 0) {
            uint32_t* Wh = reinterpret_cast<uint32_t*>(g_Wqfh);
            uint32_t* Wl = reinterpret_cast<uint32_t*>(g_Wqfl);
            int nt = n >> 4, kcg = k >> 4;
            int lane = (n & 7) * 4 + ((k & 7) >> 1);
            int reg  = ((k & 8) >> 3) | ((n & 8) >> 2);
            size_t off = ((size_t)(nt * 16 + kcg) * 32 + lane) * 4 + reg;
            Wh[off] = hi;
            Wl[off] = lo;
        } else {
            size_t off = (size_t)n * K + k;
            *reinterpret_cast<uint32_t*>(&g_Woh[off]) = hi;
            *reinterpret_cast<uint32_t*>(&g_Wol[off]) = lo;
        }
    }
}

// ---------------------------------------------------------------------------
// Kernel 1: QKV GEMM — NO SMEM. All fragments via coalesced LDG.128 from
// frag-packed X / Wq (L2-resident). Register double-buffered over 16 k-chunks.
// Block 128m x 64n, warp 64x32. Grid (24 n, 64 m).
// ---------------------------------------------------------------------------
__global__ __launch_bounds__(128, 3) void qkv_mma_kernel()
{
    const int tid = threadIdx.x, lane = tid & 31, wid = tid >> 5;
    const int n_blk = blockIdx.x * 64;
    const int m_blk = blockIdx.y * 128;
    const int mw = (wid >> 1) * 64;
    const int nw = (wid & 1) * 32;
    const int g = lane >> 2, tig = lane & 3;

    const int mt0 = (m_blk + mw) >> 4;   // 4 consecutive m16 tiles
    const int nt0 = (n_blk + nw) >> 4;   // 2 consecutive n16 tiles

    float acc[4][4][4];
    #pragma unroll
    for (int i = 0; i < 4; i++)
        #pragma unroll
        for (int j = 0; j < 4; j++)
            #pragma unroll
            for (int k = 0; k < 4; k++) acc[i][j][k] = 0.0f;

    uint4 ahf[2][4], alf[2][4], bhf[2][2], blf[2][2];

    const uint4* Xh = g_Xfh; const uint4* Xl = g_Xfl;
    const uint4* Wh = g_Wqfh; const uint4* Wl = g_Wqfl;

    // load frags for chunk 0
    #pragma unroll
    for (int mf = 0; mf < 4; mf++) {
        size_t o = ((size_t)(mt0 + mf) * 16 + 0) * 32 + lane;
        ahf[0][mf] = Xh[o]; alf[0][mf] = Xl[o];
    }
    #pragma unroll
    for (int nf = 0; nf < 2; nf++) {
        size_t o = ((size_t)(nt0 + nf) * 16 + 0) * 32 + lane;
        bhf[0][nf] = Wh[o]; blf[0][nf] = Wl[o];
    }

    #pragma unroll
    for (int kcg = 0; kcg < 16; kcg++) {
        const int cur = kcg & 1;
        if (kcg < 15) {
            const int nxt = cur ^ 1;
            #pragma unroll
            for (int mf = 0; mf < 4; mf++) {
                size_t o = ((size_t)(mt0 + mf) * 16 + (kcg + 1)) * 32 + lane;
                ahf[nxt][mf] = Xh[o]; alf[nxt][mf] = Xl[o];
            }
            #pragma unroll
            for (int nf = 0; nf < 2; nf++) {
                size_t o = ((size_t)(nt0 + nf) * 16 + (kcg + 1)) * 32 + lane;
                bhf[nxt][nf] = Wh[o]; blf[nxt][nf] = Wl[o];
            }
        }
        // product-major: hi*hi, hi*lo, lo*hi
        #pragma unroll
        for (int mf = 0; mf < 4; mf++) {
            const uint32_t* a = reinterpret_cast<const uint32_t*>(&ahf[cur][mf]);
            #pragma unroll
            for (int nf = 0; nf < 2; nf++) {
                const uint32_t* b = reinterpret_cast<const uint32_t*>(&bhf[cur][nf]);
                mma16816(acc[mf][2*nf],   a, b + 0);
                mma16816(acc[mf][2*nf+1], a, b + 2);
            }
        }
        #pragma unroll
        for (int mf = 0; mf < 4; mf++) {
            const uint32_t* a = reinterpret_cast<const uint32_t*>(&ahf[cur][mf]);
            #pragma unroll
            for (int nf = 0; nf < 2; nf++) {
                const uint32_t* b = reinterpret_cast<const uint32_t*>(&blf[cur][nf]);
                mma16816(acc[mf][2*nf],   a, b + 0);
                mma16816(acc[mf][2*nf+1], a, b + 2);
            }
        }
        #pragma unroll
        for (int mf = 0; mf < 4; mf++) {
            const uint32_t* a = reinterpret_cast<const uint32_t*>(&alf[cur][mf]);
            #pragma unroll
            for (int nf = 0; nf < 2; nf++) {
                const uint32_t* b = reinterpret_cast<const uint32_t*>(&bhf[cur][nf]);
                mma16816(acc[mf][2*nf],   a, b + 0);
                mma16816(acc[mf][2*nf+1], a, b + 2);
            }
        }
    }

    // epilogue: split into Q (scaled) / K / V  (unchanged layouts)
    const int which = n_blk >> 9;
    const int h = (n_blk >> 6) & 7;
    __nv_bfloat16 *dh, *dl;
    float sc = 1.0f;
    if (which == 0)      { dh = g_Qh; dl = g_Ql; sc = QK_SCALE; }
    else if (which == 1) { dh = g_Kh; dl = g_Kl; }
    else                 { dh = g_Vh; dl = g_Vl; }

    #pragma unroll
    for (int mf = 0; mf < 4; mf++) {
        int r0 = m_blk + mw + mf*16 + g;
        int b_ = r0 >> 10;
        int nr = r0 & 1023;
        size_t rb0 = ((size_t)(b_ * HEADS + h) * NPOS + nr) * DH;
        size_t rb1 = rb0 + 8 * DH;
        #pragma unroll
        for (int j = 0; j < 4; j++) {
            int c = nw + j * 8 + tig * 2;
            uint32_t hi, lo;
            split_pair(acc[mf][j][0] * sc, acc[mf][j][1] * sc, hi, lo);
            *reinterpret_cast<uint32_t*>(&dh[rb0 + c]) = hi;
            *reinterpret_cast<uint32_t*>(&dl[rb0 + c]) = lo;
            split_pair(acc[mf][j][2] * sc, acc[mf][j][3] * sc, hi, lo);
            *reinterpret_cast<uint32_t*>(&dh[rb1 + c]) = hi;
            *reinterpret_cast<uint32_t*>(&dl[rb1 + c]) = lo;
        }
    }
}

// ---------------------------------------------------------------------------
// Kernel 2: attention — single-barrier cp.async pipeline, product-major (R8).
// ---------------------------------------------------------------------------
__global__ __launch_bounds__(128) void attn_mma_kernel()
{
    extern __shared__ uint8_t dyn_s[];

    const int tid  = threadIdx.x;
    const int lane = tid & 31;
    const int wid  = tid >> 5;
    const int bh   = blockIdx.y;
    const int qb   = blockIdx.x * 64 + wid * 16;
    const int g    = lane >> 2;
    const int tig  = lane & 3;

    const __nv_bfloat16* gKh = g_Kh + (size_t)bh * NPOS * DH;
    const __nv_bfloat16* gKl = g_Kl + (size_t)bh * NPOS * DH;
    const __nv_bfloat16* gVh = g_Vh + (size_t)bh * NPOS * DH;
    const __nv_bfloat16* gVl = g_Vl + (size_t)bh * NPOS * DH;

    const uint32_t sbase = smem_u32(dyn_s);

    uint32_t qh[4][4], ql[4][4];
    {
        const __nv_bfloat16* Qh = g_Qh + (size_t)bh * NPOS * DH;
        const __nv_bfloat16* Ql = g_Ql + (size_t)bh * NPOS * DH;
        int r = qb + g;
        #pragma unroll
        for (int kc = 0; kc < 4; kc++) {
            int c0 = kc * 16 + tig * 2;
            qh[kc][0] = *reinterpret_cast<const uint32_t*>(Qh + (size_t)r*DH + c0);
            qh[kc][1] = *reinterpret_cast<const uint32_t*>(Qh + (size_t)(r+8)*DH + c0);
            qh[kc][2] = *reinterpret_cast<const uint32_t*>(Qh + (size_t)r*DH + c0 + 8);
            qh[kc][3] = *reinterpret_cast<const uint32_t*>(Qh + (size_t)(r+8)*DH + c0 + 8);
            ql[kc][0] = *reinterpret_cast<const uint32_t*>(Ql + (size_t)r*DH + c0);
            ql[kc][1] = *reinterpret_cast<const uint32_t*>(Ql + (size_t)(r+8)*DH + c0);
            ql[kc][2] = *reinterpret_cast<const uint32_t*>(Ql + (size_t)r*DH + c0 + 8);
            ql[kc][3] = *reinterpret_cast<const uint32_t*>(Ql + (size_t)(r+8)*DH + c0 + 8);
        }
    }

    float oc[8][4];
    #pragma unroll
    for (int i = 0; i < 8; i++)
        #pragma unroll
        for (int j = 0; j < 4; j++) oc[i][j] = 0.0f;
    float lsum0 = 0.0f, lsum1 = 0.0f;

    auto preload = [&](int kt, int buf) {
        uint32_t b0 = sbase + buf * 32768;
        #pragma unroll
        for (int i = 0; i < 4; i++) {
            int idx = i * 128 + tid;
            int row = idx >> 3, ch = idx & 7;
            uint32_t dsto = (uint32_t)(row * 128 + ((ch ^ (row & 7)) << 4));
            size_t go = (size_t)(kt * 64 + row) * DH + ch * 8;
            cp16(b0 + dsto,         gKh + go);
            cp16(b0 + 8192 + dsto,  gKl + go);
            cp16(b0 + 16384 + dsto, gVh + go);
            cp16(b0 + 24576 + dsto, gVl + go);
        }
        asm volatile("cp.async.commit_group;" ::: "memory");
    };

    preload(0, 0);

    for (int kt = 0; kt < 16; kt++) {
        asm volatile("cp.async.wait_group 0;" ::: "memory");
        __syncthreads();
        if (kt < 15) preload(kt + 1, (kt + 1) & 1);

        const uint32_t sKh = sbase + (kt & 1) * 32768;
        const uint32_t sKl = sKh + 8192;
        const uint32_t sVh = sKh + 16384;
        const uint32_t sVl = sKh + 24576;

        float s[8][4];
        #pragma unroll
        for (int i = 0; i < 8; i++)
            #pragma unroll
            for (int j = 0; j < 4; j++) s[i][j] = 0.0f;

        #pragma unroll
        for (int kc = 0; kc < 4; kc++) {
            uint32_t kh[4][4], kl[4][4];
            #pragma unroll
            for (int np = 0; np < 4; np++) {
                ldsm4(kh[np], bfrag_addr(sKh, np*16, kc, lane));
                ldsm4(kl[np], bfrag_addr(sKl, np*16, kc, lane));
            }
            #pragma unroll
            for (int np = 0; np < 4; np++) {
                mma16816(s[2*np],   qh[kc], kh[np] + 0);
                mma16816(s[2*np+1], qh[kc], kh[np] + 2);
            }
            #pragma unroll
            for (int np = 0; np < 4; np++) {
                mma16816(s[2*np],   qh[kc], kl[np] + 0);
                mma16816(s[2*np+1], qh[kc], kl[np] + 2);
            }
            #pragma unroll
            for (int np = 0; np < 4; np++) {
                mma16816(s[2*np],   ql[kc], kh[np] + 0);
                mma16816(s[2*np+1], ql[kc], kh[np] + 2);
            }
        }

        uint32_t ph[4][4], pl[4][4];
        #pragma unroll
        for (int np = 0; np < 4; np++) {
            float p0[4], p1[4];
            #pragma unroll
            for (int j = 0; j < 4; j++) {
                p0[j] = __expf(s[2*np][j]);
                p1[j] = __expf(s[2*np+1][j]);
            }
            lsum0 += p0[0] + p0[1] + p1[0] + p1[1];
            lsum1 += p0[2] + p0[3] + p1[2] + p1[3];
            split_pair(p0[0], p0[1], ph[np][0], pl[np][0]);
            split_pair(p0[2], p0[3], ph[np][1], pl[np][1]);
            split_pair(p1[0], p1[1], ph[np][2], pl[np][2]);
            split_pair(p1[2], p1[3], ph[np][3], pl[np][3]);
        }

        #pragma unroll
        for (int jc = 0; jc < 4; jc++) {
            uint32_t vh[4][4], vl[4][4];
            #pragma unroll
            for (int vp = 0; vp < 4; vp++) {
                ldsm4t(vh[vp], afrag_addr(sVh, jc*16, vp, lane));
                ldsm4t(vl[vp], afrag_addr(sVl, jc*16, vp, lane));
            }
            #pragma unroll
            for (int vp = 0; vp < 4; vp++) {
                mma16816(oc[2*vp],   ph[jc], vh[vp] + 0);
                mma16816(oc[2*vp+1], ph[jc], vh[vp] + 2);
            }
            #pragma unroll
            for (int vp = 0; vp < 4; vp++) {
                mma16816(oc[2*vp],   ph[jc], vl[vp] + 0);
                mma16816(oc[2*vp+1], ph[jc], vl[vp] + 2);
            }
            #pragma unroll
            for (int vp = 0; vp < 4; vp++) {
                mma16816(oc[2*vp],   pl[jc], vh[vp] + 0);
                mma16816(oc[2*vp+1], pl[jc], vh[vp] + 2);
            }
        }
    }

    lsum0 += __shfl_xor_sync(0xffffffffu, lsum0, 1);
    lsum0 += __shfl_xor_sync(0xffffffffu, lsum0, 2);
    lsum1 += __shfl_xor_sync(0xffffffffu, lsum1, 1);
    lsum1 += __shfl_xor_sync(0xffffffffu, lsum1, 2);
    float inv0 = 1.0f / lsum0;
    float inv1 = 1.0f / lsum1;

    int b = bh >> 3, h = bh & 7;
    int q0 = qb + g, q1 = qb + g + 8;
    size_t row0 = ((size_t)(b * AD + h * 64 + (q0 >> 4))) * NPOS + ((q0 & 15) << 6);
    size_t row1 = ((size_t)(b * AD + h * 64 + (q1 >> 4))) * NPOS + ((q1 & 15) << 6);
    #pragma unroll
    for (int ct = 0; ct < 8; ct++) {
        int c = ct * 8 + tig * 2;
        uint32_t hi, lo;
        split_pair(oc[ct][0] * inv0, oc[ct][1] * inv0, hi, lo);
        *reinterpret_cast<uint32_t*>(&g_A2h[row0 + c]) = hi;
        *reinterpret_cast<uint32_t*>(&g_A2l[row0 + c]) = lo;
        split_pair(oc[ct][2] * inv1, oc[ct][3] * inv1, hi, lo);
        *reinterpret_cast<uint32_t*>(&g_A2h[row1 + c]) = hi;
        *reinterpret_cast<uint32_t*>(&g_A2l[row1 + c]) = lo;
    }
}

// ---------------------------------------------------------------------------
// Kernel 3: out GEMM + fused GN partials (R8). Block 64x64, warp 32x32,
// BK=32, single-barrier pipeline. Grid (16, 4, 8).
// ---------------------------------------------------------------------------
__global__ __launch_bounds__(128, 4) void out_mma_kernel(const float* __restrict__ bout)
{
    extern __shared__ uint8_t dyn_o[];
    const uint32_t sbase = smem_u32(dyn_o);

    const int tid = threadIdx.x, lane = tid & 31, wid = tid >> 5;
    const int m_blk = blockIdx.x * 64;
    const int n_blk = blockIdx.y * 64;
    const int bb = blockIdx.z;
    const int mw = (wid >> 1) * 32;
    const int nw = (wid & 1) * 32;
    const int g = lane >> 2, tig = lane & 3;

    float acc[2][4][4];
    #pragma unroll
    for (int i = 0; i < 2; i++)
        #pragma unroll
        for (int j = 0; j < 4; j++)
            #pragma unroll
            for (int k = 0; k < 4; k++) acc[i][j][k] = 0.0f;

    const __nv_bfloat16* A2h = g_A2h + (size_t)bb * AD * NPOS;
    const __nv_bfloat16* A2l = g_A2l + (size_t)bb * AD * NPOS;

    auto preload = [&](int ks, int buf) {
        uint32_t b0 = sbase + buf * 16384;
        int k0 = ks * 32;
        #pragma unroll
        for (int i = 0; i < 2; i++) {
            int idx = i * 128 + tid;
            int row = idx >> 3, ch = idx & 7;
            uint32_t off = (uint32_t)(row * 128 + ((ch ^ (row & 7)) << 4));
            size_t go = (size_t)(k0 + row) * NPOS + m_blk + ch * 8;
            cp16(b0 + off,        A2h + go);
            cp16(b0 + 4096 + off, A2l + go);
        }
        #pragma unroll
        for (int i = 0; i < 2; i++) {
            int idx = i * 128 + tid;
            int lrow = idx >> 2, ch = idx & 3;
            uint32_t off = swp_off(lrow, ch);
            size_t go = (size_t)(n_blk + lrow) * AD + k0 + ch * 8;
            cp16(b0 + 8192 + off,  g_Woh + go);
            cp16(b0 + 12288 + off, g_Wol + go);
        }
        asm volatile("cp.async.commit_group;" ::: "memory");
    };

    preload(0, 0);

    for (int s = 0; s < 16; s++) {
        asm volatile("cp.async.wait_group 0;" ::: "memory");
        __syncthreads();
        if (s < 15) preload(s + 1, (s + 1) & 1);

        uint32_t b0 = sbase + (s & 1) * 16384;
        const uint32_t sAh = b0, sAl = b0 + 4096, sBh = b0 + 8192, sBl = b0 + 12288;

        #pragma unroll
        for (int kc = 0; kc < 2; kc++) {
            uint32_t bh0[4], bl0[4], bh1[4], bl1[4];
            ldsm4(bh0, bfragP_addr(sBh, nw,      kc, lane));
            ldsm4(bh1, bfragP_addr(sBh, nw + 16, kc, lane));
            ldsm4(bl0, bfragP_addr(sBl, nw,      kc, lane));
            ldsm4(bl1, bfragP_addr(sBl, nw + 16, kc, lane));
            #pragma unroll
            for (int mf = 0; mf < 2; mf++) {
                uint32_t ah[4], al[4];
                ldsm4t(ah, afragT128_addr(sAh, kc*16, mw + mf*16, lane));
                ldsm4t(al, afragT128_addr(sAl, kc*16, mw + mf*16, lane));
                mma16816(acc[mf][0], ah, bh0 + 0); mma16816(acc[mf][1], ah, bh0 + 2);
                mma16816(acc[mf][2], ah, bh1 + 0); mma16816(acc[mf][3], ah, bh1 + 2);
                mma16816(acc[mf][0], ah, bl0 + 0); mma16816(acc[mf][1], ah, bl0 + 2);
                mma16816(acc[mf][2], ah, bl1 + 0); mma16816(acc[mf][3], ah, bl1 + 2);
                mma16816(acc[mf][0], al, bh0 + 0); mma16816(acc[mf][1], al, bh0 + 2);
                mma16816(acc[mf][2], al, bh1 + 0); mma16816(acc[mf][3], al, bh1 + 2);
            }
        }
    }

    float psum = 0.0f, psq = 0.0f;
    #pragma unroll
    for (int mf = 0; mf < 2; mf++) {
        int r0 = m_blk + mw + mf*16 + g;
        #pragma unroll
        for (int j = 0; j < 4; j++) {
            int d = n_blk + nw + j * 8 + tig * 2;
            float2 bv = *reinterpret_cast<const float2*>(&bout[d]);
            float2 v0 = make_float2(acc[mf][j][0] + bv.x, acc[mf][j][1] + bv.y);
            float2 v1 = make_float2(acc[mf][j][2] + bv.x, acc[mf][j][3] + bv.y);
            *reinterpret_cast<float2*>(&g_Y[((size_t)bb*NPOS + r0)*COUT + d]) = v0;
            *reinterpret_cast<float2*>(&g_Y[((size_t)bb*NPOS + r0 + 8)*COUT + d]) = v1;
            psum += v0.x + v0.y + v1.x + v1.y;
            psq  += v0.x*v0.x + v0.y*v0.y + v1.x*v1.x + v1.y*v1.y;
        }
    }

    __syncthreads();
    float* rs  = reinterpret_cast<float*>(dyn_o);
    float* rss = rs + 128;
    rs[tid] = psum; rss[tid] = psq;
    __syncthreads();
    for (int st = 64; st > 0; st >>= 1) {
        if (tid < st) { rs[tid] += rs[tid + st]; rss[tid] += rss[tid + st]; }
        __syncthreads();
    }
    if (tid == 0) {
        int p = bb * 64 + blockIdx.x * 4 + blockIdx.y;
        g_part[2*p]   = rs[0];
        g_part[2*p+1] = rss[0];
    }
}

// ---------------------------------------------------------------------------
// GN final + normalize
// ---------------------------------------------------------------------------
__global__ void gn_final_kernel()
{
    int b = threadIdx.x;
    if (b < NB) {
        float s = 0.0f, ss = 0.0f;
        #pragma unroll
        for (int i = 0; i < 64; i++) {
            s  += g_part[2*(b*64 + i)];
            ss += g_part[2*(b*64 + i) + 1];
        }
        const float inv_n = 1.0f / (float)(NPOS * COUT);
        float mean = s * inv_n;
        float var  = ss * inv_n - mean * mean;
        g_stats[2*b]     = mean;
        g_stats[2*b + 1] = rsqrtf(var + GN_EPS);
    }
}

__global__ __launch_bounds__(256) void gn_norm_kernel(
    const float* __restrict__ gamma, const float* __restrict__ beta,
    float* __restrict__ out)
{
    int idx4 = blockIdx.x * 256 + threadIdx.x;
    int b  = idx4 >> 16;
    int d4 = idx4 & 63;

    float mean = g_stats[2*b];
    float rstd = g_stats[2*b + 1];

    float4 y  = reinterpret_cast<const float4*>(g_Y)[idx4];
    float4 g  = reinterpret_cast<const float4*>(gamma)[d4];
    float4 be = reinterpret_cast<const float4*>(beta)[d4];

    float4 r;
    r.x = (y.x - mean) * rstd * g.x + be.x;
    r.y = (y.y - mean) * rstd * g.y + be.y;
    r.z = (y.z - mean) * rstd * g.z + be.z;
    r.w = (y.w - mean) * rstd * g.w + be.w;
    reinterpret_cast<float4*>(out)[idx4] = r;
}

// ---------------------------------------------------------------------------
extern "C" void kernel_launch(void* const* d_in, const int* in_sizes, int n_in,
                              void* d_out, int out_size)
{
    const float* x      = (const float*)d_in[0];
    const float* w_qkv  = (const float*)d_in[1];
    const float* w_out  = (const float*)d_in[2];
    const float* b_out  = (const float*)d_in[3];
    const float* gamma  = (const float*)d_in[4];
    const float* beta   = (const float*)d_in[5];
    float* out = (float*)d_out;

    static int smem_set = 0;
    if (!smem_set) {
        cudaFuncSetAttribute(attn_mma_kernel,
                             cudaFuncAttributeMaxDynamicSharedMemorySize, 65536);
        cudaFuncSetAttribute(out_mma_kernel,
                             cudaFuncAttributeMaxDynamicSharedMemorySize, 32768);
        smem_set = 1;
    }

    conv_x_kernel<<<2048, 256>>>(x);
    conv_w_kernel<<<dim3(48, 8),  dim3(32, 32)>>>(w_qkv, CIN, 3*AD, 0);
    conv_w_kernel<<<dim3(8, 16),  dim3(32, 32)>>>(w_out, AD, COUT, 1);
    qkv_mma_kernel<<<dim3(24, 64), 128>>>();
    attn_mma_kernel<<<dim3(16, 64), 128, 65536>>>();
    out_mma_kernel<<<dim3(16, 4, 8), 128, 32768>>>(b_out);
    gn_final_kernel<<<1, 32>>>();
    gn_norm_kernel<<<2048, 256>>>(gamma, beta, out);
}